// round 2
// baseline (speedup 1.0000x reference)
#include <cuda_runtime.h>
#include <cstdint>
#include <cstddef>

#define D_MODEL  1024
#define N_HEADS  16
#define HEAD_DIM 64
#define BATCH    4
#define SEQ      2048
#define M_TOTAL  (BATCH * SEQ)   // 8192

// ---------------------------------------------------------------------------
// Scratch (no cudaMalloc allowed): Q, K, V projections and concat buffer.
// ---------------------------------------------------------------------------
__device__ float g_q[(size_t)M_TOTAL * D_MODEL];
__device__ float g_k[(size_t)M_TOTAL * D_MODEL];
__device__ float g_v[(size_t)M_TOTAL * D_MODEL];
__device__ float g_c[(size_t)M_TOTAL * D_MODEL];

// ---------------------------------------------------------------------------
// GEMM: C[m][n] = sum_k A[m][k] * B[n][k]   (A: MxK row-major, B: NxK row-major)
// 128x128x16 tiles, 256 threads, 8x8 microtile, register prefetch.
// ---------------------------------------------------------------------------
__global__ __launch_bounds__(256, 2)
void gemm_tn_kernel(const float* __restrict__ A, const float* __restrict__ B,
                    float* __restrict__ C, int M, int N, int K)
{
    __shared__ float As[16][128];
    __shared__ float Bs[16][128];

    const int tid = threadIdx.x;
    const int bm  = blockIdx.y * 128;
    const int bn  = blockIdx.x * 128;
    const int tr  = (tid >> 4) << 3;   // 0..120
    const int tc  = (tid & 15) << 3;   // 0..120
    const int lr  = tid >> 2;          // 0..63
    const int lk  = (tid & 3) << 2;    // 0,4,8,12

    const float* Ap = A + (size_t)(bm + lr) * K + lk;
    const float* Bp = B + (size_t)(bn + lr) * K + lk;

    float4 a0 = *(const float4*)(Ap);
    float4 a1 = *(const float4*)(Ap + (size_t)64 * K);
    float4 b0 = *(const float4*)(Bp);
    float4 b1 = *(const float4*)(Bp + (size_t)64 * K);

    float acc[8][8];
#pragma unroll
    for (int i = 0; i < 8; i++)
#pragma unroll
        for (int j = 0; j < 8; j++) acc[i][j] = 0.f;

    for (int k0 = 0; k0 < K; k0 += 16) {
        __syncthreads();
        As[lk + 0][lr]      = a0.x; As[lk + 1][lr]      = a0.y;
        As[lk + 2][lr]      = a0.z; As[lk + 3][lr]      = a0.w;
        As[lk + 0][lr + 64] = a1.x; As[lk + 1][lr + 64] = a1.y;
        As[lk + 2][lr + 64] = a1.z; As[lk + 3][lr + 64] = a1.w;
        Bs[lk + 0][lr]      = b0.x; Bs[lk + 1][lr]      = b0.y;
        Bs[lk + 2][lr]      = b0.z; Bs[lk + 3][lr]      = b0.w;
        Bs[lk + 0][lr + 64] = b1.x; Bs[lk + 1][lr + 64] = b1.y;
        Bs[lk + 2][lr + 64] = b1.z; Bs[lk + 3][lr + 64] = b1.w;
        __syncthreads();

        if (k0 + 16 < K) {
            Ap += 16; Bp += 16;
            a0 = *(const float4*)(Ap);
            a1 = *(const float4*)(Ap + (size_t)64 * K);
            b0 = *(const float4*)(Bp);
            b1 = *(const float4*)(Bp + (size_t)64 * K);
        }

#pragma unroll
        for (int kk = 0; kk < 16; kk++) {
            float ar[8], br[8];
            *(float4*)(ar)     = *(const float4*)&As[kk][tr];
            *(float4*)(ar + 4) = *(const float4*)&As[kk][tr + 4];
            *(float4*)(br)     = *(const float4*)&Bs[kk][tc];
            *(float4*)(br + 4) = *(const float4*)&Bs[kk][tc + 4];
#pragma unroll
            for (int i = 0; i < 8; i++)
#pragma unroll
                for (int j = 0; j < 8; j++)
                    acc[i][j] += ar[i] * br[j];
        }
    }

#pragma unroll
    for (int i = 0; i < 8; i++) {
        float* Cp = C + (size_t)(bm + tr + i) * N + bn + tc;
        *(float4*)(Cp)     = make_float4(acc[i][0], acc[i][1], acc[i][2], acc[i][3]);
        *(float4*)(Cp + 4) = make_float4(acc[i][4], acc[i][5], acc[i][6], acc[i][7]);
    }
}

// ---------------------------------------------------------------------------
// Causal flash attention, fp32. One block = one (b,h, 64-row Q tile).
// Online softmax in base-2 units; P staged via SMEM for the PV product.
// Output is written directly in concat layout (B,S,H*Dh).
// ---------------------------------------------------------------------------
__device__ __forceinline__ float fast_exp2(float x) {
    float y;
    asm("ex2.approx.ftz.f32 %0, %1;" : "=f"(y) : "f"(x));
    return y;
}

#define FP 65   // padded smem stride

__global__ __launch_bounds__(256)
void flash_kernel(const float* __restrict__ Qg, const float* __restrict__ Kg,
                  const float* __restrict__ Vg, float* __restrict__ Ocat)
{
    extern __shared__ float sm[];
    float* Qs = sm;              // [64][FP]  layout [d][r]
    float* Ks = sm + 64 * FP;    // [64][FP]  layout [d][c]
    float* Vs = sm + 2 * 64 * FP;// [64][FP]  layout [k][c]
    float* Ps = sm + 3 * 64 * FP;// [64][FP]  layout [r][k]

    const int tid = threadIdx.x;
    const int qi  = blockIdx.x;        // q tile (0..31)
    const int bh  = blockIdx.y;        // b*16 + h
    const int b   = bh >> 4;
    const int h   = bh & 15;
    const int q0  = qi << 6;
    const int tr  = (tid >> 4) << 2;   // row base 0..60
    const int tc  = (tid & 15) << 2;   // col base 0..60

    const size_t base = (size_t)b * SEQ * D_MODEL + (size_t)h * HEAD_DIM;
    const float* qb = Qg + base;
    const float* kb = Kg + base;
    const float* vb = Vg + base;

    // Q tile -> Qs[d][r]
#pragma unroll
    for (int it = 0; it < 4; it++) {
        int lin = tid + it * 256;
        int r   = lin >> 4;
        int d4  = (lin & 15) << 2;
        float4 t = *(const float4*)(qb + (size_t)(q0 + r) * D_MODEL + d4);
        Qs[(d4 + 0) * FP + r] = t.x;
        Qs[(d4 + 1) * FP + r] = t.y;
        Qs[(d4 + 2) * FP + r] = t.z;
        Qs[(d4 + 3) * FP + r] = t.w;
    }

    const float NEG_INF = __int_as_float(0xff800000u);
    float m2[4], l[4], o[4][4];
#pragma unroll
    for (int i = 0; i < 4; i++) {
        m2[i] = NEG_INF; l[i] = 0.f;
#pragma unroll
        for (int j = 0; j < 4; j++) o[i][j] = 0.f;
    }

    const float CSC = 0.125f * 1.4426950408889634f; // (1/sqrt(Dh)) * log2(e)

    for (int kt = 0; kt <= qi; kt++) {
        __syncthreads();   // previous tile's Ks/Vs/Ps reads done (also covers Qs first iter)
        // K,V tiles
#pragma unroll
        for (int it = 0; it < 4; it++) {
            int lin = tid + it * 256;
            int r   = lin >> 4;
            int d4  = (lin & 15) << 2;
            size_t go = (size_t)((kt << 6) + r) * D_MODEL + d4;
            float4 tk = *(const float4*)(kb + go);
            float4 tv = *(const float4*)(vb + go);
            Ks[(d4 + 0) * FP + r] = tk.x;
            Ks[(d4 + 1) * FP + r] = tk.y;
            Ks[(d4 + 2) * FP + r] = tk.z;
            Ks[(d4 + 3) * FP + r] = tk.w;
            Vs[r * FP + d4 + 0] = tv.x;
            Vs[r * FP + d4 + 1] = tv.y;
            Vs[r * FP + d4 + 2] = tv.z;
            Vs[r * FP + d4 + 3] = tv.w;
        }
        __syncthreads();

        // S = Q K^T
        float s[4][4];
#pragma unroll
        for (int i = 0; i < 4; i++)
#pragma unroll
            for (int j = 0; j < 4; j++) s[i][j] = 0.f;

#pragma unroll 16
        for (int d = 0; d < 64; d++) {
            float a0 = Qs[d * FP + tr + 0];
            float a1 = Qs[d * FP + tr + 1];
            float a2 = Qs[d * FP + tr + 2];
            float a3 = Qs[d * FP + tr + 3];
            float e0 = Ks[d * FP + tc + 0];
            float e1 = Ks[d * FP + tc + 1];
            float e2 = Ks[d * FP + tc + 2];
            float e3 = Ks[d * FP + tc + 3];
            s[0][0] += a0 * e0; s[0][1] += a0 * e1; s[0][2] += a0 * e2; s[0][3] += a0 * e3;
            s[1][0] += a1 * e0; s[1][1] += a1 * e1; s[1][2] += a1 * e2; s[1][3] += a1 * e3;
            s[2][0] += a2 * e0; s[2][1] += a2 * e1; s[2][2] += a2 * e2; s[2][3] += a2 * e3;
            s[3][0] += a3 * e0; s[3][1] += a3 * e1; s[3][2] += a3 * e2; s[3][3] += a3 * e3;
        }

        const bool diag = (kt == qi);
#pragma unroll
        for (int i = 0; i < 4; i++)
#pragma unroll
            for (int j = 0; j < 4; j++) {
                float t = s[i][j] * CSC;
                if (diag && (tc + j) > (tr + i)) t = NEG_INF;
                s[i][j] = t;
            }

        // online softmax per row (reduce across the 16 tx threads)
#pragma unroll
        for (int i = 0; i < 4; i++) {
            float rm = fmaxf(fmaxf(s[i][0], s[i][1]), fmaxf(s[i][2], s[i][3]));
#pragma unroll
            for (int off = 8; off >= 1; off >>= 1)
                rm = fmaxf(rm, __shfl_xor_sync(0xffffffffu, rm, off));
            float mn = fmaxf(m2[i], rm);
            float rs = 0.f;
#pragma unroll
            for (int j = 0; j < 4; j++) {
                float p = fast_exp2(s[i][j] - mn);
                Ps[(tr + i) * FP + tc + j] = p;
                rs += p;
            }
#pragma unroll
            for (int off = 8; off >= 1; off >>= 1)
                rs += __shfl_xor_sync(0xffffffffu, rs, off);
            float sc = fast_exp2(m2[i] - mn);
            l[i]  = l[i] * sc + rs;
            m2[i] = mn;
#pragma unroll
            for (int j = 0; j < 4; j++) o[i][j] *= sc;
        }
        __syncthreads();   // P visible

        // O += P V
#pragma unroll 16
        for (int kk = 0; kk < 64; kk++) {
            float p0 = Ps[(tr + 0) * FP + kk];
            float p1 = Ps[(tr + 1) * FP + kk];
            float p2 = Ps[(tr + 2) * FP + kk];
            float p3 = Ps[(tr + 3) * FP + kk];
            float v0 = Vs[kk * FP + tc + 0];
            float v1 = Vs[kk * FP + tc + 1];
            float v2 = Vs[kk * FP + tc + 2];
            float v3 = Vs[kk * FP + tc + 3];
            o[0][0] += p0 * v0; o[0][1] += p0 * v1; o[0][2] += p0 * v2; o[0][3] += p0 * v3;
            o[1][0] += p1 * v0; o[1][1] += p1 * v1; o[1][2] += p1 * v2; o[1][3] += p1 * v3;
            o[2][0] += p2 * v0; o[2][1] += p2 * v1; o[2][2] += p2 * v2; o[2][3] += p2 * v3;
            o[3][0] += p3 * v0; o[3][1] += p3 * v1; o[3][2] += p3 * v2; o[3][3] += p3 * v3;
        }
    }

    // epilogue: O / l, written in concat layout
#pragma unroll
    for (int i = 0; i < 4; i++) {
        float rinv = 1.0f / l[i];
        float4 w = make_float4(o[i][0] * rinv, o[i][1] * rinv,
                               o[i][2] * rinv, o[i][3] * rinv);
        *(float4*)(Ocat + base + (size_t)(q0 + tr + i) * D_MODEL + tc) = w;
    }
}

// ---------------------------------------------------------------------------
// Launch
// ---------------------------------------------------------------------------
extern "C" void kernel_launch(void* const* d_in, const int* in_sizes, int n_in,
                              void* d_out, int out_size)
{
    const float* x   = (const float*)d_in[0];
    const float* W_q = (const float*)d_in[1];
    const float* W_k = (const float*)d_in[2];
    const float* W_v = (const float*)d_in[3];
    const float* W_o = (const float*)d_in[4];
    float* out = (float*)d_out;

    float *pq, *pk, *pv, *pc;
    cudaGetSymbolAddress((void**)&pq, g_q);
    cudaGetSymbolAddress((void**)&pk, g_k);
    cudaGetSymbolAddress((void**)&pv, g_v);
    cudaGetSymbolAddress((void**)&pc, g_c);

    const int SMEM_FLASH = 4 * 64 * FP * (int)sizeof(float); // 66560 B
    cudaFuncSetAttribute(flash_kernel,
                         cudaFuncAttributeMaxDynamicSharedMemorySize, SMEM_FLASH);

    dim3 gGemm(D_MODEL / 128, M_TOTAL / 128);   // (8, 64)
    dim3 bGemm(256);

    gemm_tn_kernel<<<gGemm, bGemm>>>(x, W_q, pq, M_TOTAL, D_MODEL, D_MODEL);
    gemm_tn_kernel<<<gGemm, bGemm>>>(x, W_k, pk, M_TOTAL, D_MODEL, D_MODEL);
    gemm_tn_kernel<<<gGemm, bGemm>>>(x, W_v, pv, M_TOTAL, D_MODEL, D_MODEL);

    dim3 gFlash(SEQ / 64, BATCH * N_HEADS);     // (32, 64)
    flash_kernel<<<gFlash, 256, SMEM_FLASH>>>(pq, pk, pv, pc);

    gemm_tn_kernel<<<gGemm, bGemm>>>(pc, W_o, out, M_TOTAL, D_MODEL, D_MODEL);
}

// round 6
// speedup vs baseline: 1.4809x; 1.4809x over previous
#include <cuda_runtime.h>
#include <cuda_bf16.h>
#include <cstdint>
#include <cstddef>

#define D_MODEL  1024
#define N_HEADS  16
#define HEAD_DIM 64
#define BATCH    4
#define SEQ      2048
#define M_TOTAL  (BATCH * SEQ)   // 8192

// ---------------------------------------------------------------------------
// Scratch (no cudaMalloc allowed)
// ---------------------------------------------------------------------------
__device__ float g_q[(size_t)M_TOTAL * D_MODEL];
__device__ float g_k[(size_t)M_TOTAL * D_MODEL];
__device__ float g_v[(size_t)M_TOTAL * D_MODEL];
__device__ float g_c[(size_t)M_TOTAL * D_MODEL];
__device__ __nv_bfloat16 g_xh[(size_t)M_TOTAL * D_MODEL];
__device__ __nv_bfloat16 g_xl[(size_t)M_TOTAL * D_MODEL];
__device__ __nv_bfloat16 g_ch[(size_t)M_TOTAL * D_MODEL];
__device__ __nv_bfloat16 g_cl[(size_t)M_TOTAL * D_MODEL];
__device__ __nv_bfloat16 g_wh[(size_t)4 * D_MODEL * D_MODEL];
__device__ __nv_bfloat16 g_wl[(size_t)4 * D_MODEL * D_MODEL];

// ---------------------------------------------------------------------------
// Baseline-PTX tensor-core helpers (sm_80-class; compile under compute_103)
// ---------------------------------------------------------------------------
__device__ __forceinline__ uint32_t smem_to_u32(const void* p) {
    uint32_t a;
    asm("{ .reg .u64 t; cvta.to.shared.u64 t, %1; cvt.u32.u64 %0, t; }" : "=r"(a) : "l"(p));
    return a;
}

__device__ __forceinline__ void ldsm_x4(uint32_t* r, uint32_t addr) {
    asm volatile("ldmatrix.sync.aligned.m8n8.x4.shared.b16 {%0,%1,%2,%3}, [%4];"
        : "=r"(r[0]), "=r"(r[1]), "=r"(r[2]), "=r"(r[3]) : "r"(addr));
}
// NON-trans x2: on [n][k]-major SMEM this yields the m16n8k16 B fragment
// (thread j holds {B[k=tid*2][n=grp], B[k=tid*2+1][n=grp]}).
__device__ __forceinline__ void ldsm_x2(uint32_t* r, uint32_t addr) {
    asm volatile("ldmatrix.sync.aligned.m8n8.x2.shared.b16 {%0,%1}, [%2];"
        : "=r"(r[0]), "=r"(r[1]) : "r"(addr));
}
// D += A(bf16) * B(bf16), m16n8k16, row.col
__device__ __forceinline__ void mma16816(float* d, const uint32_t* a, const uint32_t* b) {
    asm volatile(
        "mma.sync.aligned.m16n8k16.row.col.f32.bf16.bf16.f32 "
        "{%0,%1,%2,%3}, {%4,%5,%6,%7}, {%8,%9}, {%0,%1,%2,%3};"
        : "+f"(d[0]), "+f"(d[1]), "+f"(d[2]), "+f"(d[3])
        : "r"(a[0]), "r"(a[1]), "r"(a[2]), "r"(a[3]), "r"(b[0]), "r"(b[1]));
}

// ---------------------------------------------------------------------------
// fp32 -> (bf16 hi, bf16 lo) split
// ---------------------------------------------------------------------------
__global__ __launch_bounds__(256)
void split_kernel(const float* __restrict__ x, __nv_bfloat16* __restrict__ hi,
                  __nv_bfloat16* __restrict__ lo, int n4)
{
    int i = blockIdx.x * 256 + threadIdx.x;
    if (i >= n4) return;
    float4 v = ((const float4*)x)[i];
    __nv_bfloat16 h0 = __float2bfloat16(v.x);
    __nv_bfloat16 h1 = __float2bfloat16(v.y);
    __nv_bfloat16 h2 = __float2bfloat16(v.z);
    __nv_bfloat16 h3 = __float2bfloat16(v.w);
    __nv_bfloat16 l0 = __float2bfloat16(v.x - __bfloat162float(h0));
    __nv_bfloat16 l1 = __float2bfloat16(v.y - __bfloat162float(h1));
    __nv_bfloat16 l2 = __float2bfloat16(v.z - __bfloat162float(h2));
    __nv_bfloat16 l3 = __float2bfloat16(v.w - __bfloat162float(h3));
    __nv_bfloat162 hp0; hp0.x = h0; hp0.y = h1;
    __nv_bfloat162 hp1; hp1.x = h2; hp1.y = h3;
    __nv_bfloat162 lp0; lp0.x = l0; lp0.y = l1;
    __nv_bfloat162 lp1; lp1.x = l2; lp1.y = l3;
    ((__nv_bfloat162*)hi)[2 * i]     = hp0;
    ((__nv_bfloat162*)hi)[2 * i + 1] = hp1;
    ((__nv_bfloat162*)lo)[2 * i]     = lp0;
    ((__nv_bfloat162*)lo)[2 * i + 1] = lp1;
}

// ---------------------------------------------------------------------------
// mma.sync split-bf16 GEMM: C[m][n] = sum_k A[m,k]*B[n,k]  (both K-major)
// C = Ah*Bh + Ah*Bl + Al*Bh. 128x128 CTA tile, 8 warps (2x4), 64x32 warp tile.
// SMEM rows padded to 72 bf16 (144B) -> conflict-free ldmatrix.
// ---------------------------------------------------------------------------
#define BK 64
#define SROW 72                              // padded row, bf16 elements
#define TILE_B (128 * SROW * 2)              // 18432 bytes per tile
#define SMEM_GEMM (4 * TILE_B)               // 73728 bytes

__global__ __launch_bounds__(256, 1)
void mma_gemm_kernel(const __nv_bfloat16* __restrict__ Ah, const __nv_bfloat16* __restrict__ Al,
                     const __nv_bfloat16* __restrict__ Bh, const __nv_bfloat16* __restrict__ Bl,
                     float* __restrict__ C, int M, int N, int K)
{
    extern __shared__ char smem[];
    const int tid  = threadIdx.x;
    const int warp = tid >> 5;
    const int lane = tid & 31;
    const int bm = blockIdx.y * 128;
    const int bn = blockIdx.x * 128;
    const int wm = (warp >> 2) * 64;          // 0 or 64
    const int wn = (warp & 3) * 32;           // 0,32,64,96

    char* sAh = smem;
    char* sAl = smem + TILE_B;
    char* sBh = smem + 2 * TILE_B;
    char* sBl = smem + 3 * TILE_B;
    const uint32_t uAh = smem_to_u32(sAh);
    const uint32_t uAl = smem_to_u32(sAl);
    const uint32_t uBh = smem_to_u32(sBh);
    const uint32_t uBl = smem_to_u32(sBl);

    // ldmatrix per-lane addressing
    const int a_row  = lane & 15;             // lanes 0-15: rows, 16-31: rows (k+8)
    const int a_koff = (lane >> 4) << 3;      // 0 or 8
    const int b_row  = lane & 7;
    const int b_koff = ((lane >> 3) & 1) << 3;

    float acc[4][4][4];
#pragma unroll
    for (int i = 0; i < 4; i++)
#pragma unroll
        for (int j = 0; j < 4; j++)
#pragma unroll
            for (int t = 0; t < 4; t++) acc[i][j][t] = 0.f;

    const int nchunks = K / BK;
    for (int ch = 0; ch < nchunks; ch++) {
        const int k0g = ch * BK;
        __syncthreads();   // previous chunk's frag reads done
        // load 4 tiles: 128 rows x 64 bf16 (128B) each; 256 thr x 4 iters x 16B
#pragma unroll
        for (int it = 0; it < 4; it++) {
            int lin = tid + it * 256;          // 0..1023
            int r  = lin >> 3;                 // 0..127
            int c8 = (lin & 7) << 3;           // 0,8,..,56
            size_t ga = (size_t)(bm + r) * K + k0g + c8;
            size_t gb = (size_t)(bn + r) * K + k0g + c8;
            uint32_t so = (uint32_t)(r * SROW + c8) * 2;
            *(uint4*)(sAh + so) = *(const uint4*)(Ah + ga);
            *(uint4*)(sAl + so) = *(const uint4*)(Al + ga);
            *(uint4*)(sBh + so) = *(const uint4*)(Bh + gb);
            *(uint4*)(sBl + so) = *(const uint4*)(Bl + gb);
        }
        __syncthreads();

#pragma unroll
        for (int ks = 0; ks < 4; ks++) {
            const int k0 = ks * 16;
            uint32_t ah[4][4], al[4][4], bh[4][2], bl[4][2];
#pragma unroll
            for (int i = 0; i < 4; i++) {
                uint32_t off = (uint32_t)((wm + i * 16 + a_row) * SROW + k0 + a_koff) * 2;
                ldsm_x4(ah[i], uAh + off);
                ldsm_x4(al[i], uAl + off);
            }
#pragma unroll
            for (int j = 0; j < 4; j++) {
                uint32_t off = (uint32_t)((wn + j * 8 + b_row) * SROW + k0 + b_koff) * 2;
                ldsm_x2(bh[j], uBh + off);
                ldsm_x2(bl[j], uBl + off);
            }
#pragma unroll
            for (int i = 0; i < 4; i++)
#pragma unroll
                for (int j = 0; j < 4; j++) {
                    mma16816(acc[i][j], ah[i], bh[j]);
                    mma16816(acc[i][j], ah[i], bl[j]);
                    mma16816(acc[i][j], al[i], bh[j]);
                }
        }
    }

    // epilogue: direct register -> GMEM (float2 stores)
    const int gr = lane >> 2;                 // 0..7
    const int gc = (lane & 3) << 1;           // 0,2,4,6
#pragma unroll
    for (int i = 0; i < 4; i++) {
#pragma unroll
        for (int j = 0; j < 4; j++) {
            size_t r0 = (size_t)(bm + wm + i * 16 + gr) * N + bn + wn + j * 8 + gc;
            size_t r1 = r0 + (size_t)8 * N;
            *(float2*)(C + r0) = make_float2(acc[i][j][0], acc[i][j][1]);
            *(float2*)(C + r1) = make_float2(acc[i][j][2], acc[i][j][3]);
        }
    }
}

// ---------------------------------------------------------------------------
// Causal flash attention, fp32 (unchanged).
// ---------------------------------------------------------------------------
__device__ __forceinline__ float fast_exp2(float x) {
    float y;
    asm("ex2.approx.ftz.f32 %0, %1;" : "=f"(y) : "f"(x));
    return y;
}

#define FP 65   // padded smem stride

__global__ __launch_bounds__(256)
void flash_kernel(const float* __restrict__ Qg, const float* __restrict__ Kg,
                  const float* __restrict__ Vg, float* __restrict__ Ocat)
{
    extern __shared__ float sm[];
    float* Qs = sm;
    float* Ks = sm + 64 * FP;
    float* Vs = sm + 2 * 64 * FP;
    float* Ps = sm + 3 * 64 * FP;

    const int tid = threadIdx.x;
    const int qi  = blockIdx.x;
    const int bh  = blockIdx.y;
    const int b   = bh >> 4;
    const int h   = bh & 15;
    const int q0  = qi << 6;
    const int tr  = (tid >> 4) << 2;
    const int tc  = (tid & 15) << 2;

    const size_t base = (size_t)b * SEQ * D_MODEL + (size_t)h * HEAD_DIM;
    const float* qb = Qg + base;
    const float* kb = Kg + base;
    const float* vb = Vg + base;

#pragma unroll
    for (int it = 0; it < 4; it++) {
        int lin = tid + it * 256;
        int r   = lin >> 4;
        int d4  = (lin & 15) << 2;
        float4 t = *(const float4*)(qb + (size_t)(q0 + r) * D_MODEL + d4);
        Qs[(d4 + 0) * FP + r] = t.x;
        Qs[(d4 + 1) * FP + r] = t.y;
        Qs[(d4 + 2) * FP + r] = t.z;
        Qs[(d4 + 3) * FP + r] = t.w;
    }

    const float NEG_INF = __int_as_float(0xff800000u);
    float m2[4], l[4], o[4][4];
#pragma unroll
    for (int i = 0; i < 4; i++) {
        m2[i] = NEG_INF; l[i] = 0.f;
#pragma unroll
        for (int j = 0; j < 4; j++) o[i][j] = 0.f;
    }

    const float CSC = 0.125f * 1.4426950408889634f;

    for (int kt = 0; kt <= qi; kt++) {
        __syncthreads();
#pragma unroll
        for (int it = 0; it < 4; it++) {
            int lin = tid + it * 256;
            int r   = lin >> 4;
            int d4  = (lin & 15) << 2;
            size_t go = (size_t)((kt << 6) + r) * D_MODEL + d4;
            float4 tk = *(const float4*)(kb + go);
            float4 tv = *(const float4*)(vb + go);
            Ks[(d4 + 0) * FP + r] = tk.x;
            Ks[(d4 + 1) * FP + r] = tk.y;
            Ks[(d4 + 2) * FP + r] = tk.z;
            Ks[(d4 + 3) * FP + r] = tk.w;
            Vs[r * FP + d4 + 0] = tv.x;
            Vs[r * FP + d4 + 1] = tv.y;
            Vs[r * FP + d4 + 2] = tv.z;
            Vs[r * FP + d4 + 3] = tv.w;
        }
        __syncthreads();

        float s[4][4];
#pragma unroll
        for (int i = 0; i < 4; i++)
#pragma unroll
            for (int j = 0; j < 4; j++) s[i][j] = 0.f;

#pragma unroll 16
        for (int d = 0; d < 64; d++) {
            float a0 = Qs[d * FP + tr + 0];
            float a1 = Qs[d * FP + tr + 1];
            float a2 = Qs[d * FP + tr + 2];
            float a3 = Qs[d * FP + tr + 3];
            float e0 = Ks[d * FP + tc + 0];
            float e1 = Ks[d * FP + tc + 1];
            float e2 = Ks[d * FP + tc + 2];
            float e3 = Ks[d * FP + tc + 3];
            s[0][0] += a0 * e0; s[0][1] += a0 * e1; s[0][2] += a0 * e2; s[0][3] += a0 * e3;
            s[1][0] += a1 * e0; s[1][1] += a1 * e1; s[1][2] += a1 * e2; s[1][3] += a1 * e3;
            s[2][0] += a2 * e0; s[2][1] += a2 * e1; s[2][2] += a2 * e2; s[2][3] += a2 * e3;
            s[3][0] += a3 * e0; s[3][1] += a3 * e1; s[3][2] += a3 * e2; s[3][3] += a3 * e3;
        }

        const bool diag = (kt == qi);
#pragma unroll
        for (int i = 0; i < 4; i++)
#pragma unroll
            for (int j = 0; j < 4; j++) {
                float t = s[i][j] * CSC;
                if (diag && (tc + j) > (tr + i)) t = NEG_INF;
                s[i][j] = t;
            }

#pragma unroll
        for (int i = 0; i < 4; i++) {
            float rm = fmaxf(fmaxf(s[i][0], s[i][1]), fmaxf(s[i][2], s[i][3]));
#pragma unroll
            for (int off = 8; off >= 1; off >>= 1)
                rm = fmaxf(rm, __shfl_xor_sync(0xffffffffu, rm, off));
            float mn = fmaxf(m2[i], rm);
            float rs = 0.f;
#pragma unroll
            for (int j = 0; j < 4; j++) {
                float p = fast_exp2(s[i][j] - mn);
                Ps[(tr + i) * FP + tc + j] = p;
                rs += p;
            }
#pragma unroll
            for (int off = 8; off >= 1; off >>= 1)
                rs += __shfl_xor_sync(0xffffffffu, rs, off);
            float sc = fast_exp2(m2[i] - mn);
            l[i]  = l[i] * sc + rs;
            m2[i] = mn;
#pragma unroll
            for (int j = 0; j < 4; j++) o[i][j] *= sc;
        }
        __syncthreads();

#pragma unroll 16
        for (int kk = 0; kk < 64; kk++) {
            float p0 = Ps[(tr + 0) * FP + kk];
            float p1 = Ps[(tr + 1) * FP + kk];
            float p2 = Ps[(tr + 2) * FP + kk];
            float p3 = Ps[(tr + 3) * FP + kk];
            float v0 = Vs[kk * FP + tc + 0];
            float v1 = Vs[kk * FP + tc + 1];
            float v2 = Vs[kk * FP + tc + 2];
            float v3 = Vs[kk * FP + tc + 3];
            o[0][0] += p0 * v0; o[0][1] += p0 * v1; o[0][2] += p0 * v2; o[0][3] += p0 * v3;
            o[1][0] += p1 * v0; o[1][1] += p1 * v1; o[1][2] += p1 * v2; o[1][3] += p1 * v3;
            o[2][0] += p2 * v0; o[2][1] += p2 * v1; o[2][2] += p2 * v2; o[2][3] += p2 * v3;
            o[3][0] += p3 * v0; o[3][1] += p3 * v1; o[3][2] += p3 * v2; o[3][3] += p3 * v3;
        }
    }

#pragma unroll
    for (int i = 0; i < 4; i++) {
        float rinv = 1.0f / l[i];
        float4 w = make_float4(o[i][0] * rinv, o[i][1] * rinv,
                               o[i][2] * rinv, o[i][3] * rinv);
        *(float4*)(Ocat + base + (size_t)(q0 + tr + i) * D_MODEL + tc) = w;
    }
}

// ---------------------------------------------------------------------------
// Launch
// ---------------------------------------------------------------------------
extern "C" void kernel_launch(void* const* d_in, const int* in_sizes, int n_in,
                              void* d_out, int out_size)
{
    const float* x   = (const float*)d_in[0];
    const float* W_q = (const float*)d_in[1];
    const float* W_k = (const float*)d_in[2];
    const float* W_v = (const float*)d_in[3];
    const float* W_o = (const float*)d_in[4];
    float* out = (float*)d_out;

    float *pq, *pk, *pv, *pc;
    __nv_bfloat16 *pxh, *pxl, *pch, *pcl, *pwh, *pwl;
    cudaGetSymbolAddress((void**)&pq,  g_q);
    cudaGetSymbolAddress((void**)&pk,  g_k);
    cudaGetSymbolAddress((void**)&pv,  g_v);
    cudaGetSymbolAddress((void**)&pc,  g_c);
    cudaGetSymbolAddress((void**)&pxh, g_xh);
    cudaGetSymbolAddress((void**)&pxl, g_xl);
    cudaGetSymbolAddress((void**)&pch, g_ch);
    cudaGetSymbolAddress((void**)&pcl, g_cl);
    cudaGetSymbolAddress((void**)&pwh, g_wh);
    cudaGetSymbolAddress((void**)&pwl, g_wl);

    const int SMEM_FLASH = 4 * 64 * FP * (int)sizeof(float);
    cudaFuncSetAttribute(flash_kernel,
                         cudaFuncAttributeMaxDynamicSharedMemorySize, SMEM_FLASH);
    cudaFuncSetAttribute(mma_gemm_kernel,
                         cudaFuncAttributeMaxDynamicSharedMemorySize, SMEM_GEMM);

    const size_t WSZ = (size_t)D_MODEL * D_MODEL;   // 1048576
    const int nx4 = (int)((size_t)M_TOTAL * D_MODEL / 4);
    const int nw4 = (int)(WSZ / 4);

    // split x and weights into bf16 hi/lo
    split_kernel<<<(nx4 + 255) / 256, 256>>>(x, pxh, pxl, nx4);
    split_kernel<<<(nw4 + 255) / 256, 256>>>(W_q, pwh + 0 * WSZ, pwl + 0 * WSZ, nw4);
    split_kernel<<<(nw4 + 255) / 256, 256>>>(W_k, pwh + 1 * WSZ, pwl + 1 * WSZ, nw4);
    split_kernel<<<(nw4 + 255) / 256, 256>>>(W_v, pwh + 2 * WSZ, pwl + 2 * WSZ, nw4);
    split_kernel<<<(nw4 + 255) / 256, 256>>>(W_o, pwh + 3 * WSZ, pwl + 3 * WSZ, nw4);

    dim3 gGemm(D_MODEL / 128, M_TOTAL / 128);   // (8, 64)
    mma_gemm_kernel<<<gGemm, 256, SMEM_GEMM>>>(pxh, pxl, pwh + 0 * WSZ, pwl + 0 * WSZ,
                                               pq, M_TOTAL, D_MODEL, D_MODEL);
    mma_gemm_kernel<<<gGemm, 256, SMEM_GEMM>>>(pxh, pxl, pwh + 1 * WSZ, pwl + 1 * WSZ,
                                               pk, M_TOTAL, D_MODEL, D_MODEL);
    mma_gemm_kernel<<<gGemm, 256, SMEM_GEMM>>>(pxh, pxl, pwh + 2 * WSZ, pwl + 2 * WSZ,
                                               pv, M_TOTAL, D_MODEL, D_MODEL);

    dim3 gFlash(SEQ / 64, BATCH * N_HEADS);     // (32, 64)
    flash_kernel<<<gFlash, 256, SMEM_FLASH>>>(pq, pk, pv, pc);

    split_kernel<<<(nx4 + 255) / 256, 256>>>(pc, pch, pcl, nx4);
    mma_gemm_kernel<<<gGemm, 256, SMEM_GEMM>>>(pch, pcl, pwh + 3 * WSZ, pwl + 3 * WSZ,
                                               out, M_TOTAL, D_MODEL, D_MODEL);
}

// round 7
// speedup vs baseline: 2.6147x; 1.7656x over previous
#include <cuda_runtime.h>
#include <cuda_bf16.h>
#include <cstdint>
#include <cstddef>

#define D_MODEL  1024
#define N_HEADS  16
#define HEAD_DIM 64
#define BATCH    4
#define SEQ      2048
#define M_TOTAL  (BATCH * SEQ)   // 8192

// ---------------------------------------------------------------------------
// Scratch (no cudaMalloc allowed)
// ---------------------------------------------------------------------------
__device__ float g_q[(size_t)M_TOTAL * D_MODEL];
__device__ float g_k[(size_t)M_TOTAL * D_MODEL];
__device__ float g_v[(size_t)M_TOTAL * D_MODEL];
__device__ __nv_bfloat16 g_xh[(size_t)M_TOTAL * D_MODEL];
__device__ __nv_bfloat16 g_xl[(size_t)M_TOTAL * D_MODEL];
__device__ __nv_bfloat16 g_ch[(size_t)M_TOTAL * D_MODEL];
__device__ __nv_bfloat16 g_cl[(size_t)M_TOTAL * D_MODEL];
__device__ __nv_bfloat16 g_wh[(size_t)4 * D_MODEL * D_MODEL];
__device__ __nv_bfloat16 g_wl[(size_t)4 * D_MODEL * D_MODEL];

// ---------------------------------------------------------------------------
// Baseline-PTX tensor-core helpers (sm_80-class; compile under compute_103)
// ---------------------------------------------------------------------------
__device__ __forceinline__ uint32_t smem_to_u32(const void* p) {
    uint32_t a;
    asm("{ .reg .u64 t; cvta.to.shared.u64 t, %1; cvt.u32.u64 %0, t; }" : "=r"(a) : "l"(p));
    return a;
}

__device__ __forceinline__ void ldsm_x4(uint32_t* r, uint32_t addr) {
    asm volatile("ldmatrix.sync.aligned.m8n8.x4.shared.b16 {%0,%1,%2,%3}, [%4];"
        : "=r"(r[0]), "=r"(r[1]), "=r"(r[2]), "=r"(r[3]) : "r"(addr));
}
// NON-trans x2: on [n][k]-major SMEM -> m16n8k16 B fragment.
__device__ __forceinline__ void ldsm_x2(uint32_t* r, uint32_t addr) {
    asm volatile("ldmatrix.sync.aligned.m8n8.x2.shared.b16 {%0,%1}, [%2];"
        : "=r"(r[0]), "=r"(r[1]) : "r"(addr));
}
// TRANS x2: on [k][n]-major SMEM (rows = k) -> m16n8k16 B fragment.
__device__ __forceinline__ void ldsm_x2_t(uint32_t* r, uint32_t addr) {
    asm volatile("ldmatrix.sync.aligned.m8n8.x2.trans.shared.b16 {%0,%1}, [%2];"
        : "=r"(r[0]), "=r"(r[1]) : "r"(addr));
}
// D += A(bf16) * B(bf16), m16n8k16, row.col
__device__ __forceinline__ void mma16816(float* d, const uint32_t* a, const uint32_t* b) {
    asm volatile(
        "mma.sync.aligned.m16n8k16.row.col.f32.bf16.bf16.f32 "
        "{%0,%1,%2,%3}, {%4,%5,%6,%7}, {%8,%9}, {%0,%1,%2,%3};"
        : "+f"(d[0]), "+f"(d[1]), "+f"(d[2]), "+f"(d[3])
        : "r"(a[0]), "r"(a[1]), "r"(a[2]), "r"(a[3]), "r"(b[0]), "r"(b[1]));
}

__device__ __forceinline__ float fast_exp2(float x) {
    float y;
    asm("ex2.approx.ftz.f32 %0, %1;" : "=f"(y) : "f"(x));
    return y;
}

// pack two floats to bf16x2 (hi) and return residual floats
__device__ __forceinline__ uint32_t pack_bf2(float a, float b) {
    __nv_bfloat162 h = __floats2bfloat162_rn(a, b);
    return reinterpret_cast<uint32_t&>(h);
}
__device__ __forceinline__ uint32_t pack_bf2_hi(float a, float b, float& ra, float& rb) {
    __nv_bfloat162 h = __floats2bfloat162_rn(a, b);
    ra = a - __bfloat162float(h.x);
    rb = b - __bfloat162float(h.y);
    return reinterpret_cast<uint32_t&>(h);
}

// ---------------------------------------------------------------------------
// fp32 -> (bf16 hi, bf16 lo) split
// ---------------------------------------------------------------------------
__global__ __launch_bounds__(256)
void split_kernel(const float* __restrict__ x, __nv_bfloat16* __restrict__ hi,
                  __nv_bfloat16* __restrict__ lo, int n4)
{
    int i = blockIdx.x * 256 + threadIdx.x;
    if (i >= n4) return;
    float4 v = ((const float4*)x)[i];
    float rx, ry, rz, rw;
    uint32_t h0 = pack_bf2_hi(v.x, v.y, rx, ry);
    uint32_t h1 = pack_bf2_hi(v.z, v.w, rz, rw);
    uint32_t l0 = pack_bf2(rx, ry);
    uint32_t l1 = pack_bf2(rz, rw);
    ((uint32_t*)hi)[2 * i]     = h0;
    ((uint32_t*)hi)[2 * i + 1] = h1;
    ((uint32_t*)lo)[2 * i]     = l0;
    ((uint32_t*)lo)[2 * i + 1] = l1;
}

// ---------------------------------------------------------------------------
// mma.sync split-bf16 GEMM (unchanged from round 6, verified)
// ---------------------------------------------------------------------------
#define BK 64
#define SROW 72                              // padded row, bf16 elements
#define TILE_B (128 * SROW * 2)              // 18432 bytes per tile
#define SMEM_GEMM (4 * TILE_B)               // 73728 bytes

__global__ __launch_bounds__(256, 1)
void mma_gemm_kernel(const __nv_bfloat16* __restrict__ Ah, const __nv_bfloat16* __restrict__ Al,
                     const __nv_bfloat16* __restrict__ Bh, const __nv_bfloat16* __restrict__ Bl,
                     float* __restrict__ C, int M, int N, int K)
{
    extern __shared__ char smem[];
    const int tid  = threadIdx.x;
    const int warp = tid >> 5;
    const int lane = tid & 31;
    const int bm = blockIdx.y * 128;
    const int bn = blockIdx.x * 128;
    const int wm = (warp >> 2) * 64;
    const int wn = (warp & 3) * 32;

    char* sAh = smem;
    char* sAl = smem + TILE_B;
    char* sBh = smem + 2 * TILE_B;
    char* sBl = smem + 3 * TILE_B;
    const uint32_t uAh = smem_to_u32(sAh);
    const uint32_t uAl = smem_to_u32(sAl);
    const uint32_t uBh = smem_to_u32(sBh);
    const uint32_t uBl = smem_to_u32(sBl);

    const int a_row  = lane & 15;
    const int a_koff = (lane >> 4) << 3;
    const int b_row  = lane & 7;
    const int b_koff = ((lane >> 3) & 1) << 3;

    float acc[4][4][4];
#pragma unroll
    for (int i = 0; i < 4; i++)
#pragma unroll
        for (int j = 0; j < 4; j++)
#pragma unroll
            for (int t = 0; t < 4; t++) acc[i][j][t] = 0.f;

    const int nchunks = K / BK;
    for (int ch = 0; ch < nchunks; ch++) {
        const int k0g = ch * BK;
        __syncthreads();
#pragma unroll
        for (int it = 0; it < 4; it++) {
            int lin = tid + it * 256;
            int r  = lin >> 3;
            int c8 = (lin & 7) << 3;
            size_t ga = (size_t)(bm + r) * K + k0g + c8;
            size_t gb = (size_t)(bn + r) * K + k0g + c8;
            uint32_t so = (uint32_t)(r * SROW + c8) * 2;
            *(uint4*)(sAh + so) = *(const uint4*)(Ah + ga);
            *(uint4*)(sAl + so) = *(const uint4*)(Al + ga);
            *(uint4*)(sBh + so) = *(const uint4*)(Bh + gb);
            *(uint4*)(sBl + so) = *(const uint4*)(Bl + gb);
        }
        __syncthreads();

#pragma unroll
        for (int ks = 0; ks < 4; ks++) {
            const int k0 = ks * 16;
            uint32_t ah[4][4], al[4][4], bh[4][2], bl[4][2];
#pragma unroll
            for (int i = 0; i < 4; i++) {
                uint32_t off = (uint32_t)((wm + i * 16 + a_row) * SROW + k0 + a_koff) * 2;
                ldsm_x4(ah[i], uAh + off);
                ldsm_x4(al[i], uAl + off);
            }
#pragma unroll
            for (int j = 0; j < 4; j++) {
                uint32_t off = (uint32_t)((wn + j * 8 + b_row) * SROW + k0 + b_koff) * 2;
                ldsm_x2(bh[j], uBh + off);
                ldsm_x2(bl[j], uBl + off);
            }
#pragma unroll
            for (int i = 0; i < 4; i++)
#pragma unroll
                for (int j = 0; j < 4; j++) {
                    mma16816(acc[i][j], ah[i], bh[j]);
                    mma16816(acc[i][j], ah[i], bl[j]);
                    mma16816(acc[i][j], al[i], bh[j]);
                }
        }
    }

    const int gr = lane >> 2;
    const int gc = (lane & 3) << 1;
#pragma unroll
    for (int i = 0; i < 4; i++) {
#pragma unroll
        for (int j = 0; j < 4; j++) {
            size_t r0 = (size_t)(bm + wm + i * 16 + gr) * N + bn + wn + j * 8 + gc;
            size_t r1 = r0 + (size_t)8 * N;
            *(float2*)(C + r0) = make_float2(acc[i][j][0], acc[i][j][1]);
            *(float2*)(C + r1) = make_float2(acc[i][j][2], acc[i][j][3]);
        }
    }
}

// ---------------------------------------------------------------------------
// Tensor-core causal flash attention (split-bf16 via mma.sync).
// CTA: 256 thr (8 warps), Q tile 128 rows, KV tile 64. Warp owns 16 rows.
// Writes concat output directly as bf16 hi/lo for the O-projection GEMM.
// ---------------------------------------------------------------------------
#define FSROW 72
#define FSMEM ((2 * 128 + 4 * 64) * FSROW * 2)   // 73728 bytes

__global__ __launch_bounds__(256, 1)
void flash_mma_kernel(const float* __restrict__ Qg, const float* __restrict__ Kg,
                      const float* __restrict__ Vg,
                      __nv_bfloat16* __restrict__ Oh, __nv_bfloat16* __restrict__ Ol)
{
    extern __shared__ char fsm[];
    __nv_bfloat16* sQh = (__nv_bfloat16*)fsm;          // [128][FSROW]
    __nv_bfloat16* sQl = sQh + 128 * FSROW;
    __nv_bfloat16* sKh = sQl + 128 * FSROW;            // [64][FSROW]
    __nv_bfloat16* sKl = sKh + 64 * FSROW;
    __nv_bfloat16* sVh = sKl + 64 * FSROW;
    __nv_bfloat16* sVl = sVh + 64 * FSROW;
    const uint32_t uQh = smem_to_u32(sQh);
    const uint32_t uQl = smem_to_u32(sQl);
    const uint32_t uKh = smem_to_u32(sKh);
    const uint32_t uKl = smem_to_u32(sKl);
    const uint32_t uVh = smem_to_u32(sVh);
    const uint32_t uVl = smem_to_u32(sVl);

    const int tid  = threadIdx.x;
    const int warp = tid >> 5;
    const int lane = tid & 31;
    const int qi = blockIdx.x;                 // 0..15
    const int bh = blockIdx.y;                 // b*16+h
    const int b = bh >> 4, h = bh & 15;
    const int q0 = qi << 7;                    // 128-row tile base
    const int wm = warp << 4;                  // warp row base in tile

    const size_t base = (size_t)b * SEQ * D_MODEL + (size_t)h * HEAD_DIM;
    const float* qb = Qg + base;
    const float* kb = Kg + base;
    const float* vb = Vg + base;

    // ---- load Q tile (128x64 fp32) -> bf16 hi/lo SMEM ----
    uint32_t* wQh = (uint32_t*)sQh;
    uint32_t* wQl = (uint32_t*)sQl;
#pragma unroll
    for (int it = 0; it < 8; it++) {
        int lin = tid + it * 256;              // 0..2047
        int r   = lin >> 4;
        int c4  = (lin & 15) << 2;
        float4 t = *(const float4*)(qb + (size_t)(q0 + r) * D_MODEL + c4);
        float rx, ry, rz, rw;
        uint32_t h0 = pack_bf2_hi(t.x, t.y, rx, ry);
        uint32_t h1 = pack_bf2_hi(t.z, t.w, rz, rw);
        int u = (r * FSROW + c4) >> 1;
        wQh[u]     = h0;  wQh[u + 1] = h1;
        wQl[u]     = pack_bf2(rx, ry);
        wQl[u + 1] = pack_bf2(rz, rw);
    }
    __syncthreads();

    // ---- Q fragments (held for whole kernel) ----
    uint32_t qh[4][4], ql[4][4];
    {
        const int ar = lane & 15;
        const int ak = (lane >> 4) << 3;
#pragma unroll
        for (int ks = 0; ks < 4; ks++) {
            uint32_t off = (uint32_t)((wm + ar) * FSROW + ks * 16 + ak) * 2;
            ldsm_x4(qh[ks], uQh + off);
            ldsm_x4(ql[ks], uQl + off);
        }
    }

    const float NEG = -1e30f;
    const float CSC = 0.125f * 1.4426950408889634f;   // (1/sqrt(64))*log2(e)
    float m0 = NEG, m1 = NEG, l0 = 0.f, l1 = 0.f;
    float ov[8][4];
#pragma unroll
    for (int j = 0; j < 8; j++)
#pragma unroll
        for (int t = 0; t < 4; t++) ov[j][t] = 0.f;

    const int r0g = q0 + wm + (lane >> 2);
    const int r1g = r0g + 8;
    const int br  = lane & 7;
    const int bk  = ((lane >> 3) & 1) << 3;
    const int vr  = lane & 15;

    uint32_t* wKh = (uint32_t*)sKh;
    uint32_t* wKl = (uint32_t*)sKl;
    uint32_t* wVh = (uint32_t*)sVh;
    uint32_t* wVl = (uint32_t*)sVl;

    const int kend = 2 * qi + 2;
    for (int kt = 0; kt < kend; kt++) {
        __syncthreads();
        // ---- load K,V tiles (64x64 fp32 each) -> bf16 hi/lo ----
#pragma unroll
        for (int it = 0; it < 4; it++) {
            int lin = tid + it * 256;          // 0..1023
            int r   = lin >> 4;
            int c4  = (lin & 15) << 2;
            size_t go = (size_t)((kt << 6) + r) * D_MODEL + c4;
            int u = (r * FSROW + c4) >> 1;
            float rx, ry, rz, rw;
            float4 tk = *(const float4*)(kb + go);
            uint32_t kh0 = pack_bf2_hi(tk.x, tk.y, rx, ry);
            uint32_t kh1 = pack_bf2_hi(tk.z, tk.w, rz, rw);
            wKh[u] = kh0; wKh[u + 1] = kh1;
            wKl[u]     = pack_bf2(rx, ry);
            wKl[u + 1] = pack_bf2(rz, rw);
            float4 tv = *(const float4*)(vb + go);
            uint32_t vh0 = pack_bf2_hi(tv.x, tv.y, rx, ry);
            uint32_t vh1 = pack_bf2_hi(tv.z, tv.w, rz, rw);
            wVh[u] = vh0; wVh[u + 1] = vh1;
            wVl[u]     = pack_bf2(rx, ry);
            wVl[u + 1] = pack_bf2(rz, rw);
        }
        __syncthreads();

        // ---- S = Q K^T (split bf16: 3 MMAs per step) ----
        float s[8][4];
#pragma unroll
        for (int j = 0; j < 8; j++)
#pragma unroll
            for (int t = 0; t < 4; t++) s[j][t] = 0.f;

#pragma unroll
        for (int j = 0; j < 8; j++) {
#pragma unroll
            for (int ks = 0; ks < 4; ks++) {
                uint32_t kbh[2], kbl[2];
                uint32_t off = (uint32_t)((j * 8 + br) * FSROW + ks * 16 + bk) * 2;
                ldsm_x2(kbh, uKh + off);
                ldsm_x2(kbl, uKl + off);
                mma16816(s[j], qh[ks], kbh);
                mma16816(s[j], qh[ks], kbl);
                mma16816(s[j], ql[ks], kbh);
            }
        }

        // ---- scale + causal mask ----
        const bool diag = (kt >= 2 * qi);
#pragma unroll
        for (int j = 0; j < 8; j++) {
            s[j][0] *= CSC; s[j][1] *= CSC; s[j][2] *= CSC; s[j][3] *= CSC;
            if (diag) {
                int cb = (kt << 6) + j * 8 + ((lane & 3) << 1);
                if (cb     > r0g) s[j][0] = NEG;
                if (cb + 1 > r0g) s[j][1] = NEG;
                if (cb     > r1g) s[j][2] = NEG;
                if (cb + 1 > r1g) s[j][3] = NEG;
            }
        }

        // ---- row max (per-thread, then over 4 lanes sharing the row) ----
        float rm0 = NEG, rm1 = NEG;
#pragma unroll
        for (int j = 0; j < 8; j++) {
            rm0 = fmaxf(rm0, fmaxf(s[j][0], s[j][1]));
            rm1 = fmaxf(rm1, fmaxf(s[j][2], s[j][3]));
        }
        rm0 = fmaxf(rm0, __shfl_xor_sync(0xffffffffu, rm0, 1));
        rm0 = fmaxf(rm0, __shfl_xor_sync(0xffffffffu, rm0, 2));
        rm1 = fmaxf(rm1, __shfl_xor_sync(0xffffffffu, rm1, 1));
        rm1 = fmaxf(rm1, __shfl_xor_sync(0xffffffffu, rm1, 2));

        float mn0 = fmaxf(m0, rm0);
        float mn1 = fmaxf(m1, rm1);
        float sc0 = fast_exp2(m0 - mn0);
        float sc1 = fast_exp2(m1 - mn1);
        m0 = mn0; m1 = mn1;
#pragma unroll
        for (int j = 0; j < 8; j++) {
            ov[j][0] *= sc0; ov[j][1] *= sc0;
            ov[j][2] *= sc1; ov[j][3] *= sc1;
        }

        // ---- exp, pack P (hi/lo) from accumulator, P·V ----
        float rs0 = 0.f, rs1 = 0.f;
#pragma unroll
        for (int kk = 0; kk < 4; kk++) {
            uint32_t pah[4], pal[4];
#pragma unroll
            for (int u = 0; u < 2; u++) {
                int t = 2 * kk + u;
                float p0 = fast_exp2(s[t][0] - mn0);
                float p1 = fast_exp2(s[t][1] - mn0);
                float p2 = fast_exp2(s[t][2] - mn1);
                float p3 = fast_exp2(s[t][3] - mn1);
                rs0 += p0 + p1;
                rs1 += p2 + p3;
                float e0, e1, e2, e3;
                pah[2 * u]     = pack_bf2_hi(p0, p1, e0, e1);
                pah[2 * u + 1] = pack_bf2_hi(p2, p3, e2, e3);
                pal[2 * u]     = pack_bf2(e0, e1);
                pal[2 * u + 1] = pack_bf2(e2, e3);
            }
            // fix A-frag ordering: a0 = (row r, k lo 8) from tile 2kk, a1 = (row r+8, k lo),
            // a2 = (row r, k hi 8) from tile 2kk+1, a3 = (row r+8, k hi).
            uint32_t Ah[4] = { pah[0], pah[1], pah[2], pah[3] };
            uint32_t Al[4] = { pal[0], pal[1], pal[2], pal[3] };
#pragma unroll
            for (int jv = 0; jv < 8; jv++) {
                uint32_t vbh[2], vbl[2];
                uint32_t off = (uint32_t)((kk * 16 + vr) * FSROW + jv * 8) * 2;
                ldsm_x2_t(vbh, uVh + off);
                ldsm_x2_t(vbl, uVl + off);
                mma16816(ov[jv], Ah, vbh);
                mma16816(ov[jv], Ah, vbl);
                mma16816(ov[jv], Al, vbh);
            }
        }
        rs0 += __shfl_xor_sync(0xffffffffu, rs0, 1);
        rs0 += __shfl_xor_sync(0xffffffffu, rs0, 2);
        rs1 += __shfl_xor_sync(0xffffffffu, rs1, 1);
        rs1 += __shfl_xor_sync(0xffffffffu, rs1, 2);
        l0 = l0 * sc0 + rs0;
        l1 = l1 * sc1 + rs1;
    }

    // ---- epilogue: O/l, split to bf16 hi/lo concat layout ----
    float rinv0 = 1.0f / l0;
    float rinv1 = 1.0f / l1;
    size_t orow0 = base + (size_t)(q0 + wm + (lane >> 2)) * D_MODEL;
    size_t orow1 = orow0 + (size_t)8 * D_MODEL;
    int colb = ((lane & 3) << 1);
#pragma unroll
    for (int jv = 0; jv < 8; jv++) {
        float o0 = ov[jv][0] * rinv0;
        float o1 = ov[jv][1] * rinv0;
        float o2 = ov[jv][2] * rinv1;
        float o3 = ov[jv][3] * rinv1;
        float e0, e1, e2, e3;
        uint32_t h01 = pack_bf2_hi(o0, o1, e0, e1);
        uint32_t h23 = pack_bf2_hi(o2, o3, e2, e3);
        uint32_t l01 = pack_bf2(e0, e1);
        uint32_t l23 = pack_bf2(e2, e3);
        int c = jv * 8 + colb;
        *(uint32_t*)(Oh + orow0 + c) = h01;
        *(uint32_t*)(Ol + orow0 + c) = l01;
        *(uint32_t*)(Oh + orow1 + c) = h23;
        *(uint32_t*)(Ol + orow1 + c) = l23;
    }
}

// ---------------------------------------------------------------------------
// Launch
// ---------------------------------------------------------------------------
extern "C" void kernel_launch(void* const* d_in, const int* in_sizes, int n_in,
                              void* d_out, int out_size)
{
    const float* x   = (const float*)d_in[0];
    const float* W_q = (const float*)d_in[1];
    const float* W_k = (const float*)d_in[2];
    const float* W_v = (const float*)d_in[3];
    const float* W_o = (const float*)d_in[4];
    float* out = (float*)d_out;

    float *pq, *pk, *pv;
    __nv_bfloat16 *pxh, *pxl, *pch, *pcl, *pwh, *pwl;
    cudaGetSymbolAddress((void**)&pq,  g_q);
    cudaGetSymbolAddress((void**)&pk,  g_k);
    cudaGetSymbolAddress((void**)&pv,  g_v);
    cudaGetSymbolAddress((void**)&pxh, g_xh);
    cudaGetSymbolAddress((void**)&pxl, g_xl);
    cudaGetSymbolAddress((void**)&pch, g_ch);
    cudaGetSymbolAddress((void**)&pcl, g_cl);
    cudaGetSymbolAddress((void**)&pwh, g_wh);
    cudaGetSymbolAddress((void**)&pwl, g_wl);

    cudaFuncSetAttribute(mma_gemm_kernel,
                         cudaFuncAttributeMaxDynamicSharedMemorySize, SMEM_GEMM);
    cudaFuncSetAttribute(flash_mma_kernel,
                         cudaFuncAttributeMaxDynamicSharedMemorySize, FSMEM);

    const size_t WSZ = (size_t)D_MODEL * D_MODEL;   // 1048576
    const int nx4 = (int)((size_t)M_TOTAL * D_MODEL / 4);
    const int nw4 = (int)(WSZ / 4);

    // split x and weights into bf16 hi/lo
    split_kernel<<<(nx4 + 255) / 256, 256>>>(x, pxh, pxl, nx4);
    split_kernel<<<(nw4 + 255) / 256, 256>>>(W_q, pwh + 0 * WSZ, pwl + 0 * WSZ, nw4);
    split_kernel<<<(nw4 + 255) / 256, 256>>>(W_k, pwh + 1 * WSZ, pwl + 1 * WSZ, nw4);
    split_kernel<<<(nw4 + 255) / 256, 256>>>(W_v, pwh + 2 * WSZ, pwl + 2 * WSZ, nw4);
    split_kernel<<<(nw4 + 255) / 256, 256>>>(W_o, pwh + 3 * WSZ, pwl + 3 * WSZ, nw4);

    dim3 gGemm(D_MODEL / 128, M_TOTAL / 128);   // (8, 64)
    mma_gemm_kernel<<<gGemm, 256, SMEM_GEMM>>>(pxh, pxl, pwh + 0 * WSZ, pwl + 0 * WSZ,
                                               pq, M_TOTAL, D_MODEL, D_MODEL);
    mma_gemm_kernel<<<gGemm, 256, SMEM_GEMM>>>(pxh, pxl, pwh + 1 * WSZ, pwl + 1 * WSZ,
                                               pk, M_TOTAL, D_MODEL, D_MODEL);
    mma_gemm_kernel<<<gGemm, 256, SMEM_GEMM>>>(pxh, pxl, pwh + 2 * WSZ, pwl + 2 * WSZ,
                                               pv, M_TOTAL, D_MODEL, D_MODEL);

    dim3 gFlash(SEQ / 128, BATCH * N_HEADS);    // (16, 64)
    flash_mma_kernel<<<gFlash, 256, FSMEM>>>(pq, pk, pv, pch, pcl);

    mma_gemm_kernel<<<gGemm, 256, SMEM_GEMM>>>(pch, pcl, pwh + 3 * WSZ, pwl + 3 * WSZ,
                                               out, M_TOTAL, D_MODEL, D_MODEL);
}

// round 8
// speedup vs baseline: 2.7982x; 1.0702x over previous
#include <cuda_runtime.h>
#include <cuda_bf16.h>
#include <cstdint>
#include <cstddef>

#define D_MODEL  1024
#define N_HEADS  16
#define HEAD_DIM 64
#define BATCH    4
#define SEQ      2048
#define M_TOTAL  (BATCH * SEQ)   // 8192

// ---------------------------------------------------------------------------
// Scratch (no cudaMalloc allowed)
// ---------------------------------------------------------------------------
__device__ __nv_bfloat16 g_qh[(size_t)M_TOTAL * D_MODEL];
__device__ __nv_bfloat16 g_ql[(size_t)M_TOTAL * D_MODEL];
__device__ __nv_bfloat16 g_kh[(size_t)M_TOTAL * D_MODEL];
__device__ __nv_bfloat16 g_kl[(size_t)M_TOTAL * D_MODEL];
__device__ __nv_bfloat16 g_vh[(size_t)M_TOTAL * D_MODEL];
__device__ __nv_bfloat16 g_vl[(size_t)M_TOTAL * D_MODEL];
__device__ __nv_bfloat16 g_xh[(size_t)M_TOTAL * D_MODEL];
__device__ __nv_bfloat16 g_xl[(size_t)M_TOTAL * D_MODEL];
__device__ __nv_bfloat16 g_ch[(size_t)M_TOTAL * D_MODEL];
__device__ __nv_bfloat16 g_cl[(size_t)M_TOTAL * D_MODEL];
__device__ __nv_bfloat16 g_wh[(size_t)4 * D_MODEL * D_MODEL];
__device__ __nv_bfloat16 g_wl[(size_t)4 * D_MODEL * D_MODEL];

// ---------------------------------------------------------------------------
// Baseline-PTX helpers (sm_80-class; compile under compute_103)
// ---------------------------------------------------------------------------
__device__ __forceinline__ uint32_t smem_to_u32(const void* p) {
    uint32_t a;
    asm("{ .reg .u64 t; cvta.to.shared.u64 t, %1; cvt.u32.u64 %0, t; }" : "=r"(a) : "l"(p));
    return a;
}
__device__ __forceinline__ void ldsm_x4(uint32_t* r, uint32_t addr) {
    asm volatile("ldmatrix.sync.aligned.m8n8.x4.shared.b16 {%0,%1,%2,%3}, [%4];"
        : "=r"(r[0]), "=r"(r[1]), "=r"(r[2]), "=r"(r[3]) : "r"(addr));
}
__device__ __forceinline__ void ldsm_x2(uint32_t* r, uint32_t addr) {
    asm volatile("ldmatrix.sync.aligned.m8n8.x2.shared.b16 {%0,%1}, [%2];"
        : "=r"(r[0]), "=r"(r[1]) : "r"(addr));
}
__device__ __forceinline__ void ldsm_x2_t(uint32_t* r, uint32_t addr) {
    asm volatile("ldmatrix.sync.aligned.m8n8.x2.trans.shared.b16 {%0,%1}, [%2];"
        : "=r"(r[0]), "=r"(r[1]) : "r"(addr));
}
__device__ __forceinline__ void mma16816(float* d, const uint32_t* a, const uint32_t* b) {
    asm volatile(
        "mma.sync.aligned.m16n8k16.row.col.f32.bf16.bf16.f32 "
        "{%0,%1,%2,%3}, {%4,%5,%6,%7}, {%8,%9}, {%0,%1,%2,%3};"
        : "+f"(d[0]), "+f"(d[1]), "+f"(d[2]), "+f"(d[3])
        : "r"(a[0]), "r"(a[1]), "r"(a[2]), "r"(a[3]), "r"(b[0]), "r"(b[1]));
}
__device__ __forceinline__ void cp16(uint32_t smem, const void* g) {
    asm volatile("cp.async.cg.shared.global [%0], [%1], 16;" :: "r"(smem), "l"(g));
}
#define CP_COMMIT() asm volatile("cp.async.commit_group;" ::: "memory")
#define CP_WAIT(n)  asm volatile("cp.async.wait_group %0;" :: "n"(n) : "memory")

__device__ __forceinline__ float fast_exp2(float x) {
    float y;
    asm("ex2.approx.ftz.f32 %0, %1;" : "=f"(y) : "f"(x));
    return y;
}
__device__ __forceinline__ uint32_t pack_bf2(float a, float b) {
    __nv_bfloat162 h = __floats2bfloat162_rn(a, b);
    return reinterpret_cast<uint32_t&>(h);
}
__device__ __forceinline__ uint32_t pack_bf2_hi(float a, float b, float& ra, float& rb) {
    __nv_bfloat162 h = __floats2bfloat162_rn(a, b);
    ra = a - __bfloat162float(h.x);
    rb = b - __bfloat162float(h.y);
    return reinterpret_cast<uint32_t&>(h);
}

// ---------------------------------------------------------------------------
// fp32 -> (bf16 hi, bf16 lo) split
// ---------------------------------------------------------------------------
__global__ __launch_bounds__(256)
void split_kernel(const float* __restrict__ x, __nv_bfloat16* __restrict__ hi,
                  __nv_bfloat16* __restrict__ lo, int n4)
{
    int i = blockIdx.x * 256 + threadIdx.x;
    if (i >= n4) return;
    float4 v = ((const float4*)x)[i];
    float rx, ry, rz, rw;
    uint32_t h0 = pack_bf2_hi(v.x, v.y, rx, ry);
    uint32_t h1 = pack_bf2_hi(v.z, v.w, rz, rw);
    ((uint32_t*)hi)[2 * i]     = h0;
    ((uint32_t*)hi)[2 * i + 1] = h1;
    ((uint32_t*)lo)[2 * i]     = pack_bf2(rx, ry);
    ((uint32_t*)lo)[2 * i + 1] = pack_bf2(rz, rw);
}

// ---------------------------------------------------------------------------
// mma.sync split-bf16 GEMM, 2-stage cp.async pipeline.
// C[m][n] = sum_k A[m,k]*B[n,k].  Epilogue: fp32 C, or bf16 hi/lo pair.
// ---------------------------------------------------------------------------
#define BK 64
#define SROW 72                              // padded row, bf16 elements
#define TILE_B (128 * SROW * 2)              // 18432 bytes per tile
#define STAGE_B (4 * TILE_B)                 // 73728 per stage
#define SMEM_GEMM (2 * STAGE_B)              // 147456 bytes

__global__ __launch_bounds__(256, 1)
void mma_gemm_kernel(const __nv_bfloat16* __restrict__ Ah, const __nv_bfloat16* __restrict__ Al,
                     const __nv_bfloat16* __restrict__ Bh, const __nv_bfloat16* __restrict__ Bl,
                     float* __restrict__ C,
                     __nv_bfloat16* __restrict__ Chi, __nv_bfloat16* __restrict__ Clo,
                     int M, int N, int K)
{
    extern __shared__ char smem[];
    const int tid  = threadIdx.x;
    const int warp = tid >> 5;
    const int lane = tid & 31;
    const int bm = blockIdx.y * 128;
    const int bn = blockIdx.x * 128;
    const int wm = (warp >> 2) * 64;
    const int wn = (warp & 3) * 32;

    const uint32_t sbase = smem_to_u32(smem);

    // per-thread load coords (fixed across chunks)
    const int lr  = tid >> 3;                 // 0..31 (row base, +32 per iter)
    const int lc8 = (tid & 7) << 3;           // bf16 col 0..56

    // issue cp.asyncs for one chunk into stage s
    auto issue = [&](int ch, int s) {
        const int k0g = ch * BK;
        const uint32_t st = sbase + s * STAGE_B;
#pragma unroll
        for (int it = 0; it < 4; it++) {
            int r = lr + it * 32;
            uint32_t so = (uint32_t)(r * SROW + lc8) * 2;
            size_t ga = (size_t)(bm + r) * K + k0g + lc8;
            size_t gb = (size_t)(bn + r) * K + k0g + lc8;
            cp16(st + 0 * TILE_B + so, Ah + ga);
            cp16(st + 1 * TILE_B + so, Al + ga);
            cp16(st + 2 * TILE_B + so, Bh + gb);
            cp16(st + 3 * TILE_B + so, Bl + gb);
        }
        CP_COMMIT();
    };

    const int a_row  = lane & 15;
    const int a_koff = (lane >> 4) << 3;
    const int b_row  = lane & 7;
    const int b_koff = ((lane >> 3) & 1) << 3;

    float acc[4][4][4];
#pragma unroll
    for (int i = 0; i < 4; i++)
#pragma unroll
        for (int j = 0; j < 4; j++)
#pragma unroll
            for (int t = 0; t < 4; t++) acc[i][j][t] = 0.f;

    const int nchunks = K / BK;
    issue(0, 0);

    for (int ch = 0; ch < nchunks; ch++) {
        const int s = ch & 1;
        if (ch + 1 < nchunks) {
            issue(ch + 1, 1 - s);
            CP_WAIT(1);
        } else {
            CP_WAIT(0);
        }
        __syncthreads();     // stage s data visible to all warps

        const uint32_t uAh = sbase + s * STAGE_B;
        const uint32_t uAl = uAh + TILE_B;
        const uint32_t uBh = uAh + 2 * TILE_B;
        const uint32_t uBl = uAh + 3 * TILE_B;

#pragma unroll
        for (int ks = 0; ks < 4; ks++) {
            const int k0 = ks * 16;
            uint32_t ah[4][4], al[4][4], bh[4][2], bl[4][2];
#pragma unroll
            for (int i = 0; i < 4; i++) {
                uint32_t off = (uint32_t)((wm + i * 16 + a_row) * SROW + k0 + a_koff) * 2;
                ldsm_x4(ah[i], uAh + off);
                ldsm_x4(al[i], uAl + off);
            }
#pragma unroll
            for (int j = 0; j < 4; j++) {
                uint32_t off = (uint32_t)((wn + j * 8 + b_row) * SROW + k0 + b_koff) * 2;
                ldsm_x2(bh[j], uBh + off);
                ldsm_x2(bl[j], uBl + off);
            }
#pragma unroll
            for (int i = 0; i < 4; i++)
#pragma unroll
                for (int j = 0; j < 4; j++) {
                    mma16816(acc[i][j], ah[i], bh[j]);
                    mma16816(acc[i][j], ah[i], bl[j]);
                    mma16816(acc[i][j], al[i], bh[j]);
                }
        }
        __syncthreads();     // all warps done with stage s before it is refilled
    }

    const int gr = lane >> 2;
    const int gc = (lane & 3) << 1;
    if (C) {
#pragma unroll
        for (int i = 0; i < 4; i++) {
#pragma unroll
            for (int j = 0; j < 4; j++) {
                size_t r0 = (size_t)(bm + wm + i * 16 + gr) * N + bn + wn + j * 8 + gc;
                size_t r1 = r0 + (size_t)8 * N;
                *(float2*)(C + r0) = make_float2(acc[i][j][0], acc[i][j][1]);
                *(float2*)(C + r1) = make_float2(acc[i][j][2], acc[i][j][3]);
            }
        }
    } else {
#pragma unroll
        for (int i = 0; i < 4; i++) {
#pragma unroll
            for (int j = 0; j < 4; j++) {
                size_t r0 = (size_t)(bm + wm + i * 16 + gr) * N + bn + wn + j * 8 + gc;
                size_t r1 = r0 + (size_t)8 * N;
                float e0, e1, e2, e3;
                uint32_t h01 = pack_bf2_hi(acc[i][j][0], acc[i][j][1], e0, e1);
                uint32_t h23 = pack_bf2_hi(acc[i][j][2], acc[i][j][3], e2, e3);
                *(uint32_t*)(Chi + r0) = h01;
                *(uint32_t*)(Clo + r0) = pack_bf2(e0, e1);
                *(uint32_t*)(Chi + r1) = h23;
                *(uint32_t*)(Clo + r1) = pack_bf2(e2, e3);
            }
        }
    }
}

// ---------------------------------------------------------------------------
// Tensor-core causal flash attention (split-bf16 via mma.sync).
// Q/K/V already split to bf16 hi/lo by the projection GEMM epilogues.
// CTA: 256 thr (8 warps), Q tile 128 rows, KV tile 64. Warp owns 16 rows.
// ---------------------------------------------------------------------------
#define FSROW 72
#define FSMEM ((2 * 128 + 4 * 64) * FSROW * 2)   // 73728 bytes

__global__ __launch_bounds__(256, 1)
void flash_mma_kernel(const __nv_bfloat16* __restrict__ Qh, const __nv_bfloat16* __restrict__ Ql,
                      const __nv_bfloat16* __restrict__ Kh, const __nv_bfloat16* __restrict__ Kl,
                      const __nv_bfloat16* __restrict__ Vh, const __nv_bfloat16* __restrict__ Vl,
                      __nv_bfloat16* __restrict__ Oh, __nv_bfloat16* __restrict__ Ol)
{
    extern __shared__ char fsm[];
    char* sQh = fsm;                                   // [128][FSROW] bf16
    char* sQl = sQh + 128 * FSROW * 2;
    char* sKh = sQl + 128 * FSROW * 2;                 // [64][FSROW]
    char* sKl = sKh + 64 * FSROW * 2;
    char* sVh = sKl + 64 * FSROW * 2;
    char* sVl = sVh + 64 * FSROW * 2;
    const uint32_t uQh = smem_to_u32(sQh);
    const uint32_t uQl = smem_to_u32(sQl);
    const uint32_t uKh = smem_to_u32(sKh);
    const uint32_t uKl = smem_to_u32(sKl);
    const uint32_t uVh = smem_to_u32(sVh);
    const uint32_t uVl = smem_to_u32(sVl);

    const int tid  = threadIdx.x;
    const int warp = tid >> 5;
    const int lane = tid & 31;
    const int qi = blockIdx.x;                 // 0..15
    const int bh = blockIdx.y;                 // b*16+h
    const int b = bh >> 4, h = bh & 15;
    const int q0 = qi << 7;
    const int wm = warp << 4;

    const size_t base = (size_t)b * SEQ * D_MODEL + (size_t)h * HEAD_DIM;

    // ---- load Q tile (bf16 hi/lo, direct copy) ----
    {
        const __nv_bfloat16* srcs[2] = { Qh + base, Ql + base };
        char* dsts[2] = { sQh, sQl };
#pragma unroll
        for (int it = 0; it < 8; it++) {
            int lin = tid + it * 256;          // 0..2047
            int arr = lin >> 10;               // 0..1
            int idx = lin & 1023;
            int r   = idx >> 3;
            int c8  = (idx & 7) << 3;
            uint4 t = *(const uint4*)(srcs[arr] + (size_t)(q0 + r) * D_MODEL + c8);
            char* d = dsts[arr] + (r * FSROW + c8) * 2;
            *(uint2*)(d)     = make_uint2(t.x, t.y);
            *(uint2*)(d + 8) = make_uint2(t.z, t.w);
        }
    }
    __syncthreads();

    // ---- Q fragments (held for whole kernel) ----
    uint32_t qh[4][4], ql[4][4];
    {
        const int ar = lane & 15;
        const int ak = (lane >> 4) << 3;
#pragma unroll
        for (int ks = 0; ks < 4; ks++) {
            uint32_t off = (uint32_t)((wm + ar) * FSROW + ks * 16 + ak) * 2;
            ldsm_x4(qh[ks], uQh + off);
            ldsm_x4(ql[ks], uQl + off);
        }
    }

    const float NEG = -1e30f;
    const float CSC = 0.125f * 1.4426950408889634f;   // (1/sqrt(64))*log2(e)
    float m0 = NEG, m1 = NEG, l0 = 0.f, l1 = 0.f;
    float ov[8][4];
#pragma unroll
    for (int j = 0; j < 8; j++)
#pragma unroll
        for (int t = 0; t < 4; t++) ov[j][t] = 0.f;

    const int r0g = q0 + wm + (lane >> 2);
    const int r1g = r0g + 8;
    const int br  = lane & 7;
    const int bk  = ((lane >> 3) & 1) << 3;
    const int vr  = lane & 15;

    const __nv_bfloat16* kvsrc[4] = { Kh + base, Kl + base, Vh + base, Vl + base };
    char* kvdst[4] = { sKh, sKl, sVh, sVl };

    const int kend = 2 * qi + 2;
    for (int kt = 0; kt < kend; kt++) {
        __syncthreads();
        // ---- load K,V tiles (bf16 hi/lo, direct copy) ----
#pragma unroll
        for (int it = 0; it < 8; it++) {
            int lin = tid + it * 256;          // 0..2047
            int arr = lin >> 9;                // 0..3 (512 uint4 per array)
            int idx = lin & 511;
            int r   = idx >> 3;
            int c8  = (idx & 7) << 3;
            uint4 t = *(const uint4*)(kvsrc[arr] + (size_t)((kt << 6) + r) * D_MODEL + c8);
            char* d = kvdst[arr] + (r * FSROW + c8) * 2;
            *(uint2*)(d)     = make_uint2(t.x, t.y);
            *(uint2*)(d + 8) = make_uint2(t.z, t.w);
        }
        __syncthreads();

        // ---- S = Q K^T (split bf16: 3 MMAs per step) ----
        float s[8][4];
#pragma unroll
        for (int j = 0; j < 8; j++)
#pragma unroll
            for (int t = 0; t < 4; t++) s[j][t] = 0.f;

#pragma unroll
        for (int j = 0; j < 8; j++) {
#pragma unroll
            for (int ks = 0; ks < 4; ks++) {
                uint32_t kbh[2], kbl[2];
                uint32_t off = (uint32_t)((j * 8 + br) * FSROW + ks * 16 + bk) * 2;
                ldsm_x2(kbh, uKh + off);
                ldsm_x2(kbl, uKl + off);
                mma16816(s[j], qh[ks], kbh);
                mma16816(s[j], qh[ks], kbl);
                mma16816(s[j], ql[ks], kbh);
            }
        }

        // ---- scale + causal mask ----
        const bool diag = (kt >= 2 * qi);
#pragma unroll
        for (int j = 0; j < 8; j++) {
            s[j][0] *= CSC; s[j][1] *= CSC; s[j][2] *= CSC; s[j][3] *= CSC;
            if (diag) {
                int cb = (kt << 6) + j * 8 + ((lane & 3) << 1);
                if (cb     > r0g) s[j][0] = NEG;
                if (cb + 1 > r0g) s[j][1] = NEG;
                if (cb     > r1g) s[j][2] = NEG;
                if (cb + 1 > r1g) s[j][3] = NEG;
            }
        }

        // ---- row max ----
        float rm0 = NEG, rm1 = NEG;
#pragma unroll
        for (int j = 0; j < 8; j++) {
            rm0 = fmaxf(rm0, fmaxf(s[j][0], s[j][1]));
            rm1 = fmaxf(rm1, fmaxf(s[j][2], s[j][3]));
        }
        rm0 = fmaxf(rm0, __shfl_xor_sync(0xffffffffu, rm0, 1));
        rm0 = fmaxf(rm0, __shfl_xor_sync(0xffffffffu, rm0, 2));
        rm1 = fmaxf(rm1, __shfl_xor_sync(0xffffffffu, rm1, 1));
        rm1 = fmaxf(rm1, __shfl_xor_sync(0xffffffffu, rm1, 2));

        float mn0 = fmaxf(m0, rm0);
        float mn1 = fmaxf(m1, rm1);
        float sc0 = fast_exp2(m0 - mn0);
        float sc1 = fast_exp2(m1 - mn1);
        m0 = mn0; m1 = mn1;
#pragma unroll
        for (int j = 0; j < 8; j++) {
            ov[j][0] *= sc0; ov[j][1] *= sc0;
            ov[j][2] *= sc1; ov[j][3] *= sc1;
        }

        // ---- exp, pack P (hi/lo) from accumulator, P·V ----
        float rs0 = 0.f, rs1 = 0.f;
#pragma unroll
        for (int kk = 0; kk < 4; kk++) {
            uint32_t pah[4], pal[4];
#pragma unroll
            for (int u = 0; u < 2; u++) {
                int t = 2 * kk + u;
                float p0 = fast_exp2(s[t][0] - mn0);
                float p1 = fast_exp2(s[t][1] - mn0);
                float p2 = fast_exp2(s[t][2] - mn1);
                float p3 = fast_exp2(s[t][3] - mn1);
                rs0 += p0 + p1;
                rs1 += p2 + p3;
                float e0, e1, e2, e3;
                pah[2 * u]     = pack_bf2_hi(p0, p1, e0, e1);
                pah[2 * u + 1] = pack_bf2_hi(p2, p3, e2, e3);
                pal[2 * u]     = pack_bf2(e0, e1);
                pal[2 * u + 1] = pack_bf2(e2, e3);
            }
            uint32_t Ahf[4] = { pah[0], pah[1], pah[2], pah[3] };
            uint32_t Alf[4] = { pal[0], pal[1], pal[2], pal[3] };
#pragma unroll
            for (int jv = 0; jv < 8; jv++) {
                uint32_t vbh[2], vbl[2];
                uint32_t off = (uint32_t)((kk * 16 + vr) * FSROW + jv * 8) * 2;
                ldsm_x2_t(vbh, uVh + off);
                ldsm_x2_t(vbl, uVl + off);
                mma16816(ov[jv], Ahf, vbh);
                mma16816(ov[jv], Ahf, vbl);
                mma16816(ov[jv], Alf, vbh);
            }
        }
        rs0 += __shfl_xor_sync(0xffffffffu, rs0, 1);
        rs0 += __shfl_xor_sync(0xffffffffu, rs0, 2);
        rs1 += __shfl_xor_sync(0xffffffffu, rs1, 1);
        rs1 += __shfl_xor_sync(0xffffffffu, rs1, 2);
        l0 = l0 * sc0 + rs0;
        l1 = l1 * sc1 + rs1;
    }

    // ---- epilogue: O/l, split to bf16 hi/lo concat layout ----
    float rinv0 = 1.0f / l0;
    float rinv1 = 1.0f / l1;
    size_t orow0 = base + (size_t)(q0 + wm + (lane >> 2)) * D_MODEL;
    size_t orow1 = orow0 + (size_t)8 * D_MODEL;
    int colb = ((lane & 3) << 1);
#pragma unroll
    for (int jv = 0; jv < 8; jv++) {
        float o0 = ov[jv][0] * rinv0;
        float o1 = ov[jv][1] * rinv0;
        float o2 = ov[jv][2] * rinv1;
        float o3 = ov[jv][3] * rinv1;
        float e0, e1, e2, e3;
        uint32_t h01 = pack_bf2_hi(o0, o1, e0, e1);
        uint32_t h23 = pack_bf2_hi(o2, o3, e2, e3);
        int c = jv * 8 + colb;
        *(uint32_t*)(Oh + orow0 + c) = h01;
        *(uint32_t*)(Ol + orow0 + c) = pack_bf2(e0, e1);
        *(uint32_t*)(Oh + orow1 + c) = h23;
        *(uint32_t*)(Ol + orow1 + c) = pack_bf2(e2, e3);
    }
}

// ---------------------------------------------------------------------------
// Launch
// ---------------------------------------------------------------------------
extern "C" void kernel_launch(void* const* d_in, const int* in_sizes, int n_in,
                              void* d_out, int out_size)
{
    const float* x   = (const float*)d_in[0];
    const float* W_q = (const float*)d_in[1];
    const float* W_k = (const float*)d_in[2];
    const float* W_v = (const float*)d_in[3];
    const float* W_o = (const float*)d_in[4];
    float* out = (float*)d_out;

    __nv_bfloat16 *pqh, *pql, *pkh, *pkl, *pvh, *pvl;
    __nv_bfloat16 *pxh, *pxl, *pch, *pcl, *pwh, *pwl;
    cudaGetSymbolAddress((void**)&pqh, g_qh);
    cudaGetSymbolAddress((void**)&pql, g_ql);
    cudaGetSymbolAddress((void**)&pkh, g_kh);
    cudaGetSymbolAddress((void**)&pkl, g_kl);
    cudaGetSymbolAddress((void**)&pvh, g_vh);
    cudaGetSymbolAddress((void**)&pvl, g_vl);
    cudaGetSymbolAddress((void**)&pxh, g_xh);
    cudaGetSymbolAddress((void**)&pxl, g_xl);
    cudaGetSymbolAddress((void**)&pch, g_ch);
    cudaGetSymbolAddress((void**)&pcl, g_cl);
    cudaGetSymbolAddress((void**)&pwh, g_wh);
    cudaGetSymbolAddress((void**)&pwl, g_wl);

    cudaFuncSetAttribute(mma_gemm_kernel,
                         cudaFuncAttributeMaxDynamicSharedMemorySize, SMEM_GEMM);
    cudaFuncSetAttribute(flash_mma_kernel,
                         cudaFuncAttributeMaxDynamicSharedMemorySize, FSMEM);

    const size_t WSZ = (size_t)D_MODEL * D_MODEL;   // 1048576
    const int nx4 = (int)((size_t)M_TOTAL * D_MODEL / 4);
    const int nw4 = (int)(WSZ / 4);

    // split x and weights into bf16 hi/lo
    split_kernel<<<(nx4 + 255) / 256, 256>>>(x, pxh, pxl, nx4);
    split_kernel<<<(nw4 + 255) / 256, 256>>>(W_q, pwh + 0 * WSZ, pwl + 0 * WSZ, nw4);
    split_kernel<<<(nw4 + 255) / 256, 256>>>(W_k, pwh + 1 * WSZ, pwl + 1 * WSZ, nw4);
    split_kernel<<<(nw4 + 255) / 256, 256>>>(W_v, pwh + 2 * WSZ, pwl + 2 * WSZ, nw4);
    split_kernel<<<(nw4 + 255) / 256, 256>>>(W_o, pwh + 3 * WSZ, pwl + 3 * WSZ, nw4);

    dim3 gGemm(D_MODEL / 128, M_TOTAL / 128);   // (8, 64)
    // Q/K/V projections write bf16 hi/lo directly
    mma_gemm_kernel<<<gGemm, 256, SMEM_GEMM>>>(pxh, pxl, pwh + 0 * WSZ, pwl + 0 * WSZ,
                                               nullptr, pqh, pql, M_TOTAL, D_MODEL, D_MODEL);
    mma_gemm_kernel<<<gGemm, 256, SMEM_GEMM>>>(pxh, pxl, pwh + 1 * WSZ, pwl + 1 * WSZ,
                                               nullptr, pkh, pkl, M_TOTAL, D_MODEL, D_MODEL);
    mma_gemm_kernel<<<gGemm, 256, SMEM_GEMM>>>(pxh, pxl, pwh + 2 * WSZ, pwl + 2 * WSZ,
                                               nullptr, pvh, pvl, M_TOTAL, D_MODEL, D_MODEL);

    dim3 gFlash(SEQ / 128, BATCH * N_HEADS);    // (16, 64)
    flash_mma_kernel<<<gFlash, 256, FSMEM>>>(pqh, pql, pkh, pkl, pvh, pvl, pch, pcl);

    // O projection writes fp32 output
    mma_gemm_kernel<<<gGemm, 256, SMEM_GEMM>>>(pch, pcl, pwh + 3 * WSZ, pwl + 3 * WSZ,
                                               out, nullptr, nullptr, M_TOTAL, D_MODEL, D_MODEL);
}

// round 9
// speedup vs baseline: 3.7269x; 1.3319x over previous
#include <cuda_runtime.h>
#include <cuda_fp16.h>
#include <cstdint>
#include <cstddef>

#define D_MODEL  1024
#define N_HEADS  16
#define HEAD_DIM 64
#define BATCH    4
#define SEQ      2048
#define M_TOTAL  (BATCH * SEQ)   // 8192

// ---------------------------------------------------------------------------
// Scratch (no cudaMalloc allowed) — fp16 hi/lo split buffers
// ---------------------------------------------------------------------------
__device__ __half g_xh[(size_t)M_TOTAL * D_MODEL];
__device__ __half g_qh[(size_t)M_TOTAL * D_MODEL];
__device__ __half g_kh[(size_t)M_TOTAL * D_MODEL];
__device__ __half g_kl[(size_t)M_TOTAL * D_MODEL];
__device__ __half g_vh[(size_t)M_TOTAL * D_MODEL];
__device__ __half g_vl[(size_t)M_TOTAL * D_MODEL];
__device__ __half g_ch[(size_t)M_TOTAL * D_MODEL];
__device__ __half g_wh[(size_t)4 * D_MODEL * D_MODEL];
__device__ __half g_wl[(size_t)4 * D_MODEL * D_MODEL];

// ---------------------------------------------------------------------------
// Baseline-PTX helpers (sm_80-class; compile under compute_103)
// ---------------------------------------------------------------------------
__device__ __forceinline__ uint32_t smem_to_u32(const void* p) {
    uint32_t a;
    asm("{ .reg .u64 t; cvta.to.shared.u64 t, %1; cvt.u32.u64 %0, t; }" : "=r"(a) : "l"(p));
    return a;
}
__device__ __forceinline__ void ldsm_x4(uint32_t* r, uint32_t addr) {
    asm volatile("ldmatrix.sync.aligned.m8n8.x4.shared.b16 {%0,%1,%2,%3}, [%4];"
        : "=r"(r[0]), "=r"(r[1]), "=r"(r[2]), "=r"(r[3]) : "r"(addr));
}
__device__ __forceinline__ void ldsm_x2(uint32_t* r, uint32_t addr) {
    asm volatile("ldmatrix.sync.aligned.m8n8.x2.shared.b16 {%0,%1}, [%2];"
        : "=r"(r[0]), "=r"(r[1]) : "r"(addr));
}
__device__ __forceinline__ void ldsm_x2_t(uint32_t* r, uint32_t addr) {
    asm volatile("ldmatrix.sync.aligned.m8n8.x2.trans.shared.b16 {%0,%1}, [%2];"
        : "=r"(r[0]), "=r"(r[1]) : "r"(addr));
}
// D += A(f16) * B(f16), m16n8k16, row.col, f32 accum
__device__ __forceinline__ void mma16816(float* d, const uint32_t* a, const uint32_t* b) {
    asm volatile(
        "mma.sync.aligned.m16n8k16.row.col.f32.f16.f16.f32 "
        "{%0,%1,%2,%3}, {%4,%5,%6,%7}, {%8,%9}, {%0,%1,%2,%3};"
        : "+f"(d[0]), "+f"(d[1]), "+f"(d[2]), "+f"(d[3])
        : "r"(a[0]), "r"(a[1]), "r"(a[2]), "r"(a[3]), "r"(b[0]), "r"(b[1]));
}
__device__ __forceinline__ void cp16(uint32_t smem, const void* g) {
    asm volatile("cp.async.cg.shared.global [%0], [%1], 16;" :: "r"(smem), "l"(g));
}
#define CP_COMMIT() asm volatile("cp.async.commit_group;" ::: "memory")
#define CP_WAIT(n)  asm volatile("cp.async.wait_group %0;" :: "n"(n) : "memory")

__device__ __forceinline__ float fast_exp2(float x) {
    float y;
    asm("ex2.approx.ftz.f32 %0, %1;" : "=f"(y) : "f"(x));
    return y;
}
__device__ __forceinline__ uint32_t pack_hf2(float a, float b) {
    __half2 h = __floats2half2_rn(a, b);
    return reinterpret_cast<uint32_t&>(h);
}
__device__ __forceinline__ uint32_t pack_hf2_hi(float a, float b, float& ra, float& rb) {
    __half2 h = __floats2half2_rn(a, b);
    float2 f = __half22float2(h);
    ra = a - f.x;
    rb = b - f.y;
    return reinterpret_cast<uint32_t&>(h);
}

// ---------------------------------------------------------------------------
// fp32 -> fp16 hi(/lo) splits
// ---------------------------------------------------------------------------
__global__ __launch_bounds__(256)
void split_kernel(const float* __restrict__ x, __half* __restrict__ hi,
                  __half* __restrict__ lo, int n4)
{
    int i = blockIdx.x * 256 + threadIdx.x;
    if (i >= n4) return;
    float4 v = ((const float4*)x)[i];
    float rx, ry, rz, rw;
    uint32_t h0 = pack_hf2_hi(v.x, v.y, rx, ry);
    uint32_t h1 = pack_hf2_hi(v.z, v.w, rz, rw);
    ((uint32_t*)hi)[2 * i]     = h0;
    ((uint32_t*)hi)[2 * i + 1] = h1;
    ((uint32_t*)lo)[2 * i]     = pack_hf2(rx, ry);
    ((uint32_t*)lo)[2 * i + 1] = pack_hf2(rz, rw);
}

__global__ __launch_bounds__(256)
void split_hi_kernel(const float* __restrict__ x, __half* __restrict__ hi, int n4)
{
    int i = blockIdx.x * 256 + threadIdx.x;
    if (i >= n4) return;
    float4 v = ((const float4*)x)[i];
    ((uint32_t*)hi)[2 * i]     = pack_hf2(v.x, v.y);
    ((uint32_t*)hi)[2 * i + 1] = pack_hf2(v.z, v.w);
}

// ---------------------------------------------------------------------------
// mma.sync fp16 2-product GEMM, 2-stage cp.async pipeline.
// C[m][n] = sum_k A[m,k]*B[n,k],  A fp16-hi only, B = Bh + Bl (fp16 pair).
// Epilogue: fp32 C, or fp16 hi (+ optional lo) pair.
// ---------------------------------------------------------------------------
#define BK 64
#define SROW 72                              // padded row, fp16 elements (144B)
#define TILE_B (128 * SROW * 2)              // 18432 bytes per tile
#define STAGE_B (3 * TILE_B)                 // 55296 per stage (Ah, Bh, Bl)
#define SMEM_GEMM (2 * STAGE_B)              // 110592 bytes

__global__ __launch_bounds__(256, 1)
void mma_gemm_kernel(const __half* __restrict__ Ah,
                     const __half* __restrict__ Bh, const __half* __restrict__ Bl,
                     float* __restrict__ C,
                     __half* __restrict__ Chi, __half* __restrict__ Clo,
                     int M, int N, int K)
{
    extern __shared__ char smem[];
    const int tid  = threadIdx.x;
    const int warp = tid >> 5;
    const int lane = tid & 31;
    const int bm = blockIdx.y * 128;
    const int bn = blockIdx.x * 128;
    const int wm = (warp >> 2) * 64;
    const int wn = (warp & 3) * 32;

    const uint32_t sbase = smem_to_u32(smem);

    const int lr  = tid >> 3;                 // 0..31 (row base, +32 per iter)
    const int lc8 = (tid & 7) << 3;           // fp16 col 0..56

    auto issue = [&](int ch, int s) {
        const int k0g = ch * BK;
        const uint32_t st = sbase + s * STAGE_B;
#pragma unroll
        for (int it = 0; it < 4; it++) {
            int r = lr + it * 32;
            uint32_t so = (uint32_t)(r * SROW + lc8) * 2;
            size_t ga = (size_t)(bm + r) * K + k0g + lc8;
            size_t gb = (size_t)(bn + r) * K + k0g + lc8;
            cp16(st + 0 * TILE_B + so, Ah + ga);
            cp16(st + 1 * TILE_B + so, Bh + gb);
            cp16(st + 2 * TILE_B + so, Bl + gb);
        }
        CP_COMMIT();
    };

    const int a_row  = lane & 15;
    const int a_koff = (lane >> 4) << 3;
    const int b_row  = lane & 7;
    const int b_koff = ((lane >> 3) & 1) << 3;

    float acc[4][4][4];
#pragma unroll
    for (int i = 0; i < 4; i++)
#pragma unroll
        for (int j = 0; j < 4; j++)
#pragma unroll
            for (int t = 0; t < 4; t++) acc[i][j][t] = 0.f;

    const int nchunks = K / BK;
    issue(0, 0);

    for (int ch = 0; ch < nchunks; ch++) {
        const int s = ch & 1;
        if (ch + 1 < nchunks) {
            issue(ch + 1, 1 - s);
            CP_WAIT(1);
        } else {
            CP_WAIT(0);
        }
        __syncthreads();

        const uint32_t uAh = sbase + s * STAGE_B;
        const uint32_t uBh = uAh + TILE_B;
        const uint32_t uBl = uAh + 2 * TILE_B;

#pragma unroll
        for (int ks = 0; ks < 4; ks++) {
            const int k0 = ks * 16;
            uint32_t ah[4][4], bh[4][2], bl[4][2];
#pragma unroll
            for (int i = 0; i < 4; i++) {
                uint32_t off = (uint32_t)((wm + i * 16 + a_row) * SROW + k0 + a_koff) * 2;
                ldsm_x4(ah[i], uAh + off);
            }
#pragma unroll
            for (int j = 0; j < 4; j++) {
                uint32_t off = (uint32_t)((wn + j * 8 + b_row) * SROW + k0 + b_koff) * 2;
                ldsm_x2(bh[j], uBh + off);
                ldsm_x2(bl[j], uBl + off);
            }
#pragma unroll
            for (int i = 0; i < 4; i++)
#pragma unroll
                for (int j = 0; j < 4; j++) {
                    mma16816(acc[i][j], ah[i], bh[j]);
                    mma16816(acc[i][j], ah[i], bl[j]);
                }
        }
        __syncthreads();
    }

    const int gr = lane >> 2;
    const int gc = (lane & 3) << 1;
    if (C) {
#pragma unroll
        for (int i = 0; i < 4; i++) {
#pragma unroll
            for (int j = 0; j < 4; j++) {
                size_t r0 = (size_t)(bm + wm + i * 16 + gr) * N + bn + wn + j * 8 + gc;
                size_t r1 = r0 + (size_t)8 * N;
                *(float2*)(C + r0) = make_float2(acc[i][j][0], acc[i][j][1]);
                *(float2*)(C + r1) = make_float2(acc[i][j][2], acc[i][j][3]);
            }
        }
    } else if (Clo) {
#pragma unroll
        for (int i = 0; i < 4; i++) {
#pragma unroll
            for (int j = 0; j < 4; j++) {
                size_t r0 = (size_t)(bm + wm + i * 16 + gr) * N + bn + wn + j * 8 + gc;
                size_t r1 = r0 + (size_t)8 * N;
                float e0, e1, e2, e3;
                uint32_t h01 = pack_hf2_hi(acc[i][j][0], acc[i][j][1], e0, e1);
                uint32_t h23 = pack_hf2_hi(acc[i][j][2], acc[i][j][3], e2, e3);
                *(uint32_t*)(Chi + r0) = h01;
                *(uint32_t*)(Clo + r0) = pack_hf2(e0, e1);
                *(uint32_t*)(Chi + r1) = h23;
                *(uint32_t*)(Clo + r1) = pack_hf2(e2, e3);
            }
        }
    } else {
#pragma unroll
        for (int i = 0; i < 4; i++) {
#pragma unroll
            for (int j = 0; j < 4; j++) {
                size_t r0 = (size_t)(bm + wm + i * 16 + gr) * N + bn + wn + j * 8 + gc;
                size_t r1 = r0 + (size_t)8 * N;
                *(uint32_t*)(Chi + r0) = pack_hf2(acc[i][j][0], acc[i][j][1]);
                *(uint32_t*)(Chi + r1) = pack_hf2(acc[i][j][2], acc[i][j][3]);
            }
        }
    }
}

// ---------------------------------------------------------------------------
// Tensor-core causal flash attention (fp16 2-product via mma.sync).
// Q fp16-hi only; K,V fp16 hi/lo. Output concat fp16-hi only.
// CTA: 256 thr (8 warps), Q tile 128 rows, KV tile 64. Warp owns 16 rows.
// ---------------------------------------------------------------------------
#define FSROW 72
#define FSMEM ((128 + 4 * 64) * FSROW * 2)   // 55296 bytes

__global__ __launch_bounds__(256, 1)
void flash_mma_kernel(const __half* __restrict__ Qh,
                      const __half* __restrict__ Kh, const __half* __restrict__ Kl,
                      const __half* __restrict__ Vh, const __half* __restrict__ Vl,
                      __half* __restrict__ Oh)
{
    extern __shared__ char fsm[];
    char* sQh = fsm;                                   // [128][FSROW] fp16
    char* sKh = sQh + 128 * FSROW * 2;                 // [64][FSROW]
    char* sKl = sKh + 64 * FSROW * 2;
    char* sVh = sKl + 64 * FSROW * 2;
    char* sVl = sVh + 64 * FSROW * 2;
    const uint32_t uQh = smem_to_u32(sQh);
    const uint32_t uKh = smem_to_u32(sKh);
    const uint32_t uKl = smem_to_u32(sKl);
    const uint32_t uVh = smem_to_u32(sVh);
    const uint32_t uVl = smem_to_u32(sVl);

    const int tid  = threadIdx.x;
    const int warp = tid >> 5;
    const int lane = tid & 31;
    const int qi = blockIdx.x;                 // 0..15
    const int bh = blockIdx.y;                 // b*16+h
    const int b = bh >> 4, h = bh & 15;
    const int q0 = qi << 7;
    const int wm = warp << 4;

    const size_t base = (size_t)b * SEQ * D_MODEL + (size_t)h * HEAD_DIM;

    // ---- load Q tile (fp16 hi, direct copy) ----
#pragma unroll
    for (int it = 0; it < 4; it++) {
        int lin = tid + it * 256;              // 0..1023
        int r   = lin >> 3;
        int c8  = (lin & 7) << 3;
        uint4 t = *(const uint4*)(Qh + base + (size_t)(q0 + r) * D_MODEL + c8);
        char* d = sQh + (r * FSROW + c8) * 2;
        *(uint2*)(d)     = make_uint2(t.x, t.y);
        *(uint2*)(d + 8) = make_uint2(t.z, t.w);
    }
    __syncthreads();

    // ---- Q fragments (held for whole kernel) ----
    uint32_t qh[4][4];
    {
        const int ar = lane & 15;
        const int ak = (lane >> 4) << 3;
#pragma unroll
        for (int ks = 0; ks < 4; ks++) {
            uint32_t off = (uint32_t)((wm + ar) * FSROW + ks * 16 + ak) * 2;
            ldsm_x4(qh[ks], uQh + off);
        }
    }

    const float NEG = -1e30f;
    const float CSC = 0.125f * 1.4426950408889634f;   // (1/sqrt(64))*log2(e)
    float m0 = NEG, m1 = NEG, l0 = 0.f, l1 = 0.f;
    float ov[8][4];
#pragma unroll
    for (int j = 0; j < 8; j++)
#pragma unroll
        for (int t = 0; t < 4; t++) ov[j][t] = 0.f;

    const int r0g = q0 + wm + (lane >> 2);
    const int r1g = r0g + 8;
    const int br  = lane & 7;
    const int bk  = ((lane >> 3) & 1) << 3;
    const int vr  = lane & 15;

    const __half* kvsrc[4] = { Kh + base, Kl + base, Vh + base, Vl + base };
    char* kvdst[4] = { sKh, sKl, sVh, sVl };

    const int kend = 2 * qi + 2;
    for (int kt = 0; kt < kend; kt++) {
        __syncthreads();
        // ---- load K,V tiles (fp16 hi/lo, direct copy) ----
#pragma unroll
        for (int it = 0; it < 8; it++) {
            int lin = tid + it * 256;          // 0..2047
            int arr = lin >> 9;                // 0..3 (512 uint4 per array)
            int idx = lin & 511;
            int r   = idx >> 3;
            int c8  = (idx & 7) << 3;
            uint4 t = *(const uint4*)(kvsrc[arr] + (size_t)((kt << 6) + r) * D_MODEL + c8);
            char* d = kvdst[arr] + (r * FSROW + c8) * 2;
            *(uint2*)(d)     = make_uint2(t.x, t.y);
            *(uint2*)(d + 8) = make_uint2(t.z, t.w);
        }
        __syncthreads();

        // ---- S = Q K^T (2 MMAs per step) ----
        float s[8][4];
#pragma unroll
        for (int j = 0; j < 8; j++)
#pragma unroll
            for (int t = 0; t < 4; t++) s[j][t] = 0.f;

#pragma unroll
        for (int j = 0; j < 8; j++) {
#pragma unroll
            for (int ks = 0; ks < 4; ks++) {
                uint32_t kbh[2], kbl[2];
                uint32_t off = (uint32_t)((j * 8 + br) * FSROW + ks * 16 + bk) * 2;
                ldsm_x2(kbh, uKh + off);
                ldsm_x2(kbl, uKl + off);
                mma16816(s[j], qh[ks], kbh);
                mma16816(s[j], qh[ks], kbl);
            }
        }

        // ---- scale + causal mask ----
        const bool diag = (kt >= 2 * qi);
#pragma unroll
        for (int j = 0; j < 8; j++) {
            s[j][0] *= CSC; s[j][1] *= CSC; s[j][2] *= CSC; s[j][3] *= CSC;
            if (diag) {
                int cb = (kt << 6) + j * 8 + ((lane & 3) << 1);
                if (cb     > r0g) s[j][0] = NEG;
                if (cb + 1 > r0g) s[j][1] = NEG;
                if (cb     > r1g) s[j][2] = NEG;
                if (cb + 1 > r1g) s[j][3] = NEG;
            }
        }

        // ---- row max ----
        float rm0 = NEG, rm1 = NEG;
#pragma unroll
        for (int j = 0; j < 8; j++) {
            rm0 = fmaxf(rm0, fmaxf(s[j][0], s[j][1]));
            rm1 = fmaxf(rm1, fmaxf(s[j][2], s[j][3]));
        }
        rm0 = fmaxf(rm0, __shfl_xor_sync(0xffffffffu, rm0, 1));
        rm0 = fmaxf(rm0, __shfl_xor_sync(0xffffffffu, rm0, 2));
        rm1 = fmaxf(rm1, __shfl_xor_sync(0xffffffffu, rm1, 1));
        rm1 = fmaxf(rm1, __shfl_xor_sync(0xffffffffu, rm1, 2));

        float mn0 = fmaxf(m0, rm0);
        float mn1 = fmaxf(m1, rm1);
        float sc0 = fast_exp2(m0 - mn0);
        float sc1 = fast_exp2(m1 - mn1);
        m0 = mn0; m1 = mn1;
#pragma unroll
        for (int j = 0; j < 8; j++) {
            ov[j][0] *= sc0; ov[j][1] *= sc0;
            ov[j][2] *= sc1; ov[j][3] *= sc1;
        }

        // ---- exp, pack P (fp16 hi) from accumulator, P·V ----
        float rs0 = 0.f, rs1 = 0.f;
#pragma unroll
        for (int kk = 0; kk < 4; kk++) {
            uint32_t pah[4];
#pragma unroll
            for (int u = 0; u < 2; u++) {
                int t = 2 * kk + u;
                float p0 = fast_exp2(s[t][0] - mn0);
                float p1 = fast_exp2(s[t][1] - mn0);
                float p2 = fast_exp2(s[t][2] - mn1);
                float p3 = fast_exp2(s[t][3] - mn1);
                rs0 += p0 + p1;
                rs1 += p2 + p3;
                pah[2 * u]     = pack_hf2(p0, p1);
                pah[2 * u + 1] = pack_hf2(p2, p3);
            }
#pragma unroll
            for (int jv = 0; jv < 8; jv++) {
                uint32_t vbh[2], vbl[2];
                uint32_t off = (uint32_t)((kk * 16 + vr) * FSROW + jv * 8) * 2;
                ldsm_x2_t(vbh, uVh + off);
                ldsm_x2_t(vbl, uVl + off);
                mma16816(ov[jv], pah, vbh);
                mma16816(ov[jv], pah, vbl);
            }
        }
        rs0 += __shfl_xor_sync(0xffffffffu, rs0, 1);
        rs0 += __shfl_xor_sync(0xffffffffu, rs0, 2);
        rs1 += __shfl_xor_sync(0xffffffffu, rs1, 1);
        rs1 += __shfl_xor_sync(0xffffffffu, rs1, 2);
        l0 = l0 * sc0 + rs0;
        l1 = l1 * sc1 + rs1;
    }

    // ---- epilogue: O/l, fp16 hi concat layout ----
    float rinv0 = 1.0f / l0;
    float rinv1 = 1.0f / l1;
    size_t orow0 = base + (size_t)(q0 + wm + (lane >> 2)) * D_MODEL;
    size_t orow1 = orow0 + (size_t)8 * D_MODEL;
    int colb = ((lane & 3) << 1);
#pragma unroll
    for (int jv = 0; jv < 8; jv++) {
        int c = jv * 8 + colb;
        *(uint32_t*)(Oh + orow0 + c) = pack_hf2(ov[jv][0] * rinv0, ov[jv][1] * rinv0);
        *(uint32_t*)(Oh + orow1 + c) = pack_hf2(ov[jv][2] * rinv1, ov[jv][3] * rinv1);
    }
}

// ---------------------------------------------------------------------------
// Launch
// ---------------------------------------------------------------------------
extern "C" void kernel_launch(void* const* d_in, const int* in_sizes, int n_in,
                              void* d_out, int out_size)
{
    const float* x   = (const float*)d_in[0];
    const float* W_q = (const float*)d_in[1];
    const float* W_k = (const float*)d_in[2];
    const float* W_v = (const float*)d_in[3];
    const float* W_o = (const float*)d_in[4];
    float* out = (float*)d_out;

    __half *pxh, *pqh, *pkh, *pkl, *pvh, *pvl, *pch, *pwh, *pwl;
    cudaGetSymbolAddress((void**)&pxh, g_xh);
    cudaGetSymbolAddress((void**)&pqh, g_qh);
    cudaGetSymbolAddress((void**)&pkh, g_kh);
    cudaGetSymbolAddress((void**)&pkl, g_kl);
    cudaGetSymbolAddress((void**)&pvh, g_vh);
    cudaGetSymbolAddress((void**)&pvl, g_vl);
    cudaGetSymbolAddress((void**)&pch, g_ch);
    cudaGetSymbolAddress((void**)&pwh, g_wh);
    cudaGetSymbolAddress((void**)&pwl, g_wl);

    cudaFuncSetAttribute(mma_gemm_kernel,
                         cudaFuncAttributeMaxDynamicSharedMemorySize, SMEM_GEMM);
    cudaFuncSetAttribute(flash_mma_kernel,
                         cudaFuncAttributeMaxDynamicSharedMemorySize, FSMEM);

    const size_t WSZ = (size_t)D_MODEL * D_MODEL;   // 1048576
    const int nx4 = (int)((size_t)M_TOTAL * D_MODEL / 4);
    const int nw4 = (int)(WSZ / 4);

    // x: hi only; weights: hi/lo
    split_hi_kernel<<<(nx4 + 255) / 256, 256>>>(x, pxh, nx4);
    split_kernel<<<(nw4 + 255) / 256, 256>>>(W_q, pwh + 0 * WSZ, pwl + 0 * WSZ, nw4);
    split_kernel<<<(nw4 + 255) / 256, 256>>>(W_k, pwh + 1 * WSZ, pwl + 1 * WSZ, nw4);
    split_kernel<<<(nw4 + 255) / 256, 256>>>(W_v, pwh + 2 * WSZ, pwl + 2 * WSZ, nw4);
    split_kernel<<<(nw4 + 255) / 256, 256>>>(W_o, pwh + 3 * WSZ, pwl + 3 * WSZ, nw4);

    dim3 gGemm(D_MODEL / 128, M_TOTAL / 128);   // (8, 64)
    // Q: hi only (used as MMA A operand downstream). K, V: hi+lo (B operands).
    mma_gemm_kernel<<<gGemm, 256, SMEM_GEMM>>>(pxh, pwh + 0 * WSZ, pwl + 0 * WSZ,
                                               nullptr, pqh, nullptr, M_TOTAL, D_MODEL, D_MODEL);
    mma_gemm_kernel<<<gGemm, 256, SMEM_GEMM>>>(pxh, pwh + 1 * WSZ, pwl + 1 * WSZ,
                                               nullptr, pkh, pkl, M_TOTAL, D_MODEL, D_MODEL);
    mma_gemm_kernel<<<gGemm, 256, SMEM_GEMM>>>(pxh, pwh + 2 * WSZ, pwl + 2 * WSZ,
                                               nullptr, pvh, pvl, M_TOTAL, D_MODEL, D_MODEL);

    dim3 gFlash(SEQ / 128, BATCH * N_HEADS);    // (16, 64)
    flash_mma_kernel<<<gFlash, 256, FSMEM>>>(pqh, pkh, pkl, pvh, pvl, pch);

    // O projection: fp32 output
    mma_gemm_kernel<<<gGemm, 256, SMEM_GEMM>>>(pch, pwh + 3 * WSZ, pwl + 3 * WSZ,
                                               out, nullptr, nullptr, M_TOTAL, D_MODEL, D_MODEL);
}

// round 10
// speedup vs baseline: 4.3176x; 1.1585x over previous
#include <cuda_runtime.h>
#include <cuda_fp16.h>
#include <cstdint>
#include <cstddef>

#define D_MODEL  1024
#define N_HEADS  16
#define HEAD_DIM 64
#define BATCH    4
#define SEQ      2048
#define M_TOTAL  (BATCH * SEQ)   // 8192

// ---------------------------------------------------------------------------
// Scratch (no cudaMalloc allowed) — fp16 hi/lo split buffers
// ---------------------------------------------------------------------------
__device__ __half g_xh[(size_t)M_TOTAL * D_MODEL];
__device__ __half g_qh[(size_t)M_TOTAL * D_MODEL];
__device__ __half g_kh[(size_t)M_TOTAL * D_MODEL];
__device__ __half g_kl[(size_t)M_TOTAL * D_MODEL];
__device__ __half g_vh[(size_t)M_TOTAL * D_MODEL];
__device__ __half g_vl[(size_t)M_TOTAL * D_MODEL];
__device__ __half g_ch[(size_t)M_TOTAL * D_MODEL];
__device__ __half g_wh[(size_t)4 * D_MODEL * D_MODEL];
__device__ __half g_wl[(size_t)4 * D_MODEL * D_MODEL];

// ---------------------------------------------------------------------------
// Baseline-PTX helpers (sm_80-class; compile under compute_103)
// ---------------------------------------------------------------------------
__device__ __forceinline__ uint32_t smem_to_u32(const void* p) {
    uint32_t a;
    asm("{ .reg .u64 t; cvta.to.shared.u64 t, %1; cvt.u32.u64 %0, t; }" : "=r"(a) : "l"(p));
    return a;
}
__device__ __forceinline__ void ldsm_x4(uint32_t* r, uint32_t addr) {
    asm volatile("ldmatrix.sync.aligned.m8n8.x4.shared.b16 {%0,%1,%2,%3}, [%4];"
        : "=r"(r[0]), "=r"(r[1]), "=r"(r[2]), "=r"(r[3]) : "r"(addr));
}
__device__ __forceinline__ void ldsm_x2(uint32_t* r, uint32_t addr) {
    asm volatile("ldmatrix.sync.aligned.m8n8.x2.shared.b16 {%0,%1}, [%2];"
        : "=r"(r[0]), "=r"(r[1]) : "r"(addr));
}
__device__ __forceinline__ void ldsm_x2_t(uint32_t* r, uint32_t addr) {
    asm volatile("ldmatrix.sync.aligned.m8n8.x2.trans.shared.b16 {%0,%1}, [%2];"
        : "=r"(r[0]), "=r"(r[1]) : "r"(addr));
}
// D += A(f16) * B(f16), m16n8k16, row.col, f32 accum
__device__ __forceinline__ void mma16816(float* d, const uint32_t* a, const uint32_t* b) {
    asm volatile(
        "mma.sync.aligned.m16n8k16.row.col.f32.f16.f16.f32 "
        "{%0,%1,%2,%3}, {%4,%5,%6,%7}, {%8,%9}, {%0,%1,%2,%3};"
        : "+f"(d[0]), "+f"(d[1]), "+f"(d[2]), "+f"(d[3])
        : "r"(a[0]), "r"(a[1]), "r"(a[2]), "r"(a[3]), "r"(b[0]), "r"(b[1]));
}
__device__ __forceinline__ void cp16(uint32_t smem, const void* g) {
    asm volatile("cp.async.cg.shared.global [%0], [%1], 16;" :: "r"(smem), "l"(g));
}
#define CP_COMMIT() asm volatile("cp.async.commit_group;" ::: "memory")
#define CP_WAIT(n)  asm volatile("cp.async.wait_group %0;" :: "n"(n) : "memory")

__device__ __forceinline__ float fast_exp2(float x) {
    float y;
    asm("ex2.approx.ftz.f32 %0, %1;" : "=f"(y) : "f"(x));
    return y;
}
__device__ __forceinline__ uint32_t pack_hf2(float a, float b) {
    __half2 h = __floats2half2_rn(a, b);
    return reinterpret_cast<uint32_t&>(h);
}
__device__ __forceinline__ uint32_t pack_hf2_hi(float a, float b, float& ra, float& rb) {
    __half2 h = __floats2half2_rn(a, b);
    float2 f = __half22float2(h);
    ra = a - f.x;
    rb = b - f.y;
    return reinterpret_cast<uint32_t&>(h);
}

// ---------------------------------------------------------------------------
// fp32 -> fp16 hi(/lo) splits
// ---------------------------------------------------------------------------
__global__ __launch_bounds__(256)
void split_kernel(const float* __restrict__ x, __half* __restrict__ hi,
                  __half* __restrict__ lo, int n4)
{
    int i = blockIdx.x * 256 + threadIdx.x;
    if (i >= n4) return;
    float4 v = ((const float4*)x)[i];
    float rx, ry, rz, rw;
    uint32_t h0 = pack_hf2_hi(v.x, v.y, rx, ry);
    uint32_t h1 = pack_hf2_hi(v.z, v.w, rz, rw);
    ((uint32_t*)hi)[2 * i]     = h0;
    ((uint32_t*)hi)[2 * i + 1] = h1;
    ((uint32_t*)lo)[2 * i]     = pack_hf2(rx, ry);
    ((uint32_t*)lo)[2 * i + 1] = pack_hf2(rz, rw);
}

__global__ __launch_bounds__(256)
void split_hi_kernel(const float* __restrict__ x, __half* __restrict__ hi, int n4)
{
    int i = blockIdx.x * 256 + threadIdx.x;
    if (i >= n4) return;
    float4 v = ((const float4*)x)[i];
    ((uint32_t*)hi)[2 * i]     = pack_hf2(v.x, v.y);
    ((uint32_t*)hi)[2 * i + 1] = pack_hf2(v.z, v.w);
}

// ---------------------------------------------------------------------------
// mma.sync fp16 2-product GEMM, 2-stage cp.async pipeline, 2 CTAs/SM.
// C[m][n] = sum_k A[m,k]*B[n,k],  A fp16-hi only, B = Bh + Bl (fp16 pair).
// ---------------------------------------------------------------------------
#define BK 64
#define SROW 72                              // padded row, fp16 elements (144B)
#define TILE_B (128 * SROW * 2)              // 18432 bytes per tile
#define STAGE_B (3 * TILE_B)                 // 55296 per stage (Ah, Bh, Bl)
#define SMEM_GEMM (2 * STAGE_B)              // 110592 bytes

__global__ __launch_bounds__(256, 2)
void mma_gemm_kernel(const __half* __restrict__ Ah,
                     const __half* __restrict__ Bh, const __half* __restrict__ Bl,
                     float* __restrict__ C,
                     __half* __restrict__ Chi, __half* __restrict__ Clo,
                     int M, int N, int K)
{
    extern __shared__ char smem[];
    const int tid  = threadIdx.x;
    const int warp = tid >> 5;
    const int lane = tid & 31;
    const int bm = blockIdx.y * 128;
    const int bn = blockIdx.x * 128;
    const int wm = (warp >> 2) * 64;
    const int wn = (warp & 3) * 32;

    const uint32_t sbase = smem_to_u32(smem);

    const int lr  = tid >> 3;                 // 0..31 (row base, +32 per iter)
    const int lc8 = (tid & 7) << 3;           // fp16 col 0..56

    auto issue = [&](int ch, int s) {
        const int k0g = ch * BK;
        const uint32_t st = sbase + s * STAGE_B;
#pragma unroll
        for (int it = 0; it < 4; it++) {
            int r = lr + it * 32;
            uint32_t so = (uint32_t)(r * SROW + lc8) * 2;
            size_t ga = (size_t)(bm + r) * K + k0g + lc8;
            size_t gb = (size_t)(bn + r) * K + k0g + lc8;
            cp16(st + 0 * TILE_B + so, Ah + ga);
            cp16(st + 1 * TILE_B + so, Bh + gb);
            cp16(st + 2 * TILE_B + so, Bl + gb);
        }
        CP_COMMIT();
    };

    const int a_row  = lane & 15;
    const int a_koff = (lane >> 4) << 3;
    const int b_row  = lane & 7;
    const int b_koff = ((lane >> 3) & 1) << 3;

    float acc[4][4][4];
#pragma unroll
    for (int i = 0; i < 4; i++)
#pragma unroll
        for (int j = 0; j < 4; j++)
#pragma unroll
            for (int t = 0; t < 4; t++) acc[i][j][t] = 0.f;

    const int nchunks = K / BK;
    issue(0, 0);

    for (int ch = 0; ch < nchunks; ch++) {
        const int s = ch & 1;
        if (ch + 1 < nchunks) {
            issue(ch + 1, 1 - s);
            CP_WAIT(1);
        } else {
            CP_WAIT(0);
        }
        __syncthreads();

        const uint32_t uAh = sbase + s * STAGE_B;
        const uint32_t uBh = uAh + TILE_B;
        const uint32_t uBl = uAh + 2 * TILE_B;

#pragma unroll
        for (int ks = 0; ks < 4; ks++) {
            const int k0 = ks * 16;
            uint32_t ah[4][4], bh[4][2], bl[4][2];
#pragma unroll
            for (int i = 0; i < 4; i++) {
                uint32_t off = (uint32_t)((wm + i * 16 + a_row) * SROW + k0 + a_koff) * 2;
                ldsm_x4(ah[i], uAh + off);
            }
#pragma unroll
            for (int j = 0; j < 4; j++) {
                uint32_t off = (uint32_t)((wn + j * 8 + b_row) * SROW + k0 + b_koff) * 2;
                ldsm_x2(bh[j], uBh + off);
                ldsm_x2(bl[j], uBl + off);
            }
#pragma unroll
            for (int i = 0; i < 4; i++)
#pragma unroll
                for (int j = 0; j < 4; j++) {
                    mma16816(acc[i][j], ah[i], bh[j]);
                    mma16816(acc[i][j], ah[i], bl[j]);
                }
        }
        __syncthreads();
    }

    const int gr = lane >> 2;
    const int gc = (lane & 3) << 1;
    if (C) {
#pragma unroll
        for (int i = 0; i < 4; i++) {
#pragma unroll
            for (int j = 0; j < 4; j++) {
                size_t r0 = (size_t)(bm + wm + i * 16 + gr) * N + bn + wn + j * 8 + gc;
                size_t r1 = r0 + (size_t)8 * N;
                *(float2*)(C + r0) = make_float2(acc[i][j][0], acc[i][j][1]);
                *(float2*)(C + r1) = make_float2(acc[i][j][2], acc[i][j][3]);
            }
        }
    } else if (Clo) {
#pragma unroll
        for (int i = 0; i < 4; i++) {
#pragma unroll
            for (int j = 0; j < 4; j++) {
                size_t r0 = (size_t)(bm + wm + i * 16 + gr) * N + bn + wn + j * 8 + gc;
                size_t r1 = r0 + (size_t)8 * N;
                float e0, e1, e2, e3;
                uint32_t h01 = pack_hf2_hi(acc[i][j][0], acc[i][j][1], e0, e1);
                uint32_t h23 = pack_hf2_hi(acc[i][j][2], acc[i][j][3], e2, e3);
                *(uint32_t*)(Chi + r0) = h01;
                *(uint32_t*)(Clo + r0) = pack_hf2(e0, e1);
                *(uint32_t*)(Chi + r1) = h23;
                *(uint32_t*)(Clo + r1) = pack_hf2(e2, e3);
            }
        }
    } else {
#pragma unroll
        for (int i = 0; i < 4; i++) {
#pragma unroll
            for (int j = 0; j < 4; j++) {
                size_t r0 = (size_t)(bm + wm + i * 16 + gr) * N + bn + wn + j * 8 + gc;
                size_t r1 = r0 + (size_t)8 * N;
                *(uint32_t*)(Chi + r0) = pack_hf2(acc[i][j][0], acc[i][j][1]);
                *(uint32_t*)(Chi + r1) = pack_hf2(acc[i][j][2], acc[i][j][3]);
            }
        }
    }
}

// ---------------------------------------------------------------------------
// Tensor-core causal flash attention (fp16 2-product via mma.sync),
// 2-stage cp.async K/V pipeline, 2 CTAs/SM.
// Q fp16-hi only; K,V fp16 hi/lo. Output concat fp16-hi only.
// ---------------------------------------------------------------------------
#define FSROW 72
#define KVARR_B (64 * FSROW * 2)                 // 9216 bytes per array
#define KVSTAGE_B (4 * KVARR_B)                  // 36864 per stage
#define FSMEM (128 * FSROW * 2 + 2 * KVSTAGE_B)  // 92160 bytes

__global__ __launch_bounds__(256, 2)
void flash_mma_kernel(const __half* __restrict__ Qh,
                      const __half* __restrict__ Kh, const __half* __restrict__ Kl,
                      const __half* __restrict__ Vh, const __half* __restrict__ Vl,
                      __half* __restrict__ Oh)
{
    extern __shared__ char fsm[];
    char* sQh = fsm;                                   // [128][FSROW] fp16
    const uint32_t uQh = smem_to_u32(sQh);
    const uint32_t uKV = uQh + 128 * FSROW * 2;        // 2 stages of K/V hi/lo

    const int tid  = threadIdx.x;
    const int warp = tid >> 5;
    const int lane = tid & 31;
    const int qi = blockIdx.x;                 // 0..15
    const int bh = blockIdx.y;                 // b*16+h
    const int b = bh >> 4, h = bh & 15;
    const int q0 = qi << 7;
    const int wm = warp << 4;

    const size_t base = (size_t)b * SEQ * D_MODEL + (size_t)h * HEAD_DIM;
    const __half* kvsrc[4] = { Kh + base, Kl + base, Vh + base, Vl + base };

    // cp.async issue of one K/V tile set into stage s
    auto issueKV = [&](int kt, int s) {
        const uint32_t st = uKV + s * KVSTAGE_B;
#pragma unroll
        for (int it = 0; it < 8; it++) {
            int lin = tid + it * 256;          // 0..2047
            int arr = lin >> 9;                // 0..3
            int idx = lin & 511;
            int r   = idx >> 3;
            int c8  = (idx & 7) << 3;
            cp16(st + arr * KVARR_B + (uint32_t)(r * FSROW + c8) * 2,
                 kvsrc[arr] + (size_t)((kt << 6) + r) * D_MODEL + c8);
        }
        CP_COMMIT();
    };

    // ---- load Q tile (fp16 hi, direct copy) + prefetch KV tile 0 ----
#pragma unroll
    for (int it = 0; it < 4; it++) {
        int lin = tid + it * 256;              // 0..1023
        int r   = lin >> 3;
        int c8  = (lin & 7) << 3;
        uint4 t = *(const uint4*)(Qh + base + (size_t)(q0 + r) * D_MODEL + c8);
        char* d = sQh + (r * FSROW + c8) * 2;
        *(uint2*)(d)     = make_uint2(t.x, t.y);
        *(uint2*)(d + 8) = make_uint2(t.z, t.w);
    }
    issueKV(0, 0);
    __syncthreads();

    // ---- Q fragments (held for whole kernel) ----
    uint32_t qh[4][4];
    {
        const int ar = lane & 15;
        const int ak = (lane >> 4) << 3;
#pragma unroll
        for (int ks = 0; ks < 4; ks++) {
            uint32_t off = (uint32_t)((wm + ar) * FSROW + ks * 16 + ak) * 2;
            ldsm_x4(qh[ks], uQh + off);
        }
    }

    const float NEG = -1e30f;
    const float CSC = 0.125f * 1.4426950408889634f;   // (1/sqrt(64))*log2(e)
    float m0 = NEG, m1 = NEG, l0 = 0.f, l1 = 0.f;
    float ov[8][4];
#pragma unroll
    for (int j = 0; j < 8; j++)
#pragma unroll
        for (int t = 0; t < 4; t++) ov[j][t] = 0.f;

    const int r0g = q0 + wm + (lane >> 2);
    const int r1g = r0g + 8;
    const int br  = lane & 7;
    const int bk  = ((lane >> 3) & 1) << 3;
    const int vr  = lane & 15;

    const int kend = 2 * qi + 2;
    for (int kt = 0; kt < kend; kt++) {
        const int s = kt & 1;
        if (kt + 1 < kend) {
            issueKV(kt + 1, 1 - s);            // prefetch next tile (prev stage free: barrier below covers)
            CP_WAIT(1);
        } else {
            CP_WAIT(0);
        }
        __syncthreads();                       // stage s visible to all warps

        const uint32_t uKh = uKV + s * KVSTAGE_B;
        const uint32_t uKl = uKh + KVARR_B;
        const uint32_t uVh = uKh + 2 * KVARR_B;
        const uint32_t uVl = uKh + 3 * KVARR_B;

        // ---- S = Q K^T (2 MMAs per step) ----
        float sreg[8][4];
#pragma unroll
        for (int j = 0; j < 8; j++)
#pragma unroll
            for (int t = 0; t < 4; t++) sreg[j][t] = 0.f;

#pragma unroll
        for (int j = 0; j < 8; j++) {
#pragma unroll
            for (int ks = 0; ks < 4; ks++) {
                uint32_t kbh[2], kbl[2];
                uint32_t off = (uint32_t)((j * 8 + br) * FSROW + ks * 16 + bk) * 2;
                ldsm_x2(kbh, uKh + off);
                ldsm_x2(kbl, uKl + off);
                mma16816(sreg[j], qh[ks], kbh);
                mma16816(sreg[j], qh[ks], kbl);
            }
        }

        // ---- scale + causal mask ----
        const bool diag = (kt >= 2 * qi);
#pragma unroll
        for (int j = 0; j < 8; j++) {
            sreg[j][0] *= CSC; sreg[j][1] *= CSC; sreg[j][2] *= CSC; sreg[j][3] *= CSC;
            if (diag) {
                int cb = (kt << 6) + j * 8 + ((lane & 3) << 1);
                if (cb     > r0g) sreg[j][0] = NEG;
                if (cb + 1 > r0g) sreg[j][1] = NEG;
                if (cb     > r1g) sreg[j][2] = NEG;
                if (cb + 1 > r1g) sreg[j][3] = NEG;
            }
        }

        // ---- row max ----
        float rm0 = NEG, rm1 = NEG;
#pragma unroll
        for (int j = 0; j < 8; j++) {
            rm0 = fmaxf(rm0, fmaxf(sreg[j][0], sreg[j][1]));
            rm1 = fmaxf(rm1, fmaxf(sreg[j][2], sreg[j][3]));
        }
        rm0 = fmaxf(rm0, __shfl_xor_sync(0xffffffffu, rm0, 1));
        rm0 = fmaxf(rm0, __shfl_xor_sync(0xffffffffu, rm0, 2));
        rm1 = fmaxf(rm1, __shfl_xor_sync(0xffffffffu, rm1, 1));
        rm1 = fmaxf(rm1, __shfl_xor_sync(0xffffffffu, rm1, 2));

        float mn0 = fmaxf(m0, rm0);
        float mn1 = fmaxf(m1, rm1);
        float sc0 = fast_exp2(m0 - mn0);
        float sc1 = fast_exp2(m1 - mn1);
        m0 = mn0; m1 = mn1;
#pragma unroll
        for (int j = 0; j < 8; j++) {
            ov[j][0] *= sc0; ov[j][1] *= sc0;
            ov[j][2] *= sc1; ov[j][3] *= sc1;
        }

        // ---- exp, pack P (fp16 hi) from accumulator, P·V ----
        float rs0 = 0.f, rs1 = 0.f;
#pragma unroll
        for (int kk = 0; kk < 4; kk++) {
            uint32_t pah[4];
#pragma unroll
            for (int u = 0; u < 2; u++) {
                int t = 2 * kk + u;
                float p0 = fast_exp2(sreg[t][0] - mn0);
                float p1 = fast_exp2(sreg[t][1] - mn0);
                float p2 = fast_exp2(sreg[t][2] - mn1);
                float p3 = fast_exp2(sreg[t][3] - mn1);
                rs0 += p0 + p1;
                rs1 += p2 + p3;
                pah[2 * u]     = pack_hf2(p0, p1);
                pah[2 * u + 1] = pack_hf2(p2, p3);
            }
#pragma unroll
            for (int jv = 0; jv < 8; jv++) {
                uint32_t vbh[2], vbl[2];
                uint32_t off = (uint32_t)((kk * 16 + vr) * FSROW + jv * 8) * 2;
                ldsm_x2_t(vbh, uVh + off);
                ldsm_x2_t(vbl, uVl + off);
                mma16816(ov[jv], pah, vbh);
                mma16816(ov[jv], pah, vbl);
            }
        }
        rs0 += __shfl_xor_sync(0xffffffffu, rs0, 1);
        rs0 += __shfl_xor_sync(0xffffffffu, rs0, 2);
        rs1 += __shfl_xor_sync(0xffffffffu, rs1, 1);
        rs1 += __shfl_xor_sync(0xffffffffu, rs1, 2);
        l0 = l0 * sc0 + rs0;
        l1 = l1 * sc1 + rs1;

        __syncthreads();                       // all warps done reading stage s
    }

    // ---- epilogue: O/l, fp16 hi concat layout ----
    float rinv0 = 1.0f / l0;
    float rinv1 = 1.0f / l1;
    size_t orow0 = base + (size_t)(q0 + wm + (lane >> 2)) * D_MODEL;
    size_t orow1 = orow0 + (size_t)8 * D_MODEL;
    int colb = ((lane & 3) << 1);
#pragma unroll
    for (int jv = 0; jv < 8; jv++) {
        int c = jv * 8 + colb;
        *(uint32_t*)(Oh + orow0 + c) = pack_hf2(ov[jv][0] * rinv0, ov[jv][1] * rinv0);
        *(uint32_t*)(Oh + orow1 + c) = pack_hf2(ov[jv][2] * rinv1, ov[jv][3] * rinv1);
    }
}

// ---------------------------------------------------------------------------
// Launch
// ---------------------------------------------------------------------------
extern "C" void kernel_launch(void* const* d_in, const int* in_sizes, int n_in,
                              void* d_out, int out_size)
{
    const float* x   = (const float*)d_in[0];
    const float* W_q = (const float*)d_in[1];
    const float* W_k = (const float*)d_in[2];
    const float* W_v = (const float*)d_in[3];
    const float* W_o = (const float*)d_in[4];
    float* out = (float*)d_out;

    __half *pxh, *pqh, *pkh, *pkl, *pvh, *pvl, *pch, *pwh, *pwl;
    cudaGetSymbolAddress((void**)&pxh, g_xh);
    cudaGetSymbolAddress((void**)&pqh, g_qh);
    cudaGetSymbolAddress((void**)&pkh, g_kh);
    cudaGetSymbolAddress((void**)&pkl, g_kl);
    cudaGetSymbolAddress((void**)&pvh, g_vh);
    cudaGetSymbolAddress((void**)&pvl, g_vl);
    cudaGetSymbolAddress((void**)&pch, g_ch);
    cudaGetSymbolAddress((void**)&pwh, g_wh);
    cudaGetSymbolAddress((void**)&pwl, g_wl);

    cudaFuncSetAttribute(mma_gemm_kernel,
                         cudaFuncAttributeMaxDynamicSharedMemorySize, SMEM_GEMM);
    cudaFuncSetAttribute(flash_mma_kernel,
                         cudaFuncAttributeMaxDynamicSharedMemorySize, FSMEM);

    const size_t WSZ = (size_t)D_MODEL * D_MODEL;   // 1048576
    const int nx4 = (int)((size_t)M_TOTAL * D_MODEL / 4);
    const int nw4 = (int)(WSZ / 4);

    // x: hi only; weights: hi/lo
    split_hi_kernel<<<(nx4 + 255) / 256, 256>>>(x, pxh, nx4);
    split_kernel<<<(nw4 + 255) / 256, 256>>>(W_q, pwh + 0 * WSZ, pwl + 0 * WSZ, nw4);
    split_kernel<<<(nw4 + 255) / 256, 256>>>(W_k, pwh + 1 * WSZ, pwl + 1 * WSZ, nw4);
    split_kernel<<<(nw4 + 255) / 256, 256>>>(W_v, pwh + 2 * WSZ, pwl + 2 * WSZ, nw4);
    split_kernel<<<(nw4 + 255) / 256, 256>>>(W_o, pwh + 3 * WSZ, pwl + 3 * WSZ, nw4);

    dim3 gGemm(D_MODEL / 128, M_TOTAL / 128);   // (8, 64)
    // Q: hi only (used as MMA A operand downstream). K, V: hi+lo (B operands).
    mma_gemm_kernel<<<gGemm, 256, SMEM_GEMM>>>(pxh, pwh + 0 * WSZ, pwl + 0 * WSZ,
                                               nullptr, pqh, nullptr, M_TOTAL, D_MODEL, D_MODEL);
    mma_gemm_kernel<<<gGemm, 256, SMEM_GEMM>>>(pxh, pwh + 1 * WSZ, pwl + 1 * WSZ,
                                               nullptr, pkh, pkl, M_TOTAL, D_MODEL, D_MODEL);
    mma_gemm_kernel<<<gGemm, 256, SMEM_GEMM>>>(pxh, pwh + 2 * WSZ, pwl + 2 * WSZ,
                                               nullptr, pvh, pvl, M_TOTAL, D_MODEL, D_MODEL);

    dim3 gFlash(SEQ / 128, BATCH * N_HEADS);    // (16, 64)
    flash_mma_kernel<<<gFlash, 256, FSMEM>>>(pqh, pkh, pkl, pvh, pvl, pch);

    // O projection: fp32 output
    mma_gemm_kernel<<<gGemm, 256, SMEM_GEMM>>>(pch, pwh + 3 * WSZ, pwl + 3 * WSZ,
                                               out, nullptr, nullptr, M_TOTAL, D_MODEL, D_MODEL);
}

// round 12
// speedup vs baseline: 4.5692x; 1.0583x over previous
#include <cuda_runtime.h>
#include <cuda_fp16.h>
#include <cstdint>
#include <cstddef>

#define D_MODEL  1024
#define N_HEADS  16
#define HEAD_DIM 64
#define BATCH    4
#define SEQ      2048
#define M_TOTAL  (BATCH * SEQ)   // 8192

// ---------------------------------------------------------------------------
// Scratch (no cudaMalloc allowed) — fp16 hi/lo split buffers
// ---------------------------------------------------------------------------
__device__ __half g_xh[(size_t)M_TOTAL * D_MODEL];
__device__ __half g_qh[(size_t)M_TOTAL * D_MODEL];
__device__ __half g_kh[(size_t)M_TOTAL * D_MODEL];
__device__ __half g_kl[(size_t)M_TOTAL * D_MODEL];
__device__ __half g_vh[(size_t)M_TOTAL * D_MODEL];
__device__ __half g_vl[(size_t)M_TOTAL * D_MODEL];
__device__ __half g_ch[(size_t)M_TOTAL * D_MODEL];
__device__ __half g_wh[(size_t)4 * D_MODEL * D_MODEL];
__device__ __half g_wl[(size_t)4 * D_MODEL * D_MODEL];

// ---------------------------------------------------------------------------
// Baseline-PTX helpers (sm_80-class; compile under compute_103)
// ---------------------------------------------------------------------------
__device__ __forceinline__ uint32_t smem_to_u32(const void* p) {
    uint32_t a;
    asm("{ .reg .u64 t; cvta.to.shared.u64 t, %1; cvt.u32.u64 %0, t; }" : "=r"(a) : "l"(p));
    return a;
}
__device__ __forceinline__ void ldsm_x4(uint32_t* r, uint32_t addr) {
    asm volatile("ldmatrix.sync.aligned.m8n8.x4.shared.b16 {%0,%1,%2,%3}, [%4];"
        : "=r"(r[0]), "=r"(r[1]), "=r"(r[2]), "=r"(r[3]) : "r"(addr));
}
__device__ __forceinline__ void ldsm_x2(uint32_t* r, uint32_t addr) {
    asm volatile("ldmatrix.sync.aligned.m8n8.x2.shared.b16 {%0,%1}, [%2];"
        : "=r"(r[0]), "=r"(r[1]) : "r"(addr));
}
__device__ __forceinline__ void ldsm_x2_t(uint32_t* r, uint32_t addr) {
    asm volatile("ldmatrix.sync.aligned.m8n8.x2.trans.shared.b16 {%0,%1}, [%2];"
        : "=r"(r[0]), "=r"(r[1]) : "r"(addr));
}
// D += A(f16) * B(f16), m16n8k16, row.col, f32 accum
__device__ __forceinline__ void mma16816(float* d, const uint32_t* a, const uint32_t* b) {
    asm volatile(
        "mma.sync.aligned.m16n8k16.row.col.f32.f16.f16.f32 "
        "{%0,%1,%2,%3}, {%4,%5,%6,%7}, {%8,%9}, {%0,%1,%2,%3};"
        : "+f"(d[0]), "+f"(d[1]), "+f"(d[2]), "+f"(d[3])
        : "r"(a[0]), "r"(a[1]), "r"(a[2]), "r"(a[3]), "r"(b[0]), "r"(b[1]));
}
__device__ __forceinline__ void cp16(uint32_t smem, const void* g) {
    asm volatile("cp.async.cg.shared.global [%0], [%1], 16;" :: "r"(smem), "l"(g));
}
#define CP_COMMIT() asm volatile("cp.async.commit_group;" ::: "memory")
#define CP_WAIT(n)  asm volatile("cp.async.wait_group %0;" :: "n"(n) : "memory")

__device__ __forceinline__ float fast_exp2(float x) {
    float y;
    asm("ex2.approx.ftz.f32 %0, %1;" : "=f"(y) : "f"(x));
    return y;
}
__device__ __forceinline__ uint32_t pack_hf2(float a, float b) {
    __half2 h = __floats2half2_rn(a, b);
    return reinterpret_cast<uint32_t&>(h);
}
__device__ __forceinline__ uint32_t pack_hf2_hi(float a, float b, float& ra, float& rb) {
    __half2 h = __floats2half2_rn(a, b);
    float2 f = __half22float2(h);
    ra = a - f.x;
    rb = b - f.y;
    return reinterpret_cast<uint32_t&>(h);
}

// ---------------------------------------------------------------------------
// fp32 -> fp16 splits
// ---------------------------------------------------------------------------
__global__ __launch_bounds__(256)
void split_w_kernel(const float* __restrict__ W0, const float* __restrict__ W1,
                    const float* __restrict__ W2, const float* __restrict__ W3,
                    __half* __restrict__ hi, __half* __restrict__ lo, int n4)
{
    int i = blockIdx.x * 256 + threadIdx.x;
    if (i >= n4) return;
    int w = blockIdx.y;
    const float* src = (w == 0) ? W0 : (w == 1) ? W1 : (w == 2) ? W2 : W3;
    size_t o = (size_t)w * n4 + i;            // float4-unit offset into concat
    float4 v = ((const float4*)src)[i];
    float rx, ry, rz, rw;
    uint32_t h0 = pack_hf2_hi(v.x, v.y, rx, ry);
    uint32_t h1 = pack_hf2_hi(v.z, v.w, rz, rw);
    ((uint32_t*)hi)[2 * o]     = h0;
    ((uint32_t*)hi)[2 * o + 1] = h1;
    ((uint32_t*)lo)[2 * o]     = pack_hf2(rx, ry);
    ((uint32_t*)lo)[2 * o + 1] = pack_hf2(rz, rw);
}

__global__ __launch_bounds__(256)
void split_hi_kernel(const float* __restrict__ x, __half* __restrict__ hi, int n4)
{
    int i = blockIdx.x * 256 + threadIdx.x;
    if (i >= n4) return;
    float4 v = ((const float4*)x)[i];
    ((uint32_t*)hi)[2 * i]     = pack_hf2(v.x, v.y);
    ((uint32_t*)hi)[2 * i + 1] = pack_hf2(v.z, v.w);
}

// ---------------------------------------------------------------------------
// Shared GEMM mainloop pieces (fp16 2-product, 2-stage cp.async, 2 CTAs/SM)
// ---------------------------------------------------------------------------
#define BK 64
#define SROW 72                              // padded row, fp16 elements (144B)
#define TILE_B (128 * SROW * 2)              // 18432 bytes per tile
#define STAGE_B (3 * TILE_B)                 // 55296 per stage (Ah, Bh, Bl)
#define SMEM_GEMM (2 * STAGE_B)              // 110592 bytes

// ---------------------------------------------------------------------------
// Fused Q/K/V projection GEMM: A = x (8192x1024 fp16-hi),
// B = concat(Wq,Wk,Wv) (3072x1024 hi/lo). Epilogue routes by N-segment.
// ---------------------------------------------------------------------------
__global__ __launch_bounds__(256, 2)
void mma_gemm_qkv_kernel(const __half* __restrict__ Ah,
                         const __half* __restrict__ Bh, const __half* __restrict__ Bl,
                         __half* __restrict__ Qh,
                         __half* __restrict__ Kh, __half* __restrict__ Kl,
                         __half* __restrict__ Vh, __half* __restrict__ Vl)
{
    extern __shared__ char smem[];
    const int tid  = threadIdx.x;
    const int warp = tid >> 5;
    const int lane = tid & 31;
    const int bm = blockIdx.y * 128;
    const int bn = blockIdx.x * 128;          // 0..2944 over concat N=3072
    const int wm = (warp >> 2) * 64;
    const int wn = (warp & 3) * 32;
    const int K = D_MODEL;

    const uint32_t sbase = smem_to_u32(smem);
    const int lr  = tid >> 3;
    const int lc8 = (tid & 7) << 3;

    auto issue = [&](int ch, int s) {
        const int k0g = ch * BK;
        const uint32_t st = sbase + s * STAGE_B;
#pragma unroll
        for (int it = 0; it < 4; it++) {
            int r = lr + it * 32;
            uint32_t so = (uint32_t)(r * SROW + lc8) * 2;
            size_t ga = (size_t)(bm + r) * K + k0g + lc8;
            size_t gb = (size_t)(bn + r) * K + k0g + lc8;
            cp16(st + 0 * TILE_B + so, Ah + ga);
            cp16(st + 1 * TILE_B + so, Bh + gb);
            cp16(st + 2 * TILE_B + so, Bl + gb);
        }
        CP_COMMIT();
    };

    const int a_row  = lane & 15;
    const int a_koff = (lane >> 4) << 3;
    const int b_row  = lane & 7;
    const int b_koff = ((lane >> 3) & 1) << 3;

    float acc[4][4][4];
#pragma unroll
    for (int i = 0; i < 4; i++)
#pragma unroll
        for (int j = 0; j < 4; j++)
#pragma unroll
            for (int t = 0; t < 4; t++) acc[i][j][t] = 0.f;

    const int nchunks = K / BK;
    issue(0, 0);
    for (int ch = 0; ch < nchunks; ch++) {
        const int s = ch & 1;
        if (ch + 1 < nchunks) { issue(ch + 1, 1 - s); CP_WAIT(1); }
        else                  { CP_WAIT(0); }
        __syncthreads();

        const uint32_t uAh = sbase + s * STAGE_B;
        const uint32_t uBh = uAh + TILE_B;
        const uint32_t uBl = uAh + 2 * TILE_B;
#pragma unroll
        for (int ks = 0; ks < 4; ks++) {
            const int k0 = ks * 16;
            uint32_t ah[4][4], bh[4][2], bl[4][2];
#pragma unroll
            for (int i = 0; i < 4; i++) {
                uint32_t off = (uint32_t)((wm + i * 16 + a_row) * SROW + k0 + a_koff) * 2;
                ldsm_x4(ah[i], uAh + off);
            }
#pragma unroll
            for (int j = 0; j < 4; j++) {
                uint32_t off = (uint32_t)((wn + j * 8 + b_row) * SROW + k0 + b_koff) * 2;
                ldsm_x2(bh[j], uBh + off);
                ldsm_x2(bl[j], uBl + off);
            }
#pragma unroll
            for (int i = 0; i < 4; i++)
#pragma unroll
                for (int j = 0; j < 4; j++) {
                    mma16816(acc[i][j], ah[i], bh[j]);
                    mma16816(acc[i][j], ah[i], bl[j]);
                }
        }
        __syncthreads();
    }

    // epilogue: route by segment of the concatenated N
    const int seg = bn >> 10;                 // 0=Q, 1=K, 2=V
    const int cn  = bn & 1023;
    __half* Chi = (seg == 0) ? Qh : (seg == 1) ? Kh : Vh;
    __half* Clo = (seg == 1) ? Kl : (seg == 2) ? Vl : nullptr;

    const int gr = lane >> 2;
    const int gc = (lane & 3) << 1;
    if (Clo) {
#pragma unroll
        for (int i = 0; i < 4; i++) {
#pragma unroll
            for (int j = 0; j < 4; j++) {
                size_t r0 = (size_t)(bm + wm + i * 16 + gr) * D_MODEL + cn + wn + j * 8 + gc;
                size_t r1 = r0 + (size_t)8 * D_MODEL;
                float e0, e1, e2, e3;
                uint32_t h01 = pack_hf2_hi(acc[i][j][0], acc[i][j][1], e0, e1);
                uint32_t h23 = pack_hf2_hi(acc[i][j][2], acc[i][j][3], e2, e3);
                *(uint32_t*)(Chi + r0) = h01;
                *(uint32_t*)(Clo + r0) = pack_hf2(e0, e1);
                *(uint32_t*)(Chi + r1) = h23;
                *(uint32_t*)(Clo + r1) = pack_hf2(e2, e3);
            }
        }
    } else {
#pragma unroll
        for (int i = 0; i < 4; i++) {
#pragma unroll
            for (int j = 0; j < 4; j++) {
                size_t r0 = (size_t)(bm + wm + i * 16 + gr) * D_MODEL + cn + wn + j * 8 + gc;
                size_t r1 = r0 + (size_t)8 * D_MODEL;
                *(uint32_t*)(Chi + r0) = pack_hf2(acc[i][j][0], acc[i][j][1]);
                *(uint32_t*)(Chi + r1) = pack_hf2(acc[i][j][2], acc[i][j][3]);
            }
        }
    }
}

// ---------------------------------------------------------------------------
// O-projection GEMM (fp32 output), same mainloop.
// ---------------------------------------------------------------------------
__global__ __launch_bounds__(256, 2)
void mma_gemm_kernel(const __half* __restrict__ Ah,
                     const __half* __restrict__ Bh, const __half* __restrict__ Bl,
                     float* __restrict__ C, int M, int N, int K)
{
    extern __shared__ char smem[];
    const int tid  = threadIdx.x;
    const int warp = tid >> 5;
    const int lane = tid & 31;
    const int bm = blockIdx.y * 128;
    const int bn = blockIdx.x * 128;
    const int wm = (warp >> 2) * 64;
    const int wn = (warp & 3) * 32;

    const uint32_t sbase = smem_to_u32(smem);
    const int lr  = tid >> 3;
    const int lc8 = (tid & 7) << 3;

    auto issue = [&](int ch, int s) {
        const int k0g = ch * BK;
        const uint32_t st = sbase + s * STAGE_B;
#pragma unroll
        for (int it = 0; it < 4; it++) {
            int r = lr + it * 32;
            uint32_t so = (uint32_t)(r * SROW + lc8) * 2;
            size_t ga = (size_t)(bm + r) * K + k0g + lc8;
            size_t gb = (size_t)(bn + r) * K + k0g + lc8;
            cp16(st + 0 * TILE_B + so, Ah + ga);
            cp16(st + 1 * TILE_B + so, Bh + gb);
            cp16(st + 2 * TILE_B + so, Bl + gb);
        }
        CP_COMMIT();
    };

    const int a_row  = lane & 15;
    const int a_koff = (lane >> 4) << 3;
    const int b_row  = lane & 7;
    const int b_koff = ((lane >> 3) & 1) << 3;

    float acc[4][4][4];
#pragma unroll
    for (int i = 0; i < 4; i++)
#pragma unroll
        for (int j = 0; j < 4; j++)
#pragma unroll
            for (int t = 0; t < 4; t++) acc[i][j][t] = 0.f;

    const int nchunks = K / BK;
    issue(0, 0);
    for (int ch = 0; ch < nchunks; ch++) {
        const int s = ch & 1;
        if (ch + 1 < nchunks) { issue(ch + 1, 1 - s); CP_WAIT(1); }
        else                  { CP_WAIT(0); }
        __syncthreads();

        const uint32_t uAh = sbase + s * STAGE_B;
        const uint32_t uBh = uAh + TILE_B;
        const uint32_t uBl = uAh + 2 * TILE_B;
#pragma unroll
        for (int ks = 0; ks < 4; ks++) {
            const int k0 = ks * 16;
            uint32_t ah[4][4], bh[4][2], bl[4][2];
#pragma unroll
            for (int i = 0; i < 4; i++) {
                uint32_t off = (uint32_t)((wm + i * 16 + a_row) * SROW + k0 + a_koff) * 2;
                ldsm_x4(ah[i], uAh + off);
            }
#pragma unroll
            for (int j = 0; j < 4; j++) {
                uint32_t off = (uint32_t)((wn + j * 8 + b_row) * SROW + k0 + b_koff) * 2;
                ldsm_x2(bh[j], uBh + off);
                ldsm_x2(bl[j], uBl + off);
            }
#pragma unroll
            for (int i = 0; i < 4; i++)
#pragma unroll
                for (int j = 0; j < 4; j++) {
                    mma16816(acc[i][j], ah[i], bh[j]);
                    mma16816(acc[i][j], ah[i], bl[j]);
                }
        }
        __syncthreads();
    }

    const int gr = lane >> 2;
    const int gc = (lane & 3) << 1;
#pragma unroll
    for (int i = 0; i < 4; i++) {
#pragma unroll
        for (int j = 0; j < 4; j++) {
            size_t r0 = (size_t)(bm + wm + i * 16 + gr) * N + bn + wn + j * 8 + gc;
            size_t r1 = r0 + (size_t)8 * N;
            *(float2*)(C + r0) = make_float2(acc[i][j][0], acc[i][j][1]);
            *(float2*)(C + r1) = make_float2(acc[i][j][2], acc[i][j][3]);
        }
    }
}

// ---------------------------------------------------------------------------
// Tensor-core causal flash attention (fp16 2-product via mma.sync),
// 2-stage cp.async K/V pipeline, 2 CTAs/SM, heavy-tiles-first scheduling.
// ---------------------------------------------------------------------------
#define FSROW 72
#define KVARR_B (64 * FSROW * 2)                 // 9216 bytes per array
#define KVSTAGE_B (4 * KVARR_B)                  // 36864 per stage
#define FSMEM (128 * FSROW * 2 + 2 * KVSTAGE_B)  // 92160 bytes

__global__ __launch_bounds__(256, 2)
void flash_mma_kernel(const __half* __restrict__ Qh,
                      const __half* __restrict__ Kh, const __half* __restrict__ Kl,
                      const __half* __restrict__ Vh, const __half* __restrict__ Vl,
                      __half* __restrict__ Oh)
{
    extern __shared__ char fsm[];
    char* sQh = fsm;                                   // [128][FSROW] fp16
    const uint32_t uQh = smem_to_u32(sQh);
    const uint32_t uKV = uQh + 128 * FSROW * 2;        // 2 stages of K/V hi/lo

    const int tid  = threadIdx.x;
    const int warp = tid >> 5;
    const int lane = tid & 31;
    const int qi = (int)(gridDim.x - 1) - (int)blockIdx.x;   // heavy-first (LPT)
    const int bh = blockIdx.y;                 // b*16+h
    const int b = bh >> 4, h = bh & 15;
    const int q0 = qi << 7;
    const int wm = warp << 4;

    const size_t base = (size_t)b * SEQ * D_MODEL + (size_t)h * HEAD_DIM;
    const __half* kvsrc[4] = { Kh + base, Kl + base, Vh + base, Vl + base };

    auto issueKV = [&](int kt, int s) {
        const uint32_t st = uKV + s * KVSTAGE_B;
#pragma unroll
        for (int it = 0; it < 8; it++) {
            int lin = tid + it * 256;
            int arr = lin >> 9;
            int idx = lin & 511;
            int r   = idx >> 3;
            int c8  = (idx & 7) << 3;
            cp16(st + arr * KVARR_B + (uint32_t)(r * FSROW + c8) * 2,
                 kvsrc[arr] + (size_t)((kt << 6) + r) * D_MODEL + c8);
        }
        CP_COMMIT();
    };

    // ---- load Q tile + prefetch KV tile 0 ----
#pragma unroll
    for (int it = 0; it < 4; it++) {
        int lin = tid + it * 256;
        int r   = lin >> 3;
        int c8  = (lin & 7) << 3;
        uint4 t = *(const uint4*)(Qh + base + (size_t)(q0 + r) * D_MODEL + c8);
        char* d = sQh + (r * FSROW + c8) * 2;
        *(uint2*)(d)     = make_uint2(t.x, t.y);
        *(uint2*)(d + 8) = make_uint2(t.z, t.w);
    }
    issueKV(0, 0);
    __syncthreads();

    uint32_t qh[4][4];
    {
        const int ar = lane & 15;
        const int ak = (lane >> 4) << 3;
#pragma unroll
        for (int ks = 0; ks < 4; ks++) {
            uint32_t off = (uint32_t)((wm + ar) * FSROW + ks * 16 + ak) * 2;
            ldsm_x4(qh[ks], uQh + off);
        }
    }

    const float NEG = -1e30f;
    const float CSC = 0.125f * 1.4426950408889634f;
    float m0 = NEG, m1 = NEG, l0 = 0.f, l1 = 0.f;
    float ov[8][4];
#pragma unroll
    for (int j = 0; j < 8; j++)
#pragma unroll
        for (int t = 0; t < 4; t++) ov[j][t] = 0.f;

    const int r0g = q0 + wm + (lane >> 2);
    const int r1g = r0g + 8;
    const int br  = lane & 7;
    const int bk  = ((lane >> 3) & 1) << 3;
    const int vr  = lane & 15;

    const int kend = 2 * qi + 2;
    for (int kt = 0; kt < kend; kt++) {
        const int s = kt & 1;
        if (kt + 1 < kend) { issueKV(kt + 1, 1 - s); CP_WAIT(1); }
        else               { CP_WAIT(0); }
        __syncthreads();

        const uint32_t uKh = uKV + s * KVSTAGE_B;
        const uint32_t uKl = uKh + KVARR_B;
        const uint32_t uVh = uKh + 2 * KVARR_B;
        const uint32_t uVl = uKh + 3 * KVARR_B;

        float sreg[8][4];
#pragma unroll
        for (int j = 0; j < 8; j++)
#pragma unroll
            for (int t = 0; t < 4; t++) sreg[j][t] = 0.f;

#pragma unroll
        for (int j = 0; j < 8; j++) {
#pragma unroll
            for (int ks = 0; ks < 4; ks++) {
                uint32_t kbh[2], kbl[2];
                uint32_t off = (uint32_t)((j * 8 + br) * FSROW + ks * 16 + bk) * 2;
                ldsm_x2(kbh, uKh + off);
                ldsm_x2(kbl, uKl + off);
                mma16816(sreg[j], qh[ks], kbh);
                mma16816(sreg[j], qh[ks], kbl);
            }
        }

        const bool diag = (kt >= 2 * qi);
#pragma unroll
        for (int j = 0; j < 8; j++) {
            sreg[j][0] *= CSC; sreg[j][1] *= CSC; sreg[j][2] *= CSC; sreg[j][3] *= CSC;
            if (diag) {
                int cb = (kt << 6) + j * 8 + ((lane & 3) << 1);
                if (cb     > r0g) sreg[j][0] = NEG;
                if (cb + 1 > r0g) sreg[j][1] = NEG;
                if (cb     > r1g) sreg[j][2] = NEG;
                if (cb + 1 > r1g) sreg[j][3] = NEG;
            }
        }

        float rm0 = NEG, rm1 = NEG;
#pragma unroll
        for (int j = 0; j < 8; j++) {
            rm0 = fmaxf(rm0, fmaxf(sreg[j][0], sreg[j][1]));
            rm1 = fmaxf(rm1, fmaxf(sreg[j][2], sreg[j][3]));
        }
        rm0 = fmaxf(rm0, __shfl_xor_sync(0xffffffffu, rm0, 1));
        rm0 = fmaxf(rm0, __shfl_xor_sync(0xffffffffu, rm0, 2));
        rm1 = fmaxf(rm1, __shfl_xor_sync(0xffffffffu, rm1, 1));
        rm1 = fmaxf(rm1, __shfl_xor_sync(0xffffffffu, rm1, 2));

        float mn0 = fmaxf(m0, rm0);
        float mn1 = fmaxf(m1, rm1);
        float sc0 = fast_exp2(m0 - mn0);
        float sc1 = fast_exp2(m1 - mn1);
        m0 = mn0; m1 = mn1;
#pragma unroll
        for (int j = 0; j < 8; j++) {
            ov[j][0] *= sc0; ov[j][1] *= sc0;
            ov[j][2] *= sc1; ov[j][3] *= sc1;
        }

        float rs0 = 0.f, rs1 = 0.f;
#pragma unroll
        for (int kk = 0; kk < 4; kk++) {
            uint32_t pah[4];
#pragma unroll
            for (int u = 0; u < 2; u++) {
                int t = 2 * kk + u;
                float p0 = fast_exp2(sreg[t][0] - mn0);
                float p1 = fast_exp2(sreg[t][1] - mn0);
                float p2 = fast_exp2(sreg[t][2] - mn1);
                float p3 = fast_exp2(sreg[t][3] - mn1);
                rs0 += p0 + p1;
                rs1 += p2 + p3;
                pah[2 * u]     = pack_hf2(p0, p1);
                pah[2 * u + 1] = pack_hf2(p2, p3);
            }
#pragma unroll
            for (int jv = 0; jv < 8; jv++) {
                uint32_t vbh[2], vbl[2];
                uint32_t off = (uint32_t)((kk * 16 + vr) * FSROW + jv * 8) * 2;
                ldsm_x2_t(vbh, uVh + off);
                ldsm_x2_t(vbl, uVl + off);
                mma16816(ov[jv], pah, vbh);
                mma16816(ov[jv], pah, vbl);
            }
        }
        rs0 += __shfl_xor_sync(0xffffffffu, rs0, 1);
        rs0 += __shfl_xor_sync(0xffffffffu, rs0, 2);
        rs1 += __shfl_xor_sync(0xffffffffu, rs1, 1);
        rs1 += __shfl_xor_sync(0xffffffffu, rs1, 2);
        l0 = l0 * sc0 + rs0;
        l1 = l1 * sc1 + rs1;

        __syncthreads();
    }

    float rinv0 = 1.0f / l0;
    float rinv1 = 1.0f / l1;
    size_t orow0 = base + (size_t)(q0 + wm + (lane >> 2)) * D_MODEL;
    size_t orow1 = orow0 + (size_t)8 * D_MODEL;
    int colb = ((lane & 3) << 1);
#pragma unroll
    for (int jv = 0; jv < 8; jv++) {
        int c = jv * 8 + colb;
        *(uint32_t*)(Oh + orow0 + c) = pack_hf2(ov[jv][0] * rinv0, ov[jv][1] * rinv0);
        *(uint32_t*)(Oh + orow1 + c) = pack_hf2(ov[jv][2] * rinv1, ov[jv][3] * rinv1);
    }
}

// ---------------------------------------------------------------------------
// Launch
// ---------------------------------------------------------------------------
extern "C" void kernel_launch(void* const* d_in, const int* in_sizes, int n_in,
                              void* d_out, int out_size)
{
    const float* x   = (const float*)d_in[0];
    const float* W_q = (const float*)d_in[1];
    const float* W_k = (const float*)d_in[2];
    const float* W_v = (const float*)d_in[3];
    const float* W_o = (const float*)d_in[4];
    float* out = (float*)d_out;

    __half *pxh, *pqh, *pkh, *pkl, *pvh, *pvl, *pch, *pwh, *pwl;
    cudaGetSymbolAddress((void**)&pxh, g_xh);
    cudaGetSymbolAddress((void**)&pqh, g_qh);
    cudaGetSymbolAddress((void**)&pkh, g_kh);
    cudaGetSymbolAddress((void**)&pkl, g_kl);
    cudaGetSymbolAddress((void**)&pvh, g_vh);
    cudaGetSymbolAddress((void**)&pvl, g_vl);
    cudaGetSymbolAddress((void**)&pch, g_ch);
    cudaGetSymbolAddress((void**)&pwh, g_wh);
    cudaGetSymbolAddress((void**)&pwl, g_wl);

    cudaFuncSetAttribute(mma_gemm_qkv_kernel,
                         cudaFuncAttributeMaxDynamicSharedMemorySize, SMEM_GEMM);
    cudaFuncSetAttribute(mma_gemm_kernel,
                         cudaFuncAttributeMaxDynamicSharedMemorySize, SMEM_GEMM);
    cudaFuncSetAttribute(flash_mma_kernel,
                         cudaFuncAttributeMaxDynamicSharedMemorySize, FSMEM);

    const size_t WSZ = (size_t)D_MODEL * D_MODEL;   // 1048576
    const int nx4 = (int)((size_t)M_TOTAL * D_MODEL / 4);
    const int nw4 = (int)(WSZ / 4);

    // x: hi only; all 4 weights: hi/lo in one launch
    split_hi_kernel<<<(nx4 + 255) / 256, 256>>>(x, pxh, nx4);
    dim3 gSplitW((nw4 + 255) / 256, 4);
    split_w_kernel<<<gSplitW, 256>>>(W_q, W_k, W_v, W_o, pwh, pwl, nw4);

    // fused Q/K/V projection: N = 3072 over concatenated weights
    dim3 gQKV(3 * D_MODEL / 128, M_TOTAL / 128);    // (24, 64)
    mma_gemm_qkv_kernel<<<gQKV, 256, SMEM_GEMM>>>(pxh, pwh, pwl,
                                                  pqh, pkh, pkl, pvh, pvl);

    dim3 gFlash(SEQ / 128, BATCH * N_HEADS);        // (16, 64)
    flash_mma_kernel<<<gFlash, 256, FSMEM>>>(pqh, pkh, pkl, pvh, pvl, pch);

    // O projection: fp32 output
    dim3 gGemm(D_MODEL / 128, M_TOTAL / 128);       // (8, 64)
    mma_gemm_kernel<<<gGemm, 256, SMEM_GEMM>>>(pch, pwh + 3 * WSZ, pwl + 3 * WSZ,
                                               out, M_TOTAL, D_MODEL, D_MODEL);
}

// round 13
// speedup vs baseline: 4.6995x; 1.0285x over previous
#include <cuda_runtime.h>
#include <cuda_fp16.h>
#include <cstdint>
#include <cstddef>

#define D_MODEL  1024
#define N_HEADS  16
#define HEAD_DIM 64
#define BATCH    4
#define SEQ      2048
#define M_TOTAL  (BATCH * SEQ)   // 8192

// ---------------------------------------------------------------------------
// Scratch (no cudaMalloc allowed) — fp16 hi/lo split buffers
// ---------------------------------------------------------------------------
__device__ __half g_xh[(size_t)M_TOTAL * D_MODEL];
__device__ __half g_qh[(size_t)M_TOTAL * D_MODEL];
__device__ __half g_kh[(size_t)M_TOTAL * D_MODEL];
__device__ __half g_kl[(size_t)M_TOTAL * D_MODEL];
__device__ __half g_vh[(size_t)M_TOTAL * D_MODEL];
__device__ __half g_vl[(size_t)M_TOTAL * D_MODEL];
__device__ __half g_ch[(size_t)M_TOTAL * D_MODEL];
__device__ __half g_wh[(size_t)4 * D_MODEL * D_MODEL];
__device__ __half g_wl[(size_t)4 * D_MODEL * D_MODEL];

// ---------------------------------------------------------------------------
// Baseline-PTX helpers (sm_80-class; compile under compute_103)
// ---------------------------------------------------------------------------
__device__ __forceinline__ uint32_t smem_to_u32(const void* p) {
    uint32_t a;
    asm("{ .reg .u64 t; cvta.to.shared.u64 t, %1; cvt.u32.u64 %0, t; }" : "=r"(a) : "l"(p));
    return a;
}
__device__ __forceinline__ void ldsm_x4(uint32_t* r, uint32_t addr) {
    asm volatile("ldmatrix.sync.aligned.m8n8.x4.shared.b16 {%0,%1,%2,%3}, [%4];"
        : "=r"(r[0]), "=r"(r[1]), "=r"(r[2]), "=r"(r[3]) : "r"(addr));
}
__device__ __forceinline__ void ldsm_x4_t(uint32_t* r, uint32_t addr) {
    asm volatile("ldmatrix.sync.aligned.m8n8.x4.trans.shared.b16 {%0,%1,%2,%3}, [%4];"
        : "=r"(r[0]), "=r"(r[1]), "=r"(r[2]), "=r"(r[3]) : "r"(addr));
}
// D += A(f16) * B(f16), m16n8k16, row.col, f32 accum
__device__ __forceinline__ void mma16816(float* d, const uint32_t* a, const uint32_t* b) {
    asm volatile(
        "mma.sync.aligned.m16n8k16.row.col.f32.f16.f16.f32 "
        "{%0,%1,%2,%3}, {%4,%5,%6,%7}, {%8,%9}, {%0,%1,%2,%3};"
        : "+f"(d[0]), "+f"(d[1]), "+f"(d[2]), "+f"(d[3])
        : "r"(a[0]), "r"(a[1]), "r"(a[2]), "r"(a[3]), "r"(b[0]), "r"(b[1]));
}
__device__ __forceinline__ void cp16(uint32_t smem, const void* g) {
    asm volatile("cp.async.cg.shared.global [%0], [%1], 16;" :: "r"(smem), "l"(g));
}
#define CP_COMMIT() asm volatile("cp.async.commit_group;" ::: "memory")
#define CP_WAIT(n)  asm volatile("cp.async.wait_group %0;" :: "n"(n) : "memory")

__device__ __forceinline__ float fast_exp2(float x) {
    float y;
    asm("ex2.approx.ftz.f32 %0, %1;" : "=f"(y) : "f"(x));
    return y;
}
__device__ __forceinline__ uint32_t pack_hf2(float a, float b) {
    __half2 h = __floats2half2_rn(a, b);
    return reinterpret_cast<uint32_t&>(h);
}
__device__ __forceinline__ uint32_t pack_hf2_hi(float a, float b, float& ra, float& rb) {
    __half2 h = __floats2half2_rn(a, b);
    float2 f = __half22float2(h);
    ra = a - f.x;
    rb = b - f.y;
    return reinterpret_cast<uint32_t&>(h);
}

// ---------------------------------------------------------------------------
// fp32 -> fp16 splits
// ---------------------------------------------------------------------------
__global__ __launch_bounds__(256)
void split_w_kernel(const float* __restrict__ W0, const float* __restrict__ W1,
                    const float* __restrict__ W2, const float* __restrict__ W3,
                    __half* __restrict__ hi, __half* __restrict__ lo, int n4)
{
    int i = blockIdx.x * 256 + threadIdx.x;
    if (i >= n4) return;
    int w = blockIdx.y;
    const float* src = (w == 0) ? W0 : (w == 1) ? W1 : (w == 2) ? W2 : W3;
    size_t o = (size_t)w * n4 + i;            // float4-unit offset into concat
    float4 v = ((const float4*)src)[i];
    float rx, ry, rz, rw;
    uint32_t h0 = pack_hf2_hi(v.x, v.y, rx, ry);
    uint32_t h1 = pack_hf2_hi(v.z, v.w, rz, rw);
    ((uint32_t*)hi)[2 * o]     = h0;
    ((uint32_t*)hi)[2 * o + 1] = h1;
    ((uint32_t*)lo)[2 * o]     = pack_hf2(rx, ry);
    ((uint32_t*)lo)[2 * o + 1] = pack_hf2(rz, rw);
}

__global__ __launch_bounds__(256)
void split_hi_kernel(const float* __restrict__ x, __half* __restrict__ hi, int n4)
{
    int i = blockIdx.x * 256 + threadIdx.x;
    if (i >= n4) return;
    float4 v = ((const float4*)x)[i];
    ((uint32_t*)hi)[2 * i]     = pack_hf2(v.x, v.y);
    ((uint32_t*)hi)[2 * i + 1] = pack_hf2(v.z, v.w);
}

// ---------------------------------------------------------------------------
// Shared GEMM constants (fp16 2-product, 2-stage cp.async, 2 CTAs/SM)
// ---------------------------------------------------------------------------
#define BK 64
#define SROW 72                              // padded row, fp16 elements (144B)
#define TILE_B (128 * SROW * 2)              // 18432 bytes per tile
#define STAGE_B (3 * TILE_B)                 // 55296 per stage (Ah, Bh, Bl)
#define SMEM_GEMM (2 * STAGE_B)              // 110592 bytes

// ---------------------------------------------------------------------------
// Fused Q/K/V projection GEMM: A = x (8192x1024 fp16-hi),
// B = concat(Wq,Wk,Wv) (3072x1024 hi/lo). Epilogue routes by N-segment.
// ---------------------------------------------------------------------------
__global__ __launch_bounds__(256, 2)
void mma_gemm_qkv_kernel(const __half* __restrict__ Ah,
                         const __half* __restrict__ Bh, const __half* __restrict__ Bl,
                         __half* __restrict__ Qh,
                         __half* __restrict__ Kh, __half* __restrict__ Kl,
                         __half* __restrict__ Vh, __half* __restrict__ Vl)
{
    extern __shared__ char smem[];
    const int tid  = threadIdx.x;
    const int warp = tid >> 5;
    const int lane = tid & 31;
    const int bm = blockIdx.y * 128;
    const int bn = blockIdx.x * 128;          // 0..2944 over concat N=3072
    const int wm = (warp >> 2) * 64;
    const int wn = (warp & 3) * 32;
    const int K = D_MODEL;

    const uint32_t sbase = smem_to_u32(smem);
    const int lr  = tid >> 3;
    const int lc8 = (tid & 7) << 3;

    auto issue = [&](int ch, int s) {
        const int k0g = ch * BK;
        const uint32_t st = sbase + s * STAGE_B;
#pragma unroll
        for (int it = 0; it < 4; it++) {
            int r = lr + it * 32;
            uint32_t so = (uint32_t)(r * SROW + lc8) * 2;
            size_t ga = (size_t)(bm + r) * K + k0g + lc8;
            size_t gb = (size_t)(bn + r) * K + k0g + lc8;
            cp16(st + 0 * TILE_B + so, Ah + ga);
            cp16(st + 1 * TILE_B + so, Bh + gb);
            cp16(st + 2 * TILE_B + so, Bl + gb);
        }
        CP_COMMIT();
    };

    const int a_row  = lane & 15;
    const int a_koff = (lane >> 4) << 3;
    const int b_row  = lane & 7;
    const int b_koff = ((lane >> 3) & 1) << 3;
    const int jsel8  = (lane >> 4) << 3;      // pair-select for x4 B loads

    float acc[4][4][4];
#pragma unroll
    for (int i = 0; i < 4; i++)
#pragma unroll
        for (int j = 0; j < 4; j++)
#pragma unroll
            for (int t = 0; t < 4; t++) acc[i][j][t] = 0.f;

    const int nchunks = K / BK;
    issue(0, 0);
    for (int ch = 0; ch < nchunks; ch++) {
        const int s = ch & 1;
        if (ch + 1 < nchunks) { issue(ch + 1, 1 - s); CP_WAIT(1); }
        else                  { CP_WAIT(0); }
        __syncthreads();

        const uint32_t uAh = sbase + s * STAGE_B;
        const uint32_t uBh = uAh + TILE_B;
        const uint32_t uBl = uAh + 2 * TILE_B;
#pragma unroll
        for (int ks = 0; ks < 4; ks++) {
            const int k0 = ks * 16;
            uint32_t ah[4][4], bh[2][4], bl[2][4];
#pragma unroll
            for (int i = 0; i < 4; i++) {
                uint32_t off = (uint32_t)((wm + i * 16 + a_row) * SROW + k0 + a_koff) * 2;
                ldsm_x4(ah[i], uAh + off);
            }
#pragma unroll
            for (int jp = 0; jp < 2; jp++) {   // pair (2jp, 2jp+1)
                uint32_t off = (uint32_t)((wn + jp * 16 + jsel8 + b_row) * SROW + k0 + b_koff) * 2;
                ldsm_x4(bh[jp], uBh + off);
                ldsm_x4(bl[jp], uBl + off);
            }
#pragma unroll
            for (int i = 0; i < 4; i++)
#pragma unroll
                for (int jp = 0; jp < 2; jp++)
#pragma unroll
                    for (int u = 0; u < 2; u++) {
                        mma16816(acc[i][2 * jp + u], ah[i], bh[jp] + 2 * u);
                        mma16816(acc[i][2 * jp + u], ah[i], bl[jp] + 2 * u);
                    }
        }
        __syncthreads();
    }

    // epilogue: route by segment of the concatenated N
    const int seg = bn >> 10;                 // 0=Q, 1=K, 2=V
    const int cn  = bn & 1023;
    __half* Chi = (seg == 0) ? Qh : (seg == 1) ? Kh : Vh;
    __half* Clo = (seg == 1) ? Kl : (seg == 2) ? Vl : nullptr;

    const int gr = lane >> 2;
    const int gc = (lane & 3) << 1;
    if (Clo) {
#pragma unroll
        for (int i = 0; i < 4; i++) {
#pragma unroll
            for (int j = 0; j < 4; j++) {
                size_t r0 = (size_t)(bm + wm + i * 16 + gr) * D_MODEL + cn + wn + j * 8 + gc;
                size_t r1 = r0 + (size_t)8 * D_MODEL;
                float e0, e1, e2, e3;
                uint32_t h01 = pack_hf2_hi(acc[i][j][0], acc[i][j][1], e0, e1);
                uint32_t h23 = pack_hf2_hi(acc[i][j][2], acc[i][j][3], e2, e3);
                *(uint32_t*)(Chi + r0) = h01;
                *(uint32_t*)(Clo + r0) = pack_hf2(e0, e1);
                *(uint32_t*)(Chi + r1) = h23;
                *(uint32_t*)(Clo + r1) = pack_hf2(e2, e3);
            }
        }
    } else {
#pragma unroll
        for (int i = 0; i < 4; i++) {
#pragma unroll
            for (int j = 0; j < 4; j++) {
                size_t r0 = (size_t)(bm + wm + i * 16 + gr) * D_MODEL + cn + wn + j * 8 + gc;
                size_t r1 = r0 + (size_t)8 * D_MODEL;
                *(uint32_t*)(Chi + r0) = pack_hf2(acc[i][j][0], acc[i][j][1]);
                *(uint32_t*)(Chi + r1) = pack_hf2(acc[i][j][2], acc[i][j][3]);
            }
        }
    }
}

// ---------------------------------------------------------------------------
// O-projection GEMM (fp32 output), same mainloop.
// ---------------------------------------------------------------------------
__global__ __launch_bounds__(256, 2)
void mma_gemm_kernel(const __half* __restrict__ Ah,
                     const __half* __restrict__ Bh, const __half* __restrict__ Bl,
                     float* __restrict__ C, int M, int N, int K)
{
    extern __shared__ char smem[];
    const int tid  = threadIdx.x;
    const int warp = tid >> 5;
    const int lane = tid & 31;
    const int bm = blockIdx.y * 128;
    const int bn = blockIdx.x * 128;
    const int wm = (warp >> 2) * 64;
    const int wn = (warp & 3) * 32;

    const uint32_t sbase = smem_to_u32(smem);
    const int lr  = tid >> 3;
    const int lc8 = (tid & 7) << 3;

    auto issue = [&](int ch, int s) {
        const int k0g = ch * BK;
        const uint32_t st = sbase + s * STAGE_B;
#pragma unroll
        for (int it = 0; it < 4; it++) {
            int r = lr + it * 32;
            uint32_t so = (uint32_t)(r * SROW + lc8) * 2;
            size_t ga = (size_t)(bm + r) * K + k0g + lc8;
            size_t gb = (size_t)(bn + r) * K + k0g + lc8;
            cp16(st + 0 * TILE_B + so, Ah + ga);
            cp16(st + 1 * TILE_B + so, Bh + gb);
            cp16(st + 2 * TILE_B + so, Bl + gb);
        }
        CP_COMMIT();
    };

    const int a_row  = lane & 15;
    const int a_koff = (lane >> 4) << 3;
    const int b_row  = lane & 7;
    const int b_koff = ((lane >> 3) & 1) << 3;
    const int jsel8  = (lane >> 4) << 3;

    float acc[4][4][4];
#pragma unroll
    for (int i = 0; i < 4; i++)
#pragma unroll
        for (int j = 0; j < 4; j++)
#pragma unroll
            for (int t = 0; t < 4; t++) acc[i][j][t] = 0.f;

    const int nchunks = K / BK;
    issue(0, 0);
    for (int ch = 0; ch < nchunks; ch++) {
        const int s = ch & 1;
        if (ch + 1 < nchunks) { issue(ch + 1, 1 - s); CP_WAIT(1); }
        else                  { CP_WAIT(0); }
        __syncthreads();

        const uint32_t uAh = sbase + s * STAGE_B;
        const uint32_t uBh = uAh + TILE_B;
        const uint32_t uBl = uAh + 2 * TILE_B;
#pragma unroll
        for (int ks = 0; ks < 4; ks++) {
            const int k0 = ks * 16;
            uint32_t ah[4][4], bh[2][4], bl[2][4];
#pragma unroll
            for (int i = 0; i < 4; i++) {
                uint32_t off = (uint32_t)((wm + i * 16 + a_row) * SROW + k0 + a_koff) * 2;
                ldsm_x4(ah[i], uAh + off);
            }
#pragma unroll
            for (int jp = 0; jp < 2; jp++) {
                uint32_t off = (uint32_t)((wn + jp * 16 + jsel8 + b_row) * SROW + k0 + b_koff) * 2;
                ldsm_x4(bh[jp], uBh + off);
                ldsm_x4(bl[jp], uBl + off);
            }
#pragma unroll
            for (int i = 0; i < 4; i++)
#pragma unroll
                for (int jp = 0; jp < 2; jp++)
#pragma unroll
                    for (int u = 0; u < 2; u++) {
                        mma16816(acc[i][2 * jp + u], ah[i], bh[jp] + 2 * u);
                        mma16816(acc[i][2 * jp + u], ah[i], bl[jp] + 2 * u);
                    }
        }
        __syncthreads();
    }

    const int gr = lane >> 2;
    const int gc = (lane & 3) << 1;
#pragma unroll
    for (int i = 0; i < 4; i++) {
#pragma unroll
        for (int j = 0; j < 4; j++) {
            size_t r0 = (size_t)(bm + wm + i * 16 + gr) * N + bn + wn + j * 8 + gc;
            size_t r1 = r0 + (size_t)8 * N;
            *(float2*)(C + r0) = make_float2(acc[i][j][0], acc[i][j][1]);
            *(float2*)(C + r1) = make_float2(acc[i][j][2], acc[i][j][3]);
        }
    }
}

// ---------------------------------------------------------------------------
// Tensor-core causal flash attention (fp16 2-product via mma.sync),
// 2-stage cp.async K/V pipeline, 2 CTAs/SM, heavy-tiles-first, x4 B loads.
// ---------------------------------------------------------------------------
#define FSROW 72
#define KVARR_B (64 * FSROW * 2)                 // 9216 bytes per array
#define KVSTAGE_B (4 * KVARR_B)                  // 36864 per stage
#define FSMEM (128 * FSROW * 2 + 2 * KVSTAGE_B)  // 92160 bytes

__global__ __launch_bounds__(256, 2)
void flash_mma_kernel(const __half* __restrict__ Qh,
                      const __half* __restrict__ Kh, const __half* __restrict__ Kl,
                      const __half* __restrict__ Vh, const __half* __restrict__ Vl,
                      __half* __restrict__ Oh)
{
    extern __shared__ char fsm[];
    char* sQh = fsm;                                   // [128][FSROW] fp16
    const uint32_t uQh = smem_to_u32(sQh);
    const uint32_t uKV = uQh + 128 * FSROW * 2;        // 2 stages of K/V hi/lo

    const int tid  = threadIdx.x;
    const int warp = tid >> 5;
    const int lane = tid & 31;
    const int qi = (int)(gridDim.x - 1) - (int)blockIdx.x;   // heavy-first (LPT)
    const int bh_ = blockIdx.y;                // b*16+h
    const int b = bh_ >> 4, h = bh_ & 15;
    const int q0 = qi << 7;
    const int wm = warp << 4;

    const size_t base = (size_t)b * SEQ * D_MODEL + (size_t)h * HEAD_DIM;
    const __half* kvsrc[4] = { Kh + base, Kl + base, Vh + base, Vl + base };

    auto issueKV = [&](int kt, int s) {
        const uint32_t st = uKV + s * KVSTAGE_B;
#pragma unroll
        for (int it = 0; it < 8; it++) {
            int lin = tid + it * 256;
            int arr = lin >> 9;
            int idx = lin & 511;
            int r   = idx >> 3;
            int c8  = (idx & 7) << 3;
            cp16(st + arr * KVARR_B + (uint32_t)(r * FSROW + c8) * 2,
                 kvsrc[arr] + (size_t)((kt << 6) + r) * D_MODEL + c8);
        }
        CP_COMMIT();
    };

    // ---- load Q tile + prefetch KV tile 0 ----
#pragma unroll
    for (int it = 0; it < 4; it++) {
        int lin = tid + it * 256;
        int r   = lin >> 3;
        int c8  = (lin & 7) << 3;
        uint4 t = *(const uint4*)(Qh + base + (size_t)(q0 + r) * D_MODEL + c8);
        char* d = sQh + (r * FSROW + c8) * 2;
        *(uint2*)(d)     = make_uint2(t.x, t.y);
        *(uint2*)(d + 8) = make_uint2(t.z, t.w);
    }
    issueKV(0, 0);
    __syncthreads();

    uint32_t qh[4][4];
    {
        const int ar = lane & 15;
        const int ak = (lane >> 4) << 3;
#pragma unroll
        for (int ks = 0; ks < 4; ks++) {
            uint32_t off = (uint32_t)((wm + ar) * FSROW + ks * 16 + ak) * 2;
            ldsm_x4(qh[ks], uQh + off);
        }
    }

    const float NEG = -1e30f;
    const float CSC = 0.125f * 1.4426950408889634f;
    float m0 = NEG, m1 = NEG, l0 = 0.f, l1 = 0.f;
    float ov[8][4];
#pragma unroll
    for (int j = 0; j < 8; j++)
#pragma unroll
        for (int t = 0; t < 4; t++) ov[j][t] = 0.f;

    const int r0g = q0 + wm + (lane >> 2);
    const int r1g = r0g + 8;
    const int br  = lane & 7;
    const int bk  = ((lane >> 3) & 1) << 3;
    const int vr  = lane & 15;
    const int jsel8 = (lane >> 4) << 3;        // pair-select for x4 loads

    const int kend = 2 * qi + 2;
    for (int kt = 0; kt < kend; kt++) {
        const int s = kt & 1;
        if (kt + 1 < kend) { issueKV(kt + 1, 1 - s); CP_WAIT(1); }
        else               { CP_WAIT(0); }
        __syncthreads();

        const uint32_t uKh = uKV + s * KVSTAGE_B;
        const uint32_t uKl = uKh + KVARR_B;
        const uint32_t uVh = uKh + 2 * KVARR_B;
        const uint32_t uVl = uKh + 3 * KVARR_B;

        // ---- S = Q K^T (paired x4 K loads: frag j = r0..1, frag j+1 = r2..3) ----
        float sreg[8][4];
#pragma unroll
        for (int j = 0; j < 8; j++)
#pragma unroll
            for (int t = 0; t < 4; t++) sreg[j][t] = 0.f;

#pragma unroll
        for (int jp = 0; jp < 4; jp++) {
#pragma unroll
            for (int ks = 0; ks < 4; ks++) {
                uint32_t kbh[4], kbl[4];
                uint32_t off = (uint32_t)((jp * 16 + jsel8 + br) * FSROW + ks * 16 + bk) * 2;
                ldsm_x4(kbh, uKh + off);
                ldsm_x4(kbl, uKl + off);
                mma16816(sreg[2 * jp],     qh[ks], kbh);
                mma16816(sreg[2 * jp],     qh[ks], kbl);
                mma16816(sreg[2 * jp + 1], qh[ks], kbh + 2);
                mma16816(sreg[2 * jp + 1], qh[ks], kbl + 2);
            }
        }

        const bool diag = (kt >= 2 * qi);
#pragma unroll
        for (int j = 0; j < 8; j++) {
            sreg[j][0] *= CSC; sreg[j][1] *= CSC; sreg[j][2] *= CSC; sreg[j][3] *= CSC;
            if (diag) {
                int cb = (kt << 6) + j * 8 + ((lane & 3) << 1);
                if (cb     > r0g) sreg[j][0] = NEG;
                if (cb + 1 > r0g) sreg[j][1] = NEG;
                if (cb     > r1g) sreg[j][2] = NEG;
                if (cb + 1 > r1g) sreg[j][3] = NEG;
            }
        }

        float rm0 = NEG, rm1 = NEG;
#pragma unroll
        for (int j = 0; j < 8; j++) {
            rm0 = fmaxf(rm0, fmaxf(sreg[j][0], sreg[j][1]));
            rm1 = fmaxf(rm1, fmaxf(sreg[j][2], sreg[j][3]));
        }
        rm0 = fmaxf(rm0, __shfl_xor_sync(0xffffffffu, rm0, 1));
        rm0 = fmaxf(rm0, __shfl_xor_sync(0xffffffffu, rm0, 2));
        rm1 = fmaxf(rm1, __shfl_xor_sync(0xffffffffu, rm1, 1));
        rm1 = fmaxf(rm1, __shfl_xor_sync(0xffffffffu, rm1, 2));

        float mn0 = fmaxf(m0, rm0);
        float mn1 = fmaxf(m1, rm1);
        float sc0 = fast_exp2(m0 - mn0);
        float sc1 = fast_exp2(m1 - mn1);
        m0 = mn0; m1 = mn1;
#pragma unroll
        for (int j = 0; j < 8; j++) {
            ov[j][0] *= sc0; ov[j][1] *= sc0;
            ov[j][2] *= sc1; ov[j][3] *= sc1;
        }

        // ---- exp, pack P, P·V (paired x4 trans V loads) ----
        float rs0 = 0.f, rs1 = 0.f;
#pragma unroll
        for (int kk = 0; kk < 4; kk++) {
            uint32_t pah[4];
#pragma unroll
            for (int u = 0; u < 2; u++) {
                int t = 2 * kk + u;
                float p0 = fast_exp2(sreg[t][0] - mn0);
                float p1 = fast_exp2(sreg[t][1] - mn0);
                float p2 = fast_exp2(sreg[t][2] - mn1);
                float p3 = fast_exp2(sreg[t][3] - mn1);
                rs0 += p0 + p1;
                rs1 += p2 + p3;
                pah[2 * u]     = pack_hf2(p0, p1);
                pah[2 * u + 1] = pack_hf2(p2, p3);
            }
#pragma unroll
            for (int jvp = 0; jvp < 4; jvp++) {
                uint32_t vbh[4], vbl[4];
                uint32_t off = (uint32_t)((kk * 16 + vr) * FSROW + jvp * 16 + jsel8) * 2;
                ldsm_x4_t(vbh, uVh + off);
                ldsm_x4_t(vbl, uVl + off);
                mma16816(ov[2 * jvp],     pah, vbh);
                mma16816(ov[2 * jvp],     pah, vbl);
                mma16816(ov[2 * jvp + 1], pah, vbh + 2);
                mma16816(ov[2 * jvp + 1], pah, vbl + 2);
            }
        }
        rs0 += __shfl_xor_sync(0xffffffffu, rs0, 1);
        rs0 += __shfl_xor_sync(0xffffffffu, rs0, 2);
        rs1 += __shfl_xor_sync(0xffffffffu, rs1, 1);
        rs1 += __shfl_xor_sync(0xffffffffu, rs1, 2);
        l0 = l0 * sc0 + rs0;
        l1 = l1 * sc1 + rs1;

        __syncthreads();
    }

    float rinv0 = 1.0f / l0;
    float rinv1 = 1.0f / l1;
    size_t orow0 = base + (size_t)(q0 + wm + (lane >> 2)) * D_MODEL;
    size_t orow1 = orow0 + (size_t)8 * D_MODEL;
    int colb = ((lane & 3) << 1);
#pragma unroll
    for (int jv = 0; jv < 8; jv++) {
        int c = jv * 8 + colb;
        *(uint32_t*)(Oh + orow0 + c) = pack_hf2(ov[jv][0] * rinv0, ov[jv][1] * rinv0);
        *(uint32_t*)(Oh + orow1 + c) = pack_hf2(ov[jv][2] * rinv1, ov[jv][3] * rinv1);
    }
}

// ---------------------------------------------------------------------------
// Launch
// ---------------------------------------------------------------------------
extern "C" void kernel_launch(void* const* d_in, const int* in_sizes, int n_in,
                              void* d_out, int out_size)
{
    const float* x   = (const float*)d_in[0];
    const float* W_q = (const float*)d_in[1];
    const float* W_k = (const float*)d_in[2];
    const float* W_v = (const float*)d_in[3];
    const float* W_o = (const float*)d_in[4];
    float* out = (float*)d_out;

    __half *pxh, *pqh, *pkh, *pkl, *pvh, *pvl, *pch, *pwh, *pwl;
    cudaGetSymbolAddress((void**)&pxh, g_xh);
    cudaGetSymbolAddress((void**)&pqh, g_qh);
    cudaGetSymbolAddress((void**)&pkh, g_kh);
    cudaGetSymbolAddress((void**)&pkl, g_kl);
    cudaGetSymbolAddress((void**)&pvh, g_vh);
    cudaGetSymbolAddress((void**)&pvl, g_vl);
    cudaGetSymbolAddress((void**)&pch, g_ch);
    cudaGetSymbolAddress((void**)&pwh, g_wh);
    cudaGetSymbolAddress((void**)&pwl, g_wl);

    cudaFuncSetAttribute(mma_gemm_qkv_kernel,
                         cudaFuncAttributeMaxDynamicSharedMemorySize, SMEM_GEMM);
    cudaFuncSetAttribute(mma_gemm_kernel,
                         cudaFuncAttributeMaxDynamicSharedMemorySize, SMEM_GEMM);
    cudaFuncSetAttribute(flash_mma_kernel,
                         cudaFuncAttributeMaxDynamicSharedMemorySize, FSMEM);

    const size_t WSZ = (size_t)D_MODEL * D_MODEL;   // 1048576
    const int nx4 = (int)((size_t)M_TOTAL * D_MODEL / 4);
    const int nw4 = (int)(WSZ / 4);

    // x: hi only; all 4 weights: hi/lo in one launch
    split_hi_kernel<<<(nx4 + 255) / 256, 256>>>(x, pxh, nx4);
    dim3 gSplitW((nw4 + 255) / 256, 4);
    split_w_kernel<<<gSplitW, 256>>>(W_q, W_k, W_v, W_o, pwh, pwl, nw4);

    // fused Q/K/V projection: N = 3072 over concatenated weights
    dim3 gQKV(3 * D_MODEL / 128, M_TOTAL / 128);    // (24, 64)
    mma_gemm_qkv_kernel<<<gQKV, 256, SMEM_GEMM>>>(pxh, pwh, pwl,
                                                  pqh, pkh, pkl, pvh, pvl);

    dim3 gFlash(SEQ / 128, BATCH * N_HEADS);        // (16, 64)
    flash_mma_kernel<<<gFlash, 256, FSMEM>>>(pqh, pkh, pkl, pvh, pvl, pch);

    // O projection: fp32 output
    dim3 gGemm(D_MODEL / 128, M_TOTAL / 128);       // (8, 64)
    mma_gemm_kernel<<<gGemm, 256, SMEM_GEMM>>>(pch, pwh + 3 * WSZ, pwl + 3 * WSZ,
                                               out, M_TOTAL, D_MODEL, D_MODEL);
}

// round 15
// speedup vs baseline: 5.6755x; 1.2077x over previous
#include <cuda_runtime.h>
#include <cuda_fp16.h>
#include <cstdint>
#include <cstddef>

#define D_MODEL  1024
#define N_HEADS  16
#define HEAD_DIM 64
#define BATCH    4
#define SEQ      2048
#define M_TOTAL  (BATCH * SEQ)   // 8192

// ---------------------------------------------------------------------------
// Scratch (no cudaMalloc allowed) — fp16 split buffers
// ---------------------------------------------------------------------------
__device__ __half g_xh[(size_t)M_TOTAL * D_MODEL];
__device__ __half g_qh[(size_t)M_TOTAL * D_MODEL];
__device__ __half g_kh[(size_t)M_TOTAL * D_MODEL];
__device__ __half g_vh[(size_t)M_TOTAL * D_MODEL];
__device__ __half g_ch[(size_t)M_TOTAL * D_MODEL];
__device__ __half g_wh[(size_t)4 * D_MODEL * D_MODEL];
__device__ __half g_wl[(size_t)4 * D_MODEL * D_MODEL];

// ---------------------------------------------------------------------------
// Baseline-PTX helpers (sm_80-class; compile under compute_103)
// ---------------------------------------------------------------------------
__device__ __forceinline__ uint32_t smem_to_u32(const void* p) {
    uint32_t a;
    asm("{ .reg .u64 t; cvta.to.shared.u64 t, %1; cvt.u32.u64 %0, t; }" : "=r"(a) : "l"(p));
    return a;
}
__device__ __forceinline__ void ldsm_x4(uint32_t* r, uint32_t addr) {
    asm volatile("ldmatrix.sync.aligned.m8n8.x4.shared.b16 {%0,%1,%2,%3}, [%4];"
        : "=r"(r[0]), "=r"(r[1]), "=r"(r[2]), "=r"(r[3]) : "r"(addr));
}
__device__ __forceinline__ void ldsm_x4_t(uint32_t* r, uint32_t addr) {
    asm volatile("ldmatrix.sync.aligned.m8n8.x4.trans.shared.b16 {%0,%1,%2,%3}, [%4];"
        : "=r"(r[0]), "=r"(r[1]), "=r"(r[2]), "=r"(r[3]) : "r"(addr));
}
// D += A(f16) * B(f16), m16n8k16, row.col, f32 accum
__device__ __forceinline__ void mma16816(float* d, const uint32_t* a, const uint32_t* b) {
    asm volatile(
        "mma.sync.aligned.m16n8k16.row.col.f32.f16.f16.f32 "
        "{%0,%1,%2,%3}, {%4,%5,%6,%7}, {%8,%9}, {%0,%1,%2,%3};"
        : "+f"(d[0]), "+f"(d[1]), "+f"(d[2]), "+f"(d[3])
        : "r"(a[0]), "r"(a[1]), "r"(a[2]), "r"(a[3]), "r"(b[0]), "r"(b[1]));
}
__device__ __forceinline__ void cp16(uint32_t smem, const void* g) {
    asm volatile("cp.async.cg.shared.global [%0], [%1], 16;" :: "r"(smem), "l"(g));
}
#define CP_COMMIT() asm volatile("cp.async.commit_group;" ::: "memory")
#define CP_WAIT(n)  asm volatile("cp.async.wait_group %0;" :: "n"(n) : "memory")

__device__ __forceinline__ float fast_exp2(float x) {
    float y;
    asm("ex2.approx.ftz.f32 %0, %1;" : "=f"(y) : "f"(x));
    return y;
}
__device__ __forceinline__ uint32_t pack_hf2(float a, float b) {
    __half2 h = __floats2half2_rn(a, b);
    return reinterpret_cast<uint32_t&>(h);
}
__device__ __forceinline__ uint32_t pack_hf2_hi(float a, float b, float& ra, float& rb) {
    __half2 h = __floats2half2_rn(a, b);
    float2 f = __half22float2(h);
    ra = a - f.x;
    rb = b - f.y;
    return reinterpret_cast<uint32_t&>(h);
}

// ---------------------------------------------------------------------------
// fp32 -> fp16 splits
// ---------------------------------------------------------------------------
__global__ __launch_bounds__(256)
void split_w_kernel(const float* __restrict__ W0, const float* __restrict__ W1,
                    const float* __restrict__ W2, const float* __restrict__ W3,
                    __half* __restrict__ hi, __half* __restrict__ lo, int n4)
{
    int i = blockIdx.x * 256 + threadIdx.x;
    if (i >= n4) return;
    int w = blockIdx.y;
    const float* src = (w == 0) ? W0 : (w == 1) ? W1 : (w == 2) ? W2 : W3;
    size_t o = (size_t)w * n4 + i;            // float4-unit offset into concat
    float4 v = ((const float4*)src)[i];
    float rx, ry, rz, rw;
    uint32_t h0 = pack_hf2_hi(v.x, v.y, rx, ry);
    uint32_t h1 = pack_hf2_hi(v.z, v.w, rz, rw);
    ((uint32_t*)hi)[2 * o]     = h0;
    ((uint32_t*)hi)[2 * o + 1] = h1;
    ((uint32_t*)lo)[2 * o]     = pack_hf2(rx, ry);
    ((uint32_t*)lo)[2 * o + 1] = pack_hf2(rz, rw);
}

__global__ __launch_bounds__(256)
void split_hi_kernel(const float* __restrict__ x, __half* __restrict__ hi, int n4)
{
    int i = blockIdx.x * 256 + threadIdx.x;
    if (i >= n4) return;
    float4 v = ((const float4*)x)[i];
    ((uint32_t*)hi)[2 * i]     = pack_hf2(v.x, v.y);
    ((uint32_t*)hi)[2 * i + 1] = pack_hf2(v.z, v.w);
}

// ---------------------------------------------------------------------------
// Shared GEMM constants (fp16 2-product, 2-stage cp.async, 2 CTAs/SM)
// ---------------------------------------------------------------------------
#define BK 64
#define SROW 72                              // padded row, fp16 elements (144B)
#define TILE_B (128 * SROW * 2)              // 18432 bytes per tile
#define STAGE_B (3 * TILE_B)                 // 55296 per stage (Ah, Bh, Bl)
#define SMEM_GEMM (2 * STAGE_B)              // 110592 bytes

// ---------------------------------------------------------------------------
// Fused Q/K/V projection GEMM: A = x (8192x1024 fp16-hi),
// B = concat(Wq,Wk,Wv) (3072x1024 hi/lo). Epilogue: fp16-hi out, routed by seg.
// ---------------------------------------------------------------------------
__global__ __launch_bounds__(256, 2)
void mma_gemm_qkv_kernel(const __half* __restrict__ Ah,
                         const __half* __restrict__ Bh, const __half* __restrict__ Bl,
                         __half* __restrict__ Qh,
                         __half* __restrict__ Kh, __half* __restrict__ Vh)
{
    extern __shared__ char smem[];
    const int tid  = threadIdx.x;
    const int warp = tid >> 5;
    const int lane = tid & 31;
    const int bm = blockIdx.y * 128;
    const int bn = blockIdx.x * 128;          // 0..2944 over concat N=3072
    const int wm = (warp >> 2) * 64;
    const int wn = (warp & 3) * 32;
    const int K = D_MODEL;

    const uint32_t sbase = smem_to_u32(smem);
    const int lr  = tid >> 3;
    const int lc8 = (tid & 7) << 3;

    auto issue = [&](int ch, int s) {
        const int k0g = ch * BK;
        const uint32_t st = sbase + s * STAGE_B;
#pragma unroll
        for (int it = 0; it < 4; it++) {
            int r = lr + it * 32;
            uint32_t so = (uint32_t)(r * SROW + lc8) * 2;
            size_t ga = (size_t)(bm + r) * K + k0g + lc8;
            size_t gb = (size_t)(bn + r) * K + k0g + lc8;
            cp16(st + 0 * TILE_B + so, Ah + ga);
            cp16(st + 1 * TILE_B + so, Bh + gb);
            cp16(st + 2 * TILE_B + so, Bl + gb);
        }
        CP_COMMIT();
    };

    const int a_row  = lane & 15;
    const int a_koff = (lane >> 4) << 3;
    const int b_row  = lane & 7;
    const int b_koff = ((lane >> 3) & 1) << 3;
    const int jsel8  = (lane >> 4) << 3;      // pair-select for x4 B loads

    float acc[4][4][4];
#pragma unroll
    for (int i = 0; i < 4; i++)
#pragma unroll
        for (int j = 0; j < 4; j++)
#pragma unroll
            for (int t = 0; t < 4; t++) acc[i][j][t] = 0.f;

    const int nchunks = K / BK;
    issue(0, 0);
    for (int ch = 0; ch < nchunks; ch++) {
        const int s = ch & 1;
        if (ch + 1 < nchunks) { issue(ch + 1, 1 - s); CP_WAIT(1); }
        else                  { CP_WAIT(0); }
        __syncthreads();

        const uint32_t uAh = sbase + s * STAGE_B;
        const uint32_t uBh = uAh + TILE_B;
        const uint32_t uBl = uAh + 2 * TILE_B;
#pragma unroll
        for (int ks = 0; ks < 4; ks++) {
            const int k0 = ks * 16;
            uint32_t ah[4][4], bh[2][4], bl[2][4];
#pragma unroll
            for (int i = 0; i < 4; i++) {
                uint32_t off = (uint32_t)((wm + i * 16 + a_row) * SROW + k0 + a_koff) * 2;
                ldsm_x4(ah[i], uAh + off);
            }
#pragma unroll
            for (int jp = 0; jp < 2; jp++) {   // pair (2jp, 2jp+1)
                uint32_t off = (uint32_t)((wn + jp * 16 + jsel8 + b_row) * SROW + k0 + b_koff) * 2;
                ldsm_x4(bh[jp], uBh + off);
                ldsm_x4(bl[jp], uBl + off);
            }
#pragma unroll
            for (int i = 0; i < 4; i++)
#pragma unroll
                for (int jp = 0; jp < 2; jp++)
#pragma unroll
                    for (int u = 0; u < 2; u++) {
                        mma16816(acc[i][2 * jp + u], ah[i], bh[jp] + 2 * u);
                        mma16816(acc[i][2 * jp + u], ah[i], bl[jp] + 2 * u);
                    }
        }
        __syncthreads();
    }

    // epilogue: fp16-hi output, routed by segment of the concatenated N
    const int seg = bn >> 10;                 // 0=Q, 1=K, 2=V
    const int cn  = bn & 1023;
    __half* Chi = (seg == 0) ? Qh : (seg == 1) ? Kh : Vh;

    const int gr = lane >> 2;
    const int gc = (lane & 3) << 1;
#pragma unroll
    for (int i = 0; i < 4; i++) {
#pragma unroll
        for (int j = 0; j < 4; j++) {
            size_t r0 = (size_t)(bm + wm + i * 16 + gr) * D_MODEL + cn + wn + j * 8 + gc;
            size_t r1 = r0 + (size_t)8 * D_MODEL;
            *(uint32_t*)(Chi + r0) = pack_hf2(acc[i][j][0], acc[i][j][1]);
            *(uint32_t*)(Chi + r1) = pack_hf2(acc[i][j][2], acc[i][j][3]);
        }
    }
}

// ---------------------------------------------------------------------------
// O-projection GEMM (fp32 output), same mainloop.
// ---------------------------------------------------------------------------
__global__ __launch_bounds__(256, 2)
void mma_gemm_kernel(const __half* __restrict__ Ah,
                     const __half* __restrict__ Bh, const __half* __restrict__ Bl,
                     float* __restrict__ C, int M, int N, int K)
{
    extern __shared__ char smem[];
    const int tid  = threadIdx.x;
    const int warp = tid >> 5;
    const int lane = tid & 31;
    const int bm = blockIdx.y * 128;
    const int bn = blockIdx.x * 128;
    const int wm = (warp >> 2) * 64;
    const int wn = (warp & 3) * 32;

    const uint32_t sbase = smem_to_u32(smem);
    const int lr  = tid >> 3;
    const int lc8 = (tid & 7) << 3;

    auto issue = [&](int ch, int s) {
        const int k0g = ch * BK;
        const uint32_t st = sbase + s * STAGE_B;
#pragma unroll
        for (int it = 0; it < 4; it++) {
            int r = lr + it * 32;
            uint32_t so = (uint32_t)(r * SROW + lc8) * 2;
            size_t ga = (size_t)(bm + r) * K + k0g + lc8;
            size_t gb = (size_t)(bn + r) * K + k0g + lc8;
            cp16(st + 0 * TILE_B + so, Ah + ga);
            cp16(st + 1 * TILE_B + so, Bh + gb);
            cp16(st + 2 * TILE_B + so, Bl + gb);
        }
        CP_COMMIT();
    };

    const int a_row  = lane & 15;
    const int a_koff = (lane >> 4) << 3;
    const int b_row  = lane & 7;
    const int b_koff = ((lane >> 3) & 1) << 3;
    const int jsel8  = (lane >> 4) << 3;

    float acc[4][4][4];
#pragma unroll
    for (int i = 0; i < 4; i++)
#pragma unroll
        for (int j = 0; j < 4; j++)
#pragma unroll
            for (int t = 0; t < 4; t++) acc[i][j][t] = 0.f;

    const int nchunks = K / BK;
    issue(0, 0);
    for (int ch = 0; ch < nchunks; ch++) {
        const int s = ch & 1;
        if (ch + 1 < nchunks) { issue(ch + 1, 1 - s); CP_WAIT(1); }
        else                  { CP_WAIT(0); }
        __syncthreads();

        const uint32_t uAh = sbase + s * STAGE_B;
        const uint32_t uBh = uAh + TILE_B;
        const uint32_t uBl = uAh + 2 * TILE_B;
#pragma unroll
        for (int ks = 0; ks < 4; ks++) {
            const int k0 = ks * 16;
            uint32_t ah[4][4], bh[2][4], bl[2][4];
#pragma unroll
            for (int i = 0; i < 4; i++) {
                uint32_t off = (uint32_t)((wm + i * 16 + a_row) * SROW + k0 + a_koff) * 2;
                ldsm_x4(ah[i], uAh + off);
            }
#pragma unroll
            for (int jp = 0; jp < 2; jp++) {
                uint32_t off = (uint32_t)((wn + jp * 16 + jsel8 + b_row) * SROW + k0 + b_koff) * 2;
                ldsm_x4(bh[jp], uBh + off);
                ldsm_x4(bl[jp], uBl + off);
            }
#pragma unroll
            for (int i = 0; i < 4; i++)
#pragma unroll
                for (int jp = 0; jp < 2; jp++)
#pragma unroll
                    for (int u = 0; u < 2; u++) {
                        mma16816(acc[i][2 * jp + u], ah[i], bh[jp] + 2 * u);
                        mma16816(acc[i][2 * jp + u], ah[i], bl[jp] + 2 * u);
                    }
        }
        __syncthreads();
    }

    const int gr = lane >> 2;
    const int gc = (lane & 3) << 1;
#pragma unroll
    for (int i = 0; i < 4; i++) {
#pragma unroll
        for (int j = 0; j < 4; j++) {
            size_t r0 = (size_t)(bm + wm + i * 16 + gr) * N + bn + wn + j * 8 + gc;
            size_t r1 = r0 + (size_t)8 * N;
            *(float2*)(C + r0) = make_float2(acc[i][j][0], acc[i][j][1]);
            *(float2*)(C + r1) = make_float2(acc[i][j][2], acc[i][j][3]);
        }
    }
}

// ---------------------------------------------------------------------------
// Tensor-core causal flash attention (pure fp16 via mma.sync),
// 2-stage cp.async K/V pipeline, 2 CTAs/SM, heavy-tiles-first, x4 loads.
// Q, K, V all fp16-hi. Output concat fp16-hi.
// ---------------------------------------------------------------------------
#define FSROW 72
#define KVARR_B (64 * FSROW * 2)                 // 9216 bytes per array
#define KVSTAGE_B (2 * KVARR_B)                  // 18432 per stage (K, V)
#define FSMEM (128 * FSROW * 2 + 2 * KVSTAGE_B)  // 55296 bytes

__global__ __launch_bounds__(256, 2)
void flash_mma_kernel(const __half* __restrict__ Qh,
                      const __half* __restrict__ Kh,
                      const __half* __restrict__ Vh,
                      __half* __restrict__ Oh)
{
    extern __shared__ char fsm[];
    char* sQh = fsm;                                   // [128][FSROW] fp16
    const uint32_t uQh = smem_to_u32(sQh);
    const uint32_t uKV = uQh + 128 * FSROW * 2;        // 2 stages of {K, V}

    const int tid  = threadIdx.x;
    const int warp = tid >> 5;
    const int lane = tid & 31;
    const int qi = (int)(gridDim.x - 1) - (int)blockIdx.x;   // heavy-first (LPT)
    const int bh_ = blockIdx.y;                // b*16+h
    const int b = bh_ >> 4, h = bh_ & 15;
    const int q0 = qi << 7;
    const int wm = warp << 4;

    const size_t base = (size_t)b * SEQ * D_MODEL + (size_t)h * HEAD_DIM;
    const __half* kvsrc[2] = { Kh + base, Vh + base };

    auto issueKV = [&](int kt, int s) {
        const uint32_t st = uKV + s * KVSTAGE_B;
#pragma unroll
        for (int it = 0; it < 4; it++) {
            int lin = tid + it * 256;          // 0..1023
            int arr = lin >> 9;                // 0..1
            int idx = lin & 511;
            int r   = idx >> 3;
            int c8  = (idx & 7) << 3;
            cp16(st + arr * KVARR_B + (uint32_t)(r * FSROW + c8) * 2,
                 kvsrc[arr] + (size_t)((kt << 6) + r) * D_MODEL + c8);
        }
        CP_COMMIT();
    };

    // ---- load Q tile + prefetch KV tile 0 ----
#pragma unroll
    for (int it = 0; it < 4; it++) {
        int lin = tid + it * 256;
        int r   = lin >> 3;
        int c8  = (lin & 7) << 3;
        uint4 t = *(const uint4*)(Qh + base + (size_t)(q0 + r) * D_MODEL + c8);
        char* d = sQh + (r * FSROW + c8) * 2;
        *(uint2*)(d)     = make_uint2(t.x, t.y);
        *(uint2*)(d + 8) = make_uint2(t.z, t.w);
    }
    issueKV(0, 0);
    __syncthreads();

    uint32_t qh[4][4];
    {
        const int ar = lane & 15;
        const int ak = (lane >> 4) << 3;
#pragma unroll
        for (int ks = 0; ks < 4; ks++) {
            uint32_t off = (uint32_t)((wm + ar) * FSROW + ks * 16 + ak) * 2;
            ldsm_x4(qh[ks], uQh + off);
        }
    }

    const float NEG = -1e30f;
    const float CSC = 0.125f * 1.4426950408889634f;
    float m0 = NEG, m1 = NEG, l0 = 0.f, l1 = 0.f;
    float ov[8][4];
#pragma unroll
    for (int j = 0; j < 8; j++)
#pragma unroll
        for (int t = 0; t < 4; t++) ov[j][t] = 0.f;

    const int r0g = q0 + wm + (lane >> 2);
    const int r1g = r0g + 8;
    const int br  = lane & 7;
    const int bk  = ((lane >> 3) & 1) << 3;
    const int vr  = lane & 15;
    const int jsel8 = (lane >> 4) << 3;        // pair-select for x4 loads

    const int kend = 2 * qi + 2;
    for (int kt = 0; kt < kend; kt++) {
        const int s = kt & 1;
        if (kt + 1 < kend) { issueKV(kt + 1, 1 - s); CP_WAIT(1); }
        else               { CP_WAIT(0); }
        __syncthreads();

        const uint32_t uKs = uKV + s * KVSTAGE_B;
        const uint32_t uVs = uKs + KVARR_B;

        // ---- S = Q K^T (paired x4 K loads) ----
        float sreg[8][4];
#pragma unroll
        for (int j = 0; j < 8; j++)
#pragma unroll
            for (int t = 0; t < 4; t++) sreg[j][t] = 0.f;

#pragma unroll
        for (int jp = 0; jp < 4; jp++) {
#pragma unroll
            for (int ks = 0; ks < 4; ks++) {
                uint32_t kbh[4];
                uint32_t off = (uint32_t)((jp * 16 + jsel8 + br) * FSROW + ks * 16 + bk) * 2;
                ldsm_x4(kbh, uKs + off);
                mma16816(sreg[2 * jp],     qh[ks], kbh);
                mma16816(sreg[2 * jp + 1], qh[ks], kbh + 2);
            }
        }

        const bool diag = (kt >= 2 * qi);
#pragma unroll
        for (int j = 0; j < 8; j++) {
            sreg[j][0] *= CSC; sreg[j][1] *= CSC; sreg[j][2] *= CSC; sreg[j][3] *= CSC;
            if (diag) {
                int cb = (kt << 6) + j * 8 + ((lane & 3) << 1);
                if (cb     > r0g) sreg[j][0] = NEG;
                if (cb + 1 > r0g) sreg[j][1] = NEG;
                if (cb     > r1g) sreg[j][2] = NEG;
                if (cb + 1 > r1g) sreg[j][3] = NEG;
            }
        }

        float rm0 = NEG, rm1 = NEG;
#pragma unroll
        for (int j = 0; j < 8; j++) {
            rm0 = fmaxf(rm0, fmaxf(sreg[j][0], sreg[j][1]));
            rm1 = fmaxf(rm1, fmaxf(sreg[j][2], sreg[j][3]));
        }
        rm0 = fmaxf(rm0, __shfl_xor_sync(0xffffffffu, rm0, 1));
        rm0 = fmaxf(rm0, __shfl_xor_sync(0xffffffffu, rm0, 2));
        rm1 = fmaxf(rm1, __shfl_xor_sync(0xffffffffu, rm1, 1));
        rm1 = fmaxf(rm1, __shfl_xor_sync(0xffffffffu, rm1, 2));

        float mn0 = fmaxf(m0, rm0);
        float mn1 = fmaxf(m1, rm1);
        float sc0 = fast_exp2(m0 - mn0);
        float sc1 = fast_exp2(m1 - mn1);
        m0 = mn0; m1 = mn1;
#pragma unroll
        for (int j = 0; j < 8; j++) {
            ov[j][0] *= sc0; ov[j][1] *= sc0;
            ov[j][2] *= sc1; ov[j][3] *= sc1;
        }

        // ---- exp, pack P, P·V (paired x4 trans V loads) ----
        float rs0 = 0.f, rs1 = 0.f;
#pragma unroll
        for (int kk = 0; kk < 4; kk++) {
            uint32_t pah[4];
#pragma unroll
            for (int u = 0; u < 2; u++) {
                int t = 2 * kk + u;
                float p0 = fast_exp2(sreg[t][0] - mn0);
                float p1 = fast_exp2(sreg[t][1] - mn0);
                float p2 = fast_exp2(sreg[t][2] - mn1);
                float p3 = fast_exp2(sreg[t][3] - mn1);
                rs0 += p0 + p1;
                rs1 += p2 + p3;
                pah[2 * u]     = pack_hf2(p0, p1);
                pah[2 * u + 1] = pack_hf2(p2, p3);
            }
#pragma unroll
            for (int jvp = 0; jvp < 4; jvp++) {
                uint32_t vbh[4];
                uint32_t off = (uint32_t)((kk * 16 + vr) * FSROW + jvp * 16 + jsel8) * 2;
                ldsm_x4_t(vbh, uVs + off);
                mma16816(ov[2 * jvp],     pah, vbh);
                mma16816(ov[2 * jvp + 1], pah, vbh + 2);
            }
        }
        rs0 += __shfl_xor_sync(0xffffffffu, rs0, 1);
        rs0 += __shfl_xor_sync(0xffffffffu, rs0, 2);
        rs1 += __shfl_xor_sync(0xffffffffu, rs1, 1);
        rs1 += __shfl_xor_sync(0xffffffffu, rs1, 2);
        l0 = l0 * sc0 + rs0;
        l1 = l1 * sc1 + rs1;

        __syncthreads();
    }

    float rinv0 = 1.0f / l0;
    float rinv1 = 1.0f / l1;
    size_t orow0 = base + (size_t)(q0 + wm + (lane >> 2)) * D_MODEL;
    size_t orow1 = orow0 + (size_t)8 * D_MODEL;
    int colb = ((lane & 3) << 1);
#pragma unroll
    for (int jv = 0; jv < 8; jv++) {
        int c = jv * 8 + colb;
        *(uint32_t*)(Oh + orow0 + c) = pack_hf2(ov[jv][0] * rinv0, ov[jv][1] * rinv0);
        *(uint32_t*)(Oh + orow1 + c) = pack_hf2(ov[jv][2] * rinv1, ov[jv][3] * rinv1);
    }
}

// ---------------------------------------------------------------------------
// Launch
// ---------------------------------------------------------------------------
extern "C" void kernel_launch(void* const* d_in, const int* in_sizes, int n_in,
                              void* d_out, int out_size)
{
    const float* x   = (const float*)d_in[0];
    const float* W_q = (const float*)d_in[1];
    const float* W_k = (const float*)d_in[2];
    const float* W_v = (const float*)d_in[3];
    const float* W_o = (const float*)d_in[4];
    float* out = (float*)d_out;

    __half *pxh, *pqh, *pkh, *pvh, *pch, *pwh, *pwl;
    cudaGetSymbolAddress((void**)&pxh, g_xh);
    cudaGetSymbolAddress((void**)&pqh, g_qh);
    cudaGetSymbolAddress((void**)&pkh, g_kh);
    cudaGetSymbolAddress((void**)&pvh, g_vh);
    cudaGetSymbolAddress((void**)&pch, g_ch);
    cudaGetSymbolAddress((void**)&pwh, g_wh);
    cudaGetSymbolAddress((void**)&pwl, g_wl);

    cudaFuncSetAttribute(mma_gemm_qkv_kernel,
                         cudaFuncAttributeMaxDynamicSharedMemorySize, SMEM_GEMM);
    cudaFuncSetAttribute(mma_gemm_kernel,
                         cudaFuncAttributeMaxDynamicSharedMemorySize, SMEM_GEMM);
    cudaFuncSetAttribute(flash_mma_kernel,
                         cudaFuncAttributeMaxDynamicSharedMemorySize, FSMEM);

    const size_t WSZ = (size_t)D_MODEL * D_MODEL;   // 1048576
    const int nx4 = (int)((size_t)M_TOTAL * D_MODEL / 4);
    const int nw4 = (int)(WSZ / 4);

    // x: hi only; all 4 weights: hi/lo in one launch
    split_hi_kernel<<<(nx4 + 255) / 256, 256>>>(x, pxh, nx4);
    dim3 gSplitW((nw4 + 255) / 256, 4);
    split_w_kernel<<<gSplitW, 256>>>(W_q, W_k, W_v, W_o, pwh, pwl, nw4);

    // fused Q/K/V projection: N = 3072 over concatenated weights (all hi-out)
    dim3 gQKV(3 * D_MODEL / 128, M_TOTAL / 128);    // (24, 64)
    mma_gemm_qkv_kernel<<<gQKV, 256, SMEM_GEMM>>>(pxh, pwh, pwl, pqh, pkh, pvh);

    dim3 gFlash(SEQ / 128, BATCH * N_HEADS);        // (16, 64)
    flash_mma_kernel<<<gFlash, 256, FSMEM>>>(pqh, pkh, pvh, pch);

    // O projection: fp32 output
    dim3 gGemm(D_MODEL / 128, M_TOTAL / 128);       // (8, 64)
    mma_gemm_kernel<<<gGemm, 256, SMEM_GEMM>>>(pch, pwh + 3 * WSZ, pwl + 3 * WSZ,
                                               out, M_TOTAL, D_MODEL, D_MODEL);
}